// round 7
// baseline (speedup 1.0000x reference)
#include <cuda_runtime.h>
#include <cuda_bf16.h>
#include <cstdint>

// Problem constants
#define BB 4
#define SS 2048
#define DD 1024
#define HH 16
#define DHH 64
#define BSROWS (BB * SS)          // 8192

typedef __nv_bfloat16 bf16;

// ---------------------------------------------------------------------------
// Device-global scratch (allocation-free). All pre-split bf16 hi/mid pairs.
// ---------------------------------------------------------------------------
__device__ bf16 g_xh[(size_t)BSROWS * DD], g_xm[(size_t)BSROWS * DD];
__device__ bf16 g_qh[(size_t)BSROWS * DD], g_qm[(size_t)BSROWS * DD];
__device__ bf16 g_kh[(size_t)BSROWS * DD], g_km[(size_t)BSROWS * DD];
__device__ bf16 g_vh[(size_t)BSROWS * DD], g_vm[(size_t)BSROWS * DD];
__device__ bf16 g_ah[(size_t)BSROWS * DD], g_am[(size_t)BSROWS * DD];
__device__ bf16 g_wth[4 * (size_t)DD * DD], g_wtm[4 * (size_t)DD * DD];  // W^T [n][k]

#define LOG2E 1.4426950408889634f

// ---------------------------------------------------------------------------
// Helpers
// ---------------------------------------------------------------------------
__device__ __forceinline__ void mma_bf16(float* c, const unsigned* a, const unsigned* b) {
    asm volatile(
        "mma.sync.aligned.m16n8k16.row.col.f32.bf16.bf16.f32 "
        "{%0,%1,%2,%3}, {%4,%5,%6,%7}, {%8,%9}, {%0,%1,%2,%3};\n"
        : "+f"(c[0]), "+f"(c[1]), "+f"(c[2]), "+f"(c[3])
        : "r"(a[0]), "r"(a[1]), "r"(a[2]), "r"(a[3]),
          "r"(b[0]), "r"(b[1]));
}

__device__ __forceinline__ void ldm_x4(unsigned* r, uint32_t addr) {
    asm volatile("ldmatrix.sync.aligned.m8n8.x4.shared.b16 {%0,%1,%2,%3}, [%4];"
        : "=r"(r[0]), "=r"(r[1]), "=r"(r[2]), "=r"(r[3]) : "r"(addr));
}
__device__ __forceinline__ void ldm_x4t(unsigned* r, uint32_t addr) {
    asm volatile("ldmatrix.sync.aligned.m8n8.x4.trans.shared.b16 {%0,%1,%2,%3}, [%4];"
        : "=r"(r[0]), "=r"(r[1]), "=r"(r[2]), "=r"(r[3]) : "r"(addr));
}

__device__ __forceinline__ unsigned pack2(bf16 lo, bf16 hi) {
    unsigned l = __bfloat16_as_ushort(lo), h = __bfloat16_as_ushort(hi);
    return l | (h << 16);
}

__device__ __forceinline__ void bsplit(float x, bf16& h, bf16& m) {
    h = __float2bfloat16_rn(x);
    m = __float2bfloat16_rn(x - __bfloat162float(h));
}

__device__ __forceinline__ unsigned packHM(float x, float y, unsigned& mp) {
    bf16 hx, mx, hy, my;
    bsplit(x, hx, mx);
    bsplit(y, hy, my);
    mp = pack2(mx, my);
    return pack2(hx, hy);
}

__device__ __forceinline__ void cpa16(void* s, const void* g) {
    unsigned sa = (unsigned)__cvta_generic_to_shared(s);
    asm volatile("cp.async.cg.shared.global [%0], [%1], 16;\n" :: "r"(sa), "l"(g));
}
__device__ __forceinline__ void cpa4(void* s, const void* g) {
    unsigned sa = (unsigned)__cvta_generic_to_shared(s);
    asm volatile("cp.async.ca.shared.global [%0], [%1], 4;\n" :: "r"(sa), "l"(g));
}
__device__ __forceinline__ void cpa_commit() {
    asm volatile("cp.async.commit_group;\n");
}
template <int N>
__device__ __forceinline__ void cpa_wait() {
    asm volatile("cp.async.wait_group %0;\n" :: "n"(N));
}

__device__ __forceinline__ uint32_t smem_u32(const void* p) {
    return (uint32_t)__cvta_generic_to_shared(p);
}

// ---------------------------------------------------------------------------
// Prep: split x (fp32 -> bf16 hi/mid)
// ---------------------------------------------------------------------------
__global__ __launch_bounds__(256)
void split_src(const float* __restrict__ x)
{
    int i = blockIdx.x * 256 + threadIdx.x;            // over float4s: 2M
    float4 v = reinterpret_cast<const float4*>(x)[i];
    bf16 h0, m0, h1, m1, h2, m2, h3, m3;
    bsplit(v.x, h0, m0); bsplit(v.y, h1, m1);
    bsplit(v.z, h2, m2); bsplit(v.w, h3, m3);
    uint2 uh, um;
    uh.x = pack2(h0, h1); uh.y = pack2(h2, h3);
    um.x = pack2(m0, m1); um.y = pack2(m2, m3);
    reinterpret_cast<uint2*>(g_xh)[i] = uh;
    reinterpret_cast<uint2*>(g_xm)[i] = um;
}

// ---------------------------------------------------------------------------
// Prep: transpose + split all 4 W [k][n] fp32 -> g_wt{h,m}[z] as [n][k] bf16
// ---------------------------------------------------------------------------
__global__ __launch_bounds__(256)
void wsplit_all(const float* __restrict__ W0, const float* __restrict__ W1,
                const float* __restrict__ W2, const float* __restrict__ W3)
{
    const int widx = blockIdx.z;
    const float* W = (widx == 0) ? W0 : (widx == 1) ? W1 : (widx == 2) ? W2 : W3;
    __shared__ float t[32][33];
    const int kb = blockIdx.x * 32, nb = blockIdx.y * 32;
    const int r = threadIdx.x >> 3, c4 = (threadIdx.x & 7) * 4;
    float4 v = *reinterpret_cast<const float4*>(W + (size_t)(kb + r) * DD + nb + c4);
    t[r][c4 + 0] = v.x; t[r][c4 + 1] = v.y; t[r][c4 + 2] = v.z; t[r][c4 + 3] = v.w;
    __syncthreads();
    bf16* oh = g_wth + (size_t)widx * DD * DD;
    bf16* om = g_wtm + (size_t)widx * DD * DD;
    bf16 h[4], m[4];
    #pragma unroll
    for (int j = 0; j < 4; j++) bsplit(t[c4 + j][r], h[j], m[j]);
    uint2 uh, um;
    uh.x = pack2(h[0], h[1]); uh.y = pack2(h[2], h[3]);
    um.x = pack2(m[0], m[1]); um.y = pack2(m[2], m[3]);
    size_t o = (size_t)(nb + r) * DD + kb + c4;
    *reinterpret_cast<uint2*>(oh + o) = uh;
    *reinterpret_cast<uint2*>(om + o) = um;
}

// ---------------------------------------------------------------------------
// GEMM (3xBF16, m16n8k16 + ldmatrix): C = A * W^T' + bias, M=8192, N=K=1024
// CTA tile 128x128, kstep 32, 256 threads (8 warps: 4 M x 2 N), cp.async dbuf.
// Single __syncthreads per k-iteration; full-iteration prefetch distance.
// mode -1: md=blockIdx.z (QKV, A=g_x, out bf16 split to g_{q,k,v}, q scaled 1/8)
// mode  3: A=g_a (attended), out fp32 to outF
// ---------------------------------------------------------------------------
#define KS 32
#define AST 40
#define SLAB (2 * 128 * AST)                 // halves per (dbuf) array
#define GEMM_SMEM (4 * SLAB * 2)             // 81920 bytes
#define GMOFF (SLAB * 2)                     // hi->mid byte offset

__global__ __launch_bounds__(256, 2)
void gemm_k(const float* __restrict__ b0, const float* __restrict__ b1,
            const float* __restrict__ b2, float* __restrict__ outF, int mode)
{
    const int md = (mode < 0) ? (int)blockIdx.z : mode;
    const bf16* Ah = (md < 3) ? g_xh : g_ah;
    const bf16* Am = (md < 3) ? g_xm : g_am;
    const bf16* Wh = g_wth + (size_t)md * DD * DD;
    const bf16* Wm = g_wtm + (size_t)md * DD * DD;
    const float* bias = (md == 1) ? b1 : (md == 2) ? b2 : b0;
    const float scale = (md == 0) ? 0.125f : 1.0f;
    bf16* OH = (md == 0) ? g_qh : (md == 1) ? g_kh : g_vh;
    bf16* OM = (md == 0) ? g_qm : (md == 1) ? g_km : g_vm;

    extern __shared__ bf16 sm[];
    bf16* sAh = sm;
    bf16* sAm = sm + SLAB;
    bf16* sBh = sm + 2 * SLAB;
    bf16* sBm = sm + 3 * SLAB;
    const uint32_t uAh = smem_u32(sAh);
    const uint32_t uBh = smem_u32(sBh);

    const int tid  = threadIdx.x;
    const int lane = tid & 31;
    const int warp = tid >> 5;
    const int wm = warp & 3, wn = warp >> 2;
    const int cm = blockIdx.x * 128, cn = blockIdx.y * 128;
    const int rq = lane >> 2, cq = lane & 3;

    // ldmatrix lane->row mappings
    const int a_r = lane & 15, a_k = (lane >> 4) * 8;               // A x4
    const int b_n = ((lane >> 3) & 1) * 8 + (lane & 7);             // B x4 (pair of n-tiles)
    const int b_k = (lane >> 4) * 8;

    // issue stage kt into buffer buf
    auto issue = [&](int kt, int buf) {
        const int k0 = kt * KS;
        #pragma unroll
        for (int i = 0; i < 2; i++) {
            int idx = i * 256 + tid;
            int r = idx >> 2, c8 = (idx & 3) * 8;
            size_t ga = (size_t)(cm + r) * DD + k0 + c8;
            size_t gb = (size_t)(cn + r) * DD + k0 + c8;
            int so = buf * 128 * AST + r * AST + c8;
            cpa16(&sAh[so], Ah + ga);
            cpa16(&sAm[so], Am + ga);
            cpa16(&sBh[so], Wh + gb);
            cpa16(&sBm[so], Wm + gb);
        }
        cpa_commit();
    };

    float acc[2][8][4];
    #pragma unroll
    for (int mt = 0; mt < 2; mt++)
        #pragma unroll
        for (int nt = 0; nt < 8; nt++)
            #pragma unroll
            for (int j = 0; j < 4; j++) acc[mt][nt][j] = 0.f;

    const int NK = DD / KS;  // 32
    issue(0, 0);

    for (int kt = 0; kt < NK; ++kt) {
        const int cur = kt & 1;
        cpa_wait<0>();
        __syncthreads();            // stage kt visible; readers of buf cur^1 (iter kt-1) retired
        if (kt + 1 < NK) issue(kt + 1, cur ^ 1);   // loads overlap full compute below

        const uint32_t bufOff = (uint32_t)(cur * 128 * AST * 2);
        #pragma unroll
        for (int ch = 0; ch < 2; ++ch) {
            const int kc = ch * 16;
            unsigned ah[2][4], am[2][4];
            #pragma unroll
            for (int mt = 0; mt < 2; mt++) {
                uint32_t ad = uAh + bufOff +
                    (uint32_t)(((wm * 32 + mt * 16 + a_r) * AST + kc + a_k) * 2);
                ldm_x4(ah[mt], ad);
                ldm_x4(am[mt], ad + GMOFF);
            }
            #pragma unroll
            for (int ntp = 0; ntp < 4; ntp++) {
                uint32_t bd = uBh + bufOff +
                    (uint32_t)(((wn * 64 + ntp * 16 + b_n) * AST + kc + b_k) * 2);
                unsigned kbh[4], kbm[4];
                ldm_x4(kbh, bd);
                ldm_x4(kbm, bd + GMOFF);
                unsigned bh0[2] = {kbh[0], kbh[2]}, bh1[2] = {kbh[1], kbh[3]};
                unsigned bm0[2] = {kbm[0], kbm[2]}, bm1[2] = {kbm[1], kbm[3]};
                #pragma unroll
                for (int mt = 0; mt < 2; mt++) {
                    mma_bf16(acc[mt][2 * ntp],     ah[mt], bh0);
                    mma_bf16(acc[mt][2 * ntp],     am[mt], bh0);
                    mma_bf16(acc[mt][2 * ntp],     ah[mt], bm0);
                    mma_bf16(acc[mt][2 * ntp + 1], ah[mt], bh1);
                    mma_bf16(acc[mt][2 * ntp + 1], am[mt], bh1);
                    mma_bf16(acc[mt][2 * ntp + 1], ah[mt], bm1);
                }
            }
        }
    }

    // epilogue
    #pragma unroll
    for (int mt = 0; mt < 2; mt++) {
        int r = cm + wm * 32 + mt * 16 + rq;
        #pragma unroll
        for (int nt = 0; nt < 8; nt++) {
            int c = cn + wn * 64 + nt * 8 + cq * 2;
            float bb0 = bias[c], bb1 = bias[c + 1];
            float v0 = (acc[mt][nt][0] + bb0) * scale;
            float v1 = (acc[mt][nt][1] + bb1) * scale;
            float v2 = (acc[mt][nt][2] + bb0) * scale;
            float v3 = (acc[mt][nt][3] + bb1) * scale;
            if (md == 3) {
                *reinterpret_cast<float2*>(outF + (size_t)r * DD + c) = make_float2(v0, v1);
                *reinterpret_cast<float2*>(outF + (size_t)(r + 8) * DD + c) = make_float2(v2, v3);
            } else {
                bf16 h0, m0, h1, m1;
                bsplit(v0, h0, m0); bsplit(v1, h1, m1);
                *reinterpret_cast<unsigned*>(OH + (size_t)r * DD + c) = pack2(h0, h1);
                *reinterpret_cast<unsigned*>(OM + (size_t)r * DD + c) = pack2(m0, m1);
                bsplit(v2, h0, m0); bsplit(v3, h1, m1);
                *reinterpret_cast<unsigned*>(OH + (size_t)(r + 8) * DD + c) = pack2(h0, h1);
                *reinterpret_cast<unsigned*>(OM + (size_t)(r + 8) * DD + c) = pack2(m0, m1);
            }
        }
    }
}

// ---------------------------------------------------------------------------
// Flash attention (causal + key padding), 3xBF16 m16n8k16 + ldmatrix.
// 128-row Q tiles, 8 warps (256 thr); K AND V double-buffered; ONE sync/iter.
// Grid: (S/128, B*H); warp w owns query rows [16w, 16w+16) of the 128-row tile.
// smem halves: QH,QM (128xFST) | KH0,KM0,KH1,KM1 | VH0,VM0,VH1,VM1 (64xFST) | Ms[2][64]
// ---------------------------------------------------------------------------
#define FST 72                                // smem k-stride (halves)
#define F64 (64 * FST)                        // halves per 64-row array
#define QHALVES (2 * 128 * FST)               // QH+QM
#define QMOFF (128 * FST * 2)                 // Q hi->mid byte offset
#define KVMOFF (F64 * 2)                      // K/V hi->mid byte offset
#define FLASH_SMEM ((QHALVES + 8 * F64) * 2 + 2 * 64 * 4)   // 111104 bytes

__global__ __launch_bounds__(256, 2)
void flash_attn_kernel(const int* __restrict__ pmask)
{
    extern __shared__ bf16 fsm[];
    int* Ms0 = reinterpret_cast<int*>(fsm + QHALVES + 8 * F64);
    const uint32_t uQH = smem_u32(fsm);

    const int tid = threadIdx.x, lane = tid & 31, warp = tid >> 5;
    const int qb = (int)(gridDim.x - 1) - (int)blockIdx.x;  // heavy tiles first
    const int bh = blockIdx.y;
    const int b = bh >> 4, h = bh & 15;
    const size_t head_off = ((size_t)b * SS) * DD + (size_t)h * DHH;
    const int nkb = 2 * qb + 2;               // 64-wide key blocks needed

    const int rq = lane >> 2, cq = lane & 3;
    const int row0 = warp * 16 + rq;

    // ldmatrix lane->row mappings
    const int a_r = lane & 15, a_k = (lane >> 4) * 8;      // Q (A, x4)
    const int b_n = ((lane >> 3) & 1) * 8 + (lane & 7);    // K (B, x4 pair)
    const int b_k = (lane >> 4) * 8;
    const int v_k = ((lane >> 3) & 1) * 8 + (lane & 7);    // V (B^T via x4.trans)
    const int v_n = (lane >> 4) * 8;

    // K(kb)+V(kb)+mask(kb) into buffers (kb&1); one commit group
    auto issueKV = [&](int kb) {
        const int bsel = kb & 1;
        bf16* KH = fsm + QHALVES + 2 * F64 * bsel;
        bf16* VH = fsm + QHALVES + 4 * F64 + 2 * F64 * bsel;
        #pragma unroll
        for (int i = 0; i < 2; i++) {
            int idx = i * 256 + tid;
            int r = idx >> 3, c8 = (idx & 7) * 8;
            size_t g = head_off + (size_t)(kb * 64 + r) * DD + c8;
            cpa16(&KH[r * FST + c8], g_kh + g);
            cpa16(&KH[F64 + r * FST + c8], g_km + g);
            cpa16(&VH[r * FST + c8], g_vh + g);
            cpa16(&VH[F64 + r * FST + c8], g_vm + g);
        }
        if (tid < 64) cpa4(&Ms0[bsel * 64 + tid], pmask + b * SS + kb * 64 + tid);
        cpa_commit();
    };

    // Prologue: Q (128x64 hi/mid) + K0/V0/mask0 in ONE group
    #pragma unroll
    for (int i = 0; i < 4; i++) {
        int idx = i * 256 + tid;
        int r = idx >> 3, c8 = (idx & 7) * 8;
        size_t g = head_off + (size_t)(qb * 128 + r) * DD + c8;
        cpa16(&fsm[r * FST + c8], g_qh + g);
        cpa16(&fsm[128 * FST + r * FST + c8], g_qm + g);
    }
    {
        bf16* KH = fsm + QHALVES;
        bf16* VH = fsm + QHALVES + 4 * F64;
        #pragma unroll
        for (int i = 0; i < 2; i++) {
            int idx = i * 256 + tid;
            int r = idx >> 3, c8 = (idx & 7) * 8;
            size_t g = head_off + (size_t)r * DD + c8;
            cpa16(&KH[r * FST + c8], g_kh + g);
            cpa16(&KH[F64 + r * FST + c8], g_km + g);
            cpa16(&VH[r * FST + c8], g_vh + g);
            cpa16(&VH[F64 + r * FST + c8], g_vm + g);
        }
        if (tid < 64) cpa4(&Ms0[tid], pmask + b * SS + tid);
        cpa_commit();
    }

    float o[8][4];
    #pragma unroll
    for (int nt = 0; nt < 8; nt++)
        #pragma unroll
        for (int j = 0; j < 4; j++) o[nt][j] = 0.f;
    float m0 = -1e30f, m1 = -1e30f, l0 = 0.f, l1 = 0.f;

    for (int kb = 0; kb < nkb; ++kb) {
        cpa_wait<0>();              // group kb complete (only it can be pending)
        __syncthreads();            // data visible; prior iter's buffer readers retired
        if (kb + 1 < nkb) issueKV(kb + 1);   // overlaps the whole iteration below

        const uint32_t uKH = smem_u32(fsm + QHALVES + 2 * F64 * (kb & 1));
        const uint32_t uVH = smem_u32(fsm + QHALVES + 4 * F64 + 2 * F64 * (kb & 1));
        const int* Ms = Ms0 + (kb & 1) * 64;

        // --- S = Q K^T (warp: 16 x 64), 3xBF16 via ldmatrix ---
        float sc[8][4];
        #pragma unroll
        for (int nt = 0; nt < 8; nt++)
            #pragma unroll
            for (int j = 0; j < 4; j++) sc[nt][j] = 0.f;

        #pragma unroll
        for (int ch = 0; ch < 4; ++ch) {
            const int kc = ch * 16;
            unsigned ah[4], am[4];
            uint32_t qd = uQH + (uint32_t)(((warp * 16 + a_r) * FST + kc + a_k) * 2);
            ldm_x4(ah, qd);
            ldm_x4(am, qd + QMOFF);
            #pragma unroll
            for (int ntp = 0; ntp < 4; ntp++) {
                uint32_t kd = uKH + (uint32_t)(((ntp * 16 + b_n) * FST + kc + b_k) * 2);
                unsigned kbh[4], kbm[4];
                ldm_x4(kbh, kd);
                ldm_x4(kbm, kd + KVMOFF);
                unsigned bh0[2] = {kbh[0], kbh[2]}, bh1[2] = {kbh[1], kbh[3]};
                unsigned bm0[2] = {kbm[0], kbm[2]}, bm1[2] = {kbm[1], kbm[3]};
                mma_bf16(sc[2 * ntp],     ah, bh0);
                mma_bf16(sc[2 * ntp],     am, bh0);
                mma_bf16(sc[2 * ntp],     ah, bm0);
                mma_bf16(sc[2 * ntp + 1], ah, bh1);
                mma_bf16(sc[2 * ntp + 1], am, bh1);
                mma_bf16(sc[2 * ntp + 1], ah, bm1);
            }
        }

        // --- mask (Q already scaled; sentinel -1e30) ---
        const int gm0 = qb * 128 + row0, gm1 = gm0 + 8;
        #pragma unroll
        for (int nt = 0; nt < 8; nt++) {
            int nloc = nt * 8 + cq * 2;
            int gn = kb * 64 + nloc;
            #pragma unroll
            for (int j = 0; j < 2; j++) {
                bool pv = (Ms[nloc + j] != 0);
                sc[nt][j]     = (pv && (gn + j) <= gm0) ? sc[nt][j]     : -1e30f;
                sc[nt][2 + j] = (pv && (gn + j) <= gm1) ? sc[nt][2 + j] : -1e30f;
            }
        }

        // --- online softmax (p written back into sc) ---
        float mx0 = -1e30f, mx1 = -1e30f;
        #pragma unroll
        for (int nt = 0; nt < 8; nt++) {
            mx0 = fmaxf(mx0, fmaxf(sc[nt][0], sc[nt][1]));
            mx1 = fmaxf(mx1, fmaxf(sc[nt][2], sc[nt][3]));
        }
        mx0 = fmaxf(mx0, __shfl_xor_sync(0xffffffffu, mx0, 1));
        mx0 = fmaxf(mx0, __shfl_xor_sync(0xffffffffu, mx0, 2));
        mx1 = fmaxf(mx1, __shfl_xor_sync(0xffffffffu, mx1, 1));
        mx1 = fmaxf(mx1, __shfl_xor_sync(0xffffffffu, mx1, 2));

        float mn0 = fmaxf(m0, mx0), mn1 = fmaxf(m1, mx1);
        float al0 = exp2f((m0 - mn0) * LOG2E);
        float al1 = exp2f((m1 - mn1) * LOG2E);

        float s0 = 0.f, s1 = 0.f;
        #pragma unroll
        for (int nt = 0; nt < 8; nt++) {
            sc[nt][0] = exp2f((sc[nt][0] - mn0) * LOG2E);
            sc[nt][1] = exp2f((sc[nt][1] - mn0) * LOG2E);
            sc[nt][2] = exp2f((sc[nt][2] - mn1) * LOG2E);
            sc[nt][3] = exp2f((sc[nt][3] - mn1) * LOG2E);
            s0 += sc[nt][0] + sc[nt][1];
            s1 += sc[nt][2] + sc[nt][3];
        }
        s0 += __shfl_xor_sync(0xffffffffu, s0, 1);
        s0 += __shfl_xor_sync(0xffffffffu, s0, 2);
        s1 += __shfl_xor_sync(0xffffffffu, s1, 1);
        s1 += __shfl_xor_sync(0xffffffffu, s1, 2);

        l0 = l0 * al0 + s0;
        l1 = l1 * al1 + s1;
        m0 = mn0; m1 = mn1;

        #pragma unroll
        for (int nt = 0; nt < 8; nt++) {
            o[nt][0] *= al0; o[nt][1] *= al0;
            o[nt][2] *= al1; o[nt][3] *= al1;
        }

        // --- O += P V: A from S registers; V fragments via ldmatrix.trans ---
        #pragma unroll
        for (int ch = 0; ch < 4; ++ch) {
            const int kc = ch * 16;
            const int t0 = 2 * ch, t1 = 2 * ch + 1;
            unsigned ah[4], am[4];
            ah[0] = packHM(sc[t0][0], sc[t0][1], am[0]);
            ah[1] = packHM(sc[t0][2], sc[t0][3], am[1]);
            ah[2] = packHM(sc[t1][0], sc[t1][1], am[2]);
            ah[3] = packHM(sc[t1][2], sc[t1][3], am[3]);
            #pragma unroll
            for (int ntp = 0; ntp < 4; ntp++) {
                uint32_t vd = uVH + (uint32_t)(((kc + v_k) * FST + ntp * 16 + v_n) * 2);
                unsigned vbh[4], vbm[4];
                ldm_x4t(vbh, vd);
                ldm_x4t(vbm, vd + KVMOFF);
                unsigned bh0[2] = {vbh[0], vbh[1]}, bh1[2] = {vbh[2], vbh[3]};
                unsigned bm0[2] = {vbm[0], vbm[1]}, bm1[2] = {vbm[2], vbm[3]};
                mma_bf16(o[2 * ntp],     ah, bh0);
                mma_bf16(o[2 * ntp],     am, bh0);
                mma_bf16(o[2 * ntp],     ah, bm0);
                mma_bf16(o[2 * ntp + 1], ah, bh1);
                mma_bf16(o[2 * ntp + 1], am, bh1);
                mma_bf16(o[2 * ntp + 1], ah, bm1);
            }
        }
    }

    // --- epilogue: normalize, split, store to g_a{h,m} [b, s, h, dh] ---
    float i0 = (l0 > 0.f) ? 1.f / l0 : 0.f;
    float i1 = (l1 > 0.f) ? 1.f / l1 : 0.f;
    size_t ob = head_off + (size_t)(qb * 128) * DD;
    #pragma unroll
    for (int nt = 0; nt < 8; nt++) {
        int c = nt * 8 + cq * 2;
        bf16 h0, mm0, h1, mm1;
        bsplit(o[nt][0] * i0, h0, mm0); bsplit(o[nt][1] * i0, h1, mm1);
        *reinterpret_cast<unsigned*>(g_ah + ob + (size_t)row0 * DD + c) = pack2(h0, h1);
        *reinterpret_cast<unsigned*>(g_am + ob + (size_t)row0 * DD + c) = pack2(mm0, mm1);
        bsplit(o[nt][2] * i1, h0, mm0); bsplit(o[nt][3] * i1, h1, mm1);
        *reinterpret_cast<unsigned*>(g_ah + ob + (size_t)(row0 + 8) * DD + c) = pack2(h0, h1);
        *reinterpret_cast<unsigned*>(g_am + ob + (size_t)(row0 + 8) * DD + c) = pack2(mm0, mm1);
    }
}

// ---------------------------------------------------------------------------
extern "C" void kernel_launch(void* const* d_in, const int* in_sizes, int n_in,
                              void* d_out, int out_size)
{
    (void)in_sizes; (void)n_in; (void)out_size;
    const float* x  = (const float*)d_in[0];
    const float* Wq = (const float*)d_in[1];
    const float* bq = (const float*)d_in[2];
    const float* Wk = (const float*)d_in[3];
    const float* bk = (const float*)d_in[4];
    const float* Wv = (const float*)d_in[5];
    const float* bv = (const float*)d_in[6];
    const float* Wo = (const float*)d_in[7];
    const float* bo = (const float*)d_in[8];
    const int*   pm = (const int*)d_in[9];
    float* out = (float*)d_out;

    cudaFuncSetAttribute(gemm_k, cudaFuncAttributeMaxDynamicSharedMemorySize, GEMM_SMEM);
    cudaFuncSetAttribute(flash_attn_kernel, cudaFuncAttributeMaxDynamicSharedMemorySize, FLASH_SMEM);

    split_src<<<(BSROWS * DD / 4) / 256, 256>>>(x);
    dim3 wgrid(32, 32, 4);
    wsplit_all<<<wgrid, 256>>>(Wq, Wk, Wv, Wo);

    dim3 qkvgrid(BSROWS / 128, DD / 128, 3);    // (64, 8, 3)
    gemm_k<<<qkvgrid, 256, GEMM_SMEM>>>(bq, bk, bv, nullptr, -1);

    dim3 fgrid(SS / 128, BB * HH);              // (16, 64)
    flash_attn_kernel<<<fgrid, 256, FLASH_SMEM>>>(pm);

    dim3 ogrid(BSROWS / 128, DD / 128, 1);
    gemm_k<<<ogrid, 256, GEMM_SMEM>>>(bo, nullptr, nullptr, out, 3);
}

// round 8
// speedup vs baseline: 1.0833x; 1.0833x over previous
#include <cuda_runtime.h>
#include <cuda_bf16.h>
#include <cuda_fp16.h>
#include <cstdint>

// Problem constants
#define BB 4
#define SS 2048
#define DD 1024
#define HH 16
#define DHH 64
#define BSROWS (BB * SS)          // 8192

typedef __nv_bfloat16 bf16;

// ---------------------------------------------------------------------------
// Device-global scratch (allocation-free). Q/K/x/att: bf16 hi/mid. V: fp16 hi/mid.
// ---------------------------------------------------------------------------
__device__ bf16 g_xh[(size_t)BSROWS * DD], g_xm[(size_t)BSROWS * DD];
__device__ bf16 g_qh[(size_t)BSROWS * DD], g_qm[(size_t)BSROWS * DD];
__device__ bf16 g_kh[(size_t)BSROWS * DD], g_km[(size_t)BSROWS * DD];
__device__ __half g_vh[(size_t)BSROWS * DD], g_vm[(size_t)BSROWS * DD];
__device__ bf16 g_ah[(size_t)BSROWS * DD], g_am[(size_t)BSROWS * DD];
__device__ bf16 g_wth[4 * (size_t)DD * DD], g_wtm[4 * (size_t)DD * DD];  // W^T [n][k]

#define LOG2E 1.4426950408889634f

// ---------------------------------------------------------------------------
// Helpers
// ---------------------------------------------------------------------------
__device__ __forceinline__ void mma_bf16(float* c, const unsigned* a, const unsigned* b) {
    asm volatile(
        "mma.sync.aligned.m16n8k16.row.col.f32.bf16.bf16.f32 "
        "{%0,%1,%2,%3}, {%4,%5,%6,%7}, {%8,%9}, {%0,%1,%2,%3};\n"
        : "+f"(c[0]), "+f"(c[1]), "+f"(c[2]), "+f"(c[3])
        : "r"(a[0]), "r"(a[1]), "r"(a[2]), "r"(a[3]),
          "r"(b[0]), "r"(b[1]));
}
__device__ __forceinline__ void mma_f16(float* c, const unsigned* a, const unsigned* b) {
    asm volatile(
        "mma.sync.aligned.m16n8k16.row.col.f32.f16.f16.f32 "
        "{%0,%1,%2,%3}, {%4,%5,%6,%7}, {%8,%9}, {%0,%1,%2,%3};\n"
        : "+f"(c[0]), "+f"(c[1]), "+f"(c[2]), "+f"(c[3])
        : "r"(a[0]), "r"(a[1]), "r"(a[2]), "r"(a[3]),
          "r"(b[0]), "r"(b[1]));
}

__device__ __forceinline__ void ldm_x4(unsigned* r, uint32_t addr) {
    asm volatile("ldmatrix.sync.aligned.m8n8.x4.shared.b16 {%0,%1,%2,%3}, [%4];"
        : "=r"(r[0]), "=r"(r[1]), "=r"(r[2]), "=r"(r[3]) : "r"(addr));
}
__device__ __forceinline__ void ldm_x4t(unsigned* r, uint32_t addr) {
    asm volatile("ldmatrix.sync.aligned.m8n8.x4.trans.shared.b16 {%0,%1,%2,%3}, [%4];"
        : "=r"(r[0]), "=r"(r[1]), "=r"(r[2]), "=r"(r[3]) : "r"(addr));
}

__device__ __forceinline__ unsigned pack2(bf16 lo, bf16 hi) {
    unsigned l = __bfloat16_as_ushort(lo), h = __bfloat16_as_ushort(hi);
    return l | (h << 16);
}
__device__ __forceinline__ void bsplit(float x, bf16& h, bf16& m) {
    h = __float2bfloat16_rn(x);
    m = __float2bfloat16_rn(x - __bfloat162float(h));
}
__device__ __forceinline__ unsigned packHM(float x, float y, unsigned& mp) {
    bf16 hx, mx, hy, my;
    bsplit(x, hx, mx);
    bsplit(y, hy, my);
    mp = pack2(mx, my);
    return pack2(hx, hy);
}
// fp16 split/pack (for V)
__device__ __forceinline__ unsigned packh2(__half lo, __half hi) {
    unsigned l = __half_as_ushort(lo), h = __half_as_ushort(hi);
    return l | (h << 16);
}
__device__ __forceinline__ void hsplit(float x, __half& h, __half& m) {
    h = __float2half_rn(x);
    m = __float2half_rn(x - __half2float(h));
}
__device__ __forceinline__ unsigned packHMh(float x, float y, unsigned& mp) {
    __half hx, mx, hy, my;
    hsplit(x, hx, mx);
    hsplit(y, hy, my);
    mp = packh2(mx, my);
    return packh2(hx, hy);
}
// f32 pair -> f16x2 (hi arg -> upper half)
__device__ __forceinline__ unsigned f16x2_of(float hi, float lo) {
    unsigned r;
    asm("cvt.rn.f16x2.f32 %0, %1, %2;" : "=r"(r) : "f"(hi), "f"(lo));
    return r;
}
__device__ __forceinline__ float ex2f(float x) {
    float r;
    asm("ex2.approx.ftz.f32 %0, %1;" : "=f"(r) : "f"(x));
    return r;
}

__device__ __forceinline__ void cpa16(void* s, const void* g) {
    unsigned sa = (unsigned)__cvta_generic_to_shared(s);
    asm volatile("cp.async.cg.shared.global [%0], [%1], 16;\n" :: "r"(sa), "l"(g));
}
__device__ __forceinline__ void cpa4(void* s, const void* g) {
    unsigned sa = (unsigned)__cvta_generic_to_shared(s);
    asm volatile("cp.async.ca.shared.global [%0], [%1], 4;\n" :: "r"(sa), "l"(g));
}
__device__ __forceinline__ void cpa_commit() {
    asm volatile("cp.async.commit_group;\n");
}
template <int N>
__device__ __forceinline__ void cpa_wait() {
    asm volatile("cp.async.wait_group %0;\n" :: "n"(N));
}
__device__ __forceinline__ uint32_t smem_u32(const void* p) {
    return (uint32_t)__cvta_generic_to_shared(p);
}

// ---------------------------------------------------------------------------
// Prep: split x (fp32 -> bf16 hi/mid)
// ---------------------------------------------------------------------------
__global__ __launch_bounds__(256)
void split_src(const float* __restrict__ x)
{
    int i = blockIdx.x * 256 + threadIdx.x;            // over float4s: 2M
    float4 v = reinterpret_cast<const float4*>(x)[i];
    bf16 h0, m0, h1, m1, h2, m2, h3, m3;
    bsplit(v.x, h0, m0); bsplit(v.y, h1, m1);
    bsplit(v.z, h2, m2); bsplit(v.w, h3, m3);
    uint2 uh, um;
    uh.x = pack2(h0, h1); uh.y = pack2(h2, h3);
    um.x = pack2(m0, m1); um.y = pack2(m2, m3);
    reinterpret_cast<uint2*>(g_xh)[i] = uh;
    reinterpret_cast<uint2*>(g_xm)[i] = um;
}

// ---------------------------------------------------------------------------
// Prep: transpose + split all 4 W [k][n] fp32 -> g_wt{h,m}[z] as [n][k] bf16
// ---------------------------------------------------------------------------
__global__ __launch_bounds__(256)
void wsplit_all(const float* __restrict__ W0, const float* __restrict__ W1,
                const float* __restrict__ W2, const float* __restrict__ W3)
{
    const int widx = blockIdx.z;
    const float* W = (widx == 0) ? W0 : (widx == 1) ? W1 : (widx == 2) ? W2 : W3;
    __shared__ float t[32][33];
    const int kb = blockIdx.x * 32, nb = blockIdx.y * 32;
    const int r = threadIdx.x >> 3, c4 = (threadIdx.x & 7) * 4;
    float4 v = *reinterpret_cast<const float4*>(W + (size_t)(kb + r) * DD + nb + c4);
    t[r][c4 + 0] = v.x; t[r][c4 + 1] = v.y; t[r][c4 + 2] = v.z; t[r][c4 + 3] = v.w;
    __syncthreads();
    bf16* oh = g_wth + (size_t)widx * DD * DD;
    bf16* om = g_wtm + (size_t)widx * DD * DD;
    bf16 h[4], m[4];
    #pragma unroll
    for (int j = 0; j < 4; j++) bsplit(t[c4 + j][r], h[j], m[j]);
    uint2 uh, um;
    uh.x = pack2(h[0], h[1]); uh.y = pack2(h[2], h[3]);
    um.x = pack2(m[0], m[1]); um.y = pack2(m[2], m[3]);
    size_t o = (size_t)(nb + r) * DD + kb + c4;
    *reinterpret_cast<uint2*>(oh + o) = uh;
    *reinterpret_cast<uint2*>(om + o) = um;
}

// ---------------------------------------------------------------------------
// GEMM (3xBF16, m16n8k16 + ldmatrix): C = A * W^T' + bias, M=8192, N=K=1024
// CTA tile 128x128, kstep 32, 256 threads (8 warps: 4 M x 2 N), cp.async dbuf.
// Term-major MMA passes: accumulator reuse distance 16 MMAs (breaks chains).
// mode -1: md=blockIdx.z (QKV; q scaled 1/8; V emitted as fp16 hi/mid)
// mode  3: A=g_a (attended), out fp32 to outF
// ---------------------------------------------------------------------------
#define KS 32
#define AST 40
#define SLAB (2 * 128 * AST)                 // halves per (dbuf) array
#define GEMM_SMEM (4 * SLAB * 2)             // 81920 bytes
#define GMOFF (SLAB * 2)                     // hi->mid byte offset

__global__ __launch_bounds__(256, 2)
void gemm_k(const float* __restrict__ b0, const float* __restrict__ b1,
            const float* __restrict__ b2, float* __restrict__ outF, int mode)
{
    const int md = (mode < 0) ? (int)blockIdx.z : mode;
    const bf16* Ah = (md < 3) ? g_xh : g_ah;
    const bf16* Am = (md < 3) ? g_xm : g_am;
    const bf16* Wh = g_wth + (size_t)md * DD * DD;
    const bf16* Wm = g_wtm + (size_t)md * DD * DD;
    const float* bias = (md == 1) ? b1 : (md == 2) ? b2 : b0;
    const float scale = (md == 0) ? 0.125f : 1.0f;
    bf16* OH = (md == 0) ? g_qh : g_kh;
    bf16* OM = (md == 0) ? g_qm : g_km;

    extern __shared__ bf16 sm[];
    bf16* sAh = sm;
    bf16* sAm = sm + SLAB;
    bf16* sBh = sm + 2 * SLAB;
    bf16* sBm = sm + 3 * SLAB;
    const uint32_t uAh = smem_u32(sAh);
    const uint32_t uBh = smem_u32(sBh);

    const int tid  = threadIdx.x;
    const int lane = tid & 31;
    const int warp = tid >> 5;
    const int wm = warp & 3, wn = warp >> 2;
    const int cm = blockIdx.x * 128, cn = blockIdx.y * 128;
    const int rq = lane >> 2, cq = lane & 3;

    // ldmatrix lane->row mappings
    const int a_r = lane & 15, a_k = (lane >> 4) * 8;               // A x4
    const int b_n = ((lane >> 3) & 1) * 8 + (lane & 7);             // B x4 (pair of n-tiles)
    const int b_k = (lane >> 4) * 8;

    auto issue = [&](int kt, int buf) {
        const int k0 = kt * KS;
        #pragma unroll
        for (int i = 0; i < 2; i++) {
            int idx = i * 256 + tid;
            int r = idx >> 2, c8 = (idx & 3) * 8;
            size_t ga = (size_t)(cm + r) * DD + k0 + c8;
            size_t gb = (size_t)(cn + r) * DD + k0 + c8;
            int so = buf * 128 * AST + r * AST + c8;
            cpa16(&sAh[so], Ah + ga);
            cpa16(&sAm[so], Am + ga);
            cpa16(&sBh[so], Wh + gb);
            cpa16(&sBm[so], Wm + gb);
        }
        cpa_commit();
    };

    float acc[2][8][4];
    #pragma unroll
    for (int mt = 0; mt < 2; mt++)
        #pragma unroll
        for (int nt = 0; nt < 8; nt++)
            #pragma unroll
            for (int j = 0; j < 4; j++) acc[mt][nt][j] = 0.f;

    const int NK = DD / KS;  // 32
    issue(0, 0);

    for (int kt = 0; kt < NK; ++kt) {
        const int cur = kt & 1;
        cpa_wait<0>();
        __syncthreads();
        if (kt + 1 < NK) issue(kt + 1, cur ^ 1);

        const uint32_t bufOff = (uint32_t)(cur * 128 * AST * 2);
        const uint32_t abase = uAh + bufOff + (uint32_t)(((wm * 32 + a_r) * AST + a_k) * 2);
        const uint32_t bbase = uBh + bufOff + (uint32_t)(((wn * 64 + b_n) * AST + b_k) * 2);
        #pragma unroll
        for (int ch = 0; ch < 2; ++ch) {
            const uint32_t kc2 = (uint32_t)(ch * 32);   // kc * 2 bytes
            unsigned ah[2][4], am[2][4];
            #pragma unroll
            for (int mt = 0; mt < 2; mt++) {
                uint32_t ad = abase + (uint32_t)(mt * 16 * AST * 2) + kc2;
                ldm_x4(ah[mt], ad);
                ldm_x4(am[mt], ad + GMOFF);
            }
            // pass A: aH * bH
            #pragma unroll
            for (int ntp = 0; ntp < 4; ntp++) {
                unsigned kf[4];
                ldm_x4(kf, bbase + (uint32_t)(ntp * 16 * AST * 2) + kc2);
                unsigned bb0[2] = {kf[0], kf[2]}, bb1[2] = {kf[1], kf[3]};
                mma_bf16(acc[0][2 * ntp],     ah[0], bb0);
                mma_bf16(acc[1][2 * ntp],     ah[1], bb0);
                mma_bf16(acc[0][2 * ntp + 1], ah[0], bb1);
                mma_bf16(acc[1][2 * ntp + 1], ah[1], bb1);
            }
            // pass B: aM * bH
            #pragma unroll
            for (int ntp = 0; ntp < 4; ntp++) {
                unsigned kf[4];
                ldm_x4(kf, bbase + (uint32_t)(ntp * 16 * AST * 2) + kc2);
                unsigned bb0[2] = {kf[0], kf[2]}, bb1[2] = {kf[1], kf[3]};
                mma_bf16(acc[0][2 * ntp],     am[0], bb0);
                mma_bf16(acc[1][2 * ntp],     am[1], bb0);
                mma_bf16(acc[0][2 * ntp + 1], am[0], bb1);
                mma_bf16(acc[1][2 * ntp + 1], am[1], bb1);
            }
            // pass C: aH * bM
            #pragma unroll
            for (int ntp = 0; ntp < 4; ntp++) {
                unsigned kf[4];
                ldm_x4(kf, bbase + (uint32_t)(ntp * 16 * AST * 2) + kc2 + GMOFF);
                unsigned bb0[2] = {kf[0], kf[2]}, bb1[2] = {kf[1], kf[3]};
                mma_bf16(acc[0][2 * ntp],     ah[0], bb0);
                mma_bf16(acc[1][2 * ntp],     ah[1], bb0);
                mma_bf16(acc[0][2 * ntp + 1], ah[0], bb1);
                mma_bf16(acc[1][2 * ntp + 1], ah[1], bb1);
            }
        }
    }

    // epilogue
    #pragma unroll
    for (int mt = 0; mt < 2; mt++) {
        int r = cm + wm * 32 + mt * 16 + rq;
        #pragma unroll
        for (int nt = 0; nt < 8; nt++) {
            int c = cn + wn * 64 + nt * 8 + cq * 2;
            float bb0 = bias[c], bb1 = bias[c + 1];
            float v0 = (acc[mt][nt][0] + bb0) * scale;
            float v1 = (acc[mt][nt][1] + bb1) * scale;
            float v2 = (acc[mt][nt][2] + bb0) * scale;
            float v3 = (acc[mt][nt][3] + bb1) * scale;
            if (md == 3) {
                *reinterpret_cast<float2*>(outF + (size_t)r * DD + c) = make_float2(v0, v1);
                *reinterpret_cast<float2*>(outF + (size_t)(r + 8) * DD + c) = make_float2(v2, v3);
            } else if (md == 2) {   // V: fp16 hi/mid
                unsigned mp0, mp1, hp0, hp1;
                hp0 = packHMh(v0, v1, mp0);
                hp1 = packHMh(v2, v3, mp1);
                *reinterpret_cast<unsigned*>(g_vh + (size_t)r * DD + c) = hp0;
                *reinterpret_cast<unsigned*>(g_vm + (size_t)r * DD + c) = mp0;
                *reinterpret_cast<unsigned*>(g_vh + (size_t)(r + 8) * DD + c) = hp1;
                *reinterpret_cast<unsigned*>(g_vm + (size_t)(r + 8) * DD + c) = mp1;
            } else {                // Q/K: bf16 hi/mid
                unsigned mp0, mp1, hp0, hp1;
                hp0 = packHM(v0, v1, mp0);
                hp1 = packHM(v2, v3, mp1);
                *reinterpret_cast<unsigned*>(OH + (size_t)r * DD + c) = hp0;
                *reinterpret_cast<unsigned*>(OM + (size_t)r * DD + c) = mp0;
                *reinterpret_cast<unsigned*>(OH + (size_t)(r + 8) * DD + c) = hp1;
                *reinterpret_cast<unsigned*>(OM + (size_t)(r + 8) * DD + c) = mp1;
            }
        }
    }
}

// ---------------------------------------------------------------------------
// Flash attention, 128-row Q tiles, 8 warps. QK: 3xBF16. PV: fp16 P (exact pack),
// 2-term fp16 V. Mask fast-path via ballots; above-diagonal warps skip iteration.
// smem halves: QH,QM (128xFST) | KH0,KM0,KH1,KM1 | VH0,VM0,VH1,VM1 (64xFST) | Ms[2][64]
// ---------------------------------------------------------------------------
#define FST 72                                // smem k-stride (halves)
#define F64 (64 * FST)                        // halves per 64-row array
#define QHALVES (2 * 128 * FST)               // QH+QM
#define QMOFF (128 * FST * 2)                 // Q hi->mid byte offset
#define KVMOFF (F64 * 2)                      // K/V hi->mid byte offset
#define FLASH_SMEM ((QHALVES + 8 * F64) * 2 + 2 * 64 * 4)   // 111104 bytes

__global__ __launch_bounds__(256, 2)
void flash_attn_kernel(const int* __restrict__ pmask)
{
    extern __shared__ bf16 fsm[];
    int* Ms0 = reinterpret_cast<int*>(fsm + QHALVES + 8 * F64);
    const uint32_t uQH = smem_u32(fsm);

    const int tid = threadIdx.x, lane = tid & 31, warp = tid >> 5;
    const int qb = (int)(gridDim.x - 1) - (int)blockIdx.x;  // heavy tiles first
    const int bh = blockIdx.y;
    const int b = bh >> 4, h = bh & 15;
    const size_t head_off = ((size_t)b * SS) * DD + (size_t)h * DHH;
    const int nkb = 2 * qb + 2;               // 64-wide key blocks needed

    const int rq = lane >> 2, cq = lane & 3;
    const int row0 = warp * 16 + rq;

    // ldmatrix lane->row mappings
    const int a_r = lane & 15, a_k = (lane >> 4) * 8;      // Q (A, x4)
    const int b_n = ((lane >> 3) & 1) * 8 + (lane & 7);    // K (B, x4 pair)
    const int b_k = (lane >> 4) * 8;
    const int v_k = ((lane >> 3) & 1) * 8 + (lane & 7);    // V (B^T via x4.trans)
    const int v_n = (lane >> 4) * 8;

    auto issueKV = [&](int kb) {
        const int bsel = kb & 1;
        bf16* KH = fsm + QHALVES + 2 * F64 * bsel;
        bf16* VH = fsm + QHALVES + 4 * F64 + 2 * F64 * bsel;
        #pragma unroll
        for (int i = 0; i < 2; i++) {
            int idx = i * 256 + tid;
            int r = idx >> 3, c8 = (idx & 7) * 8;
            size_t g = head_off + (size_t)(kb * 64 + r) * DD + c8;
            cpa16(&KH[r * FST + c8], g_kh + g);
            cpa16(&KH[F64 + r * FST + c8], g_km + g);
            cpa16(&VH[r * FST + c8], g_vh + g);
            cpa16(&VH[F64 + r * FST + c8], g_vm + g);
        }
        if (tid < 64) cpa4(&Ms0[bsel * 64 + tid], pmask + b * SS + kb * 64 + tid);
        cpa_commit();
    };

    // Prologue: Q (128x64 hi/mid) + K0/V0/mask0 in ONE group
    #pragma unroll
    for (int i = 0; i < 4; i++) {
        int idx = i * 256 + tid;
        int r = idx >> 3, c8 = (idx & 7) * 8;
        size_t g = head_off + (size_t)(qb * 128 + r) * DD + c8;
        cpa16(&fsm[r * FST + c8], g_qh + g);
        cpa16(&fsm[128 * FST + r * FST + c8], g_qm + g);
    }
    {
        bf16* KH = fsm + QHALVES;
        bf16* VH = fsm + QHALVES + 4 * F64;
        #pragma unroll
        for (int i = 0; i < 2; i++) {
            int idx = i * 256 + tid;
            int r = idx >> 3, c8 = (idx & 7) * 8;
            size_t g = head_off + (size_t)r * DD + c8;
            cpa16(&KH[r * FST + c8], g_kh + g);
            cpa16(&KH[F64 + r * FST + c8], g_km + g);
            cpa16(&VH[r * FST + c8], g_vh + g);
            cpa16(&VH[F64 + r * FST + c8], g_vm + g);
        }
        if (tid < 64) cpa4(&Ms0[tid], pmask + b * SS + tid);
        cpa_commit();
    }

    float o[8][4];
    #pragma unroll
    for (int nt = 0; nt < 8; nt++)
        #pragma unroll
        for (int j = 0; j < 4; j++) o[nt][j] = 0.f;
    float m0 = -1e30f, m1 = -1e30f, l0 = 0.f, l1 = 0.f;

    const uint32_t qbase = uQH + (uint32_t)(((warp * 16 + a_r) * FST + a_k) * 2);

    for (int kb = 0; kb < nkb; ++kb) {
        cpa_wait<0>();
        __syncthreads();
        if (kb + 1 < nkb) issueKV(kb + 1);

        // warp-uniform skip: entire kv-block above this warp's rows
        if (kb * 64 > qb * 128 + warp * 16 + 15) continue;

        const uint32_t uKH = smem_u32(fsm + QHALVES + 2 * F64 * (kb & 1));
        const uint32_t uVH = smem_u32(fsm + QHALVES + 4 * F64 + 2 * F64 * (kb & 1));
        const int* Ms = Ms0 + (kb & 1) * 64;

        // mask fast-path detection (warp-uniform)
        unsigned mw0 = __ballot_sync(0xffffffffu, Ms[lane] != 0);
        unsigned mw1 = __ballot_sync(0xffffffffu, Ms[32 + lane] != 0);
        const bool needmask = ((mw0 & mw1) != 0xffffffffu) ||
                              (kb * 64 + 63 > qb * 128 + warp * 16);

        // --- S = Q K^T (warp: 16 x 64), 3xBF16, term-major passes ---
        float sc[8][4];
        #pragma unroll
        for (int nt = 0; nt < 8; nt++)
            #pragma unroll
            for (int j = 0; j < 4; j++) sc[nt][j] = 0.f;

        const uint32_t kbase = uKH + (uint32_t)((b_n * FST + b_k) * 2);
        #pragma unroll
        for (int ch = 0; ch < 4; ++ch) {
            const uint32_t kc2 = (uint32_t)(ch * 32);
            unsigned ah[4], am[4];
            ldm_x4(ah, qbase + kc2);
            ldm_x4(am, qbase + kc2 + QMOFF);
            // pass A: qH * kH
            #pragma unroll
            for (int ntp = 0; ntp < 4; ntp++) {
                unsigned kf[4];
                ldm_x4(kf, kbase + (uint32_t)(ntp * 16 * FST * 2) + kc2);
                unsigned bb0[2] = {kf[0], kf[2]}, bb1[2] = {kf[1], kf[3]};
                mma_bf16(sc[2 * ntp],     ah, bb0);
                mma_bf16(sc[2 * ntp + 1], ah, bb1);
            }
            // pass B: qM * kH
            #pragma unroll
            for (int ntp = 0; ntp < 4; ntp++) {
                unsigned kf[4];
                ldm_x4(kf, kbase + (uint32_t)(ntp * 16 * FST * 2) + kc2);
                unsigned bb0[2] = {kf[0], kf[2]}, bb1[2] = {kf[1], kf[3]};
                mma_bf16(sc[2 * ntp],     am, bb0);
                mma_bf16(sc[2 * ntp + 1], am, bb1);
            }
            // pass C: qH * kM
            #pragma unroll
            for (int ntp = 0; ntp < 4; ntp++) {
                unsigned kf[4];
                ldm_x4(kf, kbase + (uint32_t)(ntp * 16 * FST * 2) + kc2 + KVMOFF);
                unsigned bb0[2] = {kf[0], kf[2]}, bb1[2] = {kf[1], kf[3]};
                mma_bf16(sc[2 * ntp],     ah, bb0);
                mma_bf16(sc[2 * ntp + 1], ah, bb1);
            }
        }

        // --- mask (slow path only; Q pre-scaled; sentinel -1e30) ---
        if (needmask) {
            const int gm0 = qb * 128 + row0, gm1 = gm0 + 8;
            #pragma unroll
            for (int nt = 0; nt < 8; nt++) {
                int nloc = nt * 8 + cq * 2;
                int gn = kb * 64 + nloc;
                #pragma unroll
                for (int j = 0; j < 2; j++) {
                    bool pv = (Ms[nloc + j] != 0);
                    sc[nt][j]     = (pv && (gn + j) <= gm0) ? sc[nt][j]     : -1e30f;
                    sc[nt][2 + j] = (pv && (gn + j) <= gm1) ? sc[nt][2 + j] : -1e30f;
                }
            }
        }

        // --- online softmax ---
        float mx0 = -1e30f, mx1 = -1e30f;
        #pragma unroll
        for (int nt = 0; nt < 8; nt++) {
            mx0 = fmaxf(mx0, fmaxf(sc[nt][0], sc[nt][1]));
            mx1 = fmaxf(mx1, fmaxf(sc[nt][2], sc[nt][3]));
        }
        mx0 = fmaxf(mx0, __shfl_xor_sync(0xffffffffu, mx0, 1));
        mx0 = fmaxf(mx0, __shfl_xor_sync(0xffffffffu, mx0, 2));
        mx1 = fmaxf(mx1, __shfl_xor_sync(0xffffffffu, mx1, 1));
        mx1 = fmaxf(mx1, __shfl_xor_sync(0xffffffffu, mx1, 2));

        float mn0 = fmaxf(m0, mx0), mn1 = fmaxf(m1, mx1);
        float al0 = ex2f((m0 - mn0) * LOG2E);
        float al1 = ex2f((m1 - mn1) * LOG2E);
        const float c0 = mn0 * LOG2E, c1 = mn1 * LOG2E;

        float s0 = 0.f, s1 = 0.f;
        #pragma unroll
        for (int nt = 0; nt < 8; nt++) {
            sc[nt][0] = ex2f(fmaf(sc[nt][0], LOG2E, -c0));
            sc[nt][1] = ex2f(fmaf(sc[nt][1], LOG2E, -c0));
            sc[nt][2] = ex2f(fmaf(sc[nt][2], LOG2E, -c1));
            sc[nt][3] = ex2f(fmaf(sc[nt][3], LOG2E, -c1));
            s0 += sc[nt][0] + sc[nt][1];
            s1 += sc[nt][2] + sc[nt][3];
        }
        s0 += __shfl_xor_sync(0xffffffffu, s0, 1);
        s0 += __shfl_xor_sync(0xffffffffu, s0, 2);
        s1 += __shfl_xor_sync(0xffffffffu, s1, 1);
        s1 += __shfl_xor_sync(0xffffffffu, s1, 2);

        l0 = l0 * al0 + s0;
        l1 = l1 * al1 + s1;
        m0 = mn0; m1 = mn1;

        #pragma unroll
        for (int nt = 0; nt < 8; nt++) {
            o[nt][0] *= al0; o[nt][1] *= al0;
            o[nt][2] *= al1; o[nt][3] *= al1;
        }

        // --- P -> fp16x2 fragments (exact pack, 1 instr per pair) ---
        unsigned pf[16];
        #pragma unroll
        for (int nt = 0; nt < 8; nt++) {
            pf[2 * nt]     = f16x2_of(sc[nt][1], sc[nt][0]);
            pf[2 * nt + 1] = f16x2_of(sc[nt][3], sc[nt][2]);
        }

        // --- O += P V (fp16, 2-term), term-major passes ---
        const uint32_t vbase = uVH + (uint32_t)((v_k * FST + v_n) * 2);
        #pragma unroll
        for (int ch = 0; ch < 4; ++ch) {
            unsigned* af = &pf[4 * ch];
            const uint32_t cOff = (uint32_t)(ch * 16 * FST * 2);
            // pass A: p * vH
            #pragma unroll
            for (int ntp = 0; ntp < 4; ntp++) {
                unsigned vf[4];
                ldm_x4t(vf, vbase + cOff + (uint32_t)(ntp * 16 * 2));
                unsigned bb0[2] = {vf[0], vf[1]}, bb1[2] = {vf[2], vf[3]};
                mma_f16(o[2 * ntp],     af, bb0);
                mma_f16(o[2 * ntp + 1], af, bb1);
            }
            // pass B: p * vM
            #pragma unroll
            for (int ntp = 0; ntp < 4; ntp++) {
                unsigned vf[4];
                ldm_x4t(vf, vbase + cOff + (uint32_t)(ntp * 16 * 2) + KVMOFF);
                unsigned bb0[2] = {vf[0], vf[1]}, bb1[2] = {vf[2], vf[3]};
                mma_f16(o[2 * ntp],     af, bb0);
                mma_f16(o[2 * ntp + 1], af, bb1);
            }
        }
    }

    // --- epilogue: normalize, split, store to g_a{h,m} [b, s, h, dh] ---
    float i0 = (l0 > 0.f) ? 1.f / l0 : 0.f;
    float i1 = (l1 > 0.f) ? 1.f / l1 : 0.f;
    size_t ob = head_off + (size_t)(qb * 128) * DD;
    #pragma unroll
    for (int nt = 0; nt < 8; nt++) {
        int c = nt * 8 + cq * 2;
        unsigned mp0, mp1, hp0, hp1;
        hp0 = packHM(o[nt][0] * i0, o[nt][1] * i0, mp0);
        hp1 = packHM(o[nt][2] * i1, o[nt][3] * i1, mp1);
        *reinterpret_cast<unsigned*>(g_ah + ob + (size_t)row0 * DD + c) = hp0;
        *reinterpret_cast<unsigned*>(g_am + ob + (size_t)row0 * DD + c) = mp0;
        *reinterpret_cast<unsigned*>(g_ah + ob + (size_t)(row0 + 8) * DD + c) = hp1;
        *reinterpret_cast<unsigned*>(g_am + ob + (size_t)(row0 + 8) * DD + c) = mp1;
    }
}

// ---------------------------------------------------------------------------
extern "C" void kernel_launch(void* const* d_in, const int* in_sizes, int n_in,
                              void* d_out, int out_size)
{
    (void)in_sizes; (void)n_in; (void)out_size;
    const float* x  = (const float*)d_in[0];
    const float* Wq = (const float*)d_in[1];
    const float* bq = (const float*)d_in[2];
    const float* Wk = (const float*)d_in[3];
    const float* bk = (const float*)d_in[4];
    const float* Wv = (const float*)d_in[5];
    const float* bv = (const float*)d_in[6];
    const float* Wo = (const float*)d_in[7];
    const float* bo = (const float*)d_in[8];
    const int*   pm = (const int*)d_in[9];
    float* out = (float*)d_out;

    cudaFuncSetAttribute(gemm_k, cudaFuncAttributeMaxDynamicSharedMemorySize, GEMM_SMEM);
    cudaFuncSetAttribute(flash_attn_kernel, cudaFuncAttributeMaxDynamicSharedMemorySize, FLASH_SMEM);

    split_src<<<(BSROWS * DD / 4) / 256, 256>>>(x);
    dim3 wgrid(32, 32, 4);
    wsplit_all<<<wgrid, 256>>>(Wq, Wk, Wv, Wo);

    dim3 qkvgrid(BSROWS / 128, DD / 128, 3);    // (64, 8, 3)
    gemm_k<<<qkvgrid, 256, GEMM_SMEM>>>(bq, bk, bv, nullptr, -1);

    dim3 fgrid(SS / 128, BB * HH);              // (16, 64)
    flash_attn_kernel<<<fgrid, 256, FLASH_SMEM>>>(pm);

    dim3 ogrid(BSROWS / 128, DD / 128, 1);
    gemm_k<<<ogrid, 256, GEMM_SMEM>>>(bo, nullptr, nullptr, out, 3);
}

// round 9
// speedup vs baseline: 1.4885x; 1.3740x over previous
#include <cuda_runtime.h>
#include <cuda_bf16.h>
#include <cuda_fp16.h>
#include <cstdint>

// Problem constants
#define BB 4
#define SS 2048
#define DD 1024
#define HH 16
#define DHH 64
#define BSROWS (BB * SS)          // 8192

// ---------------------------------------------------------------------------
// Device-global scratch (allocation-free). All fp16 now:
// x, q, attended: single; K, V, W: hi/mid 2-term.
// ---------------------------------------------------------------------------
__device__ __half g_x[(size_t)BSROWS * DD];
__device__ __half g_q[(size_t)BSROWS * DD];
__device__ __half g_kh[(size_t)BSROWS * DD], g_km[(size_t)BSROWS * DD];
__device__ __half g_vh[(size_t)BSROWS * DD], g_vm[(size_t)BSROWS * DD];
__device__ __half g_a[(size_t)BSROWS * DD];
__device__ __half g_wth[4 * (size_t)DD * DD], g_wtm[4 * (size_t)DD * DD];  // W^T [n][k]

#define LOG2E 1.4426950408889634f

// ---------------------------------------------------------------------------
// Helpers
// ---------------------------------------------------------------------------
__device__ __forceinline__ void mma_f16(float* c, const unsigned* a, const unsigned* b) {
    asm volatile(
        "mma.sync.aligned.m16n8k16.row.col.f32.f16.f16.f32 "
        "{%0,%1,%2,%3}, {%4,%5,%6,%7}, {%8,%9}, {%0,%1,%2,%3};\n"
        : "+f"(c[0]), "+f"(c[1]), "+f"(c[2]), "+f"(c[3])
        : "r"(a[0]), "r"(a[1]), "r"(a[2]), "r"(a[3]),
          "r"(b[0]), "r"(b[1]));
}

__device__ __forceinline__ void ldm_x4(unsigned* r, uint32_t addr) {
    asm volatile("ldmatrix.sync.aligned.m8n8.x4.shared.b16 {%0,%1,%2,%3}, [%4];"
        : "=r"(r[0]), "=r"(r[1]), "=r"(r[2]), "=r"(r[3]) : "r"(addr));
}
__device__ __forceinline__ void ldm_x4t(unsigned* r, uint32_t addr) {
    asm volatile("ldmatrix.sync.aligned.m8n8.x4.trans.shared.b16 {%0,%1,%2,%3}, [%4];"
        : "=r"(r[0]), "=r"(r[1]), "=r"(r[2]), "=r"(r[3]) : "r"(addr));
}

// fp16 split/pack
__device__ __forceinline__ unsigned packh2(__half lo, __half hi) {
    unsigned l = __half_as_ushort(lo), h = __half_as_ushort(hi);
    return l | (h << 16);
}
__device__ __forceinline__ void hsplit(float x, __half& h, __half& m) {
    h = __float2half_rn(x);
    m = __float2half_rn(x - __half2float(h));
}
__device__ __forceinline__ unsigned packHMh(float x, float y, unsigned& mp) {
    __half hx, mx, hy, my;
    hsplit(x, hx, mx);
    hsplit(y, hy, my);
    mp = packh2(mx, my);
    return packh2(hx, hy);
}
// f32 pair -> f16x2 (hi arg -> upper half)
__device__ __forceinline__ unsigned f16x2_of(float hi, float lo) {
    unsigned r;
    asm("cvt.rn.f16x2.f32 %0, %1, %2;" : "=r"(r) : "f"(hi), "f"(lo));
    return r;
}
__device__ __forceinline__ float ex2f(float x) {
    float r;
    asm("ex2.approx.ftz.f32 %0, %1;" : "=f"(r) : "f"(x));
    return r;
}

__device__ __forceinline__ void cpa16(void* s, const void* g) {
    unsigned sa = (unsigned)__cvta_generic_to_shared(s);
    asm volatile("cp.async.cg.shared.global [%0], [%1], 16;\n" :: "r"(sa), "l"(g));
}
__device__ __forceinline__ void cpa4(void* s, const void* g) {
    unsigned sa = (unsigned)__cvta_generic_to_shared(s);
    asm volatile("cp.async.ca.shared.global [%0], [%1], 4;\n" :: "r"(sa), "l"(g));
}
__device__ __forceinline__ void cpa_commit() {
    asm volatile("cp.async.commit_group;\n");
}
template <int N>
__device__ __forceinline__ void cpa_wait() {
    asm volatile("cp.async.wait_group %0;\n" :: "n"(N));
}
__device__ __forceinline__ uint32_t smem_u32(const void* p) {
    return (uint32_t)__cvta_generic_to_shared(p);
}

// ---------------------------------------------------------------------------
// Prep: x fp32 -> single fp16
// ---------------------------------------------------------------------------
__global__ __launch_bounds__(256)
void split_src(const float* __restrict__ x)
{
    int i = blockIdx.x * 256 + threadIdx.x;            // over float4s: 2M
    float4 v = reinterpret_cast<const float4*>(x)[i];
    uint2 u;
    u.x = f16x2_of(v.y, v.x);
    u.y = f16x2_of(v.w, v.z);
    reinterpret_cast<uint2*>(g_x)[i] = u;
}

// ---------------------------------------------------------------------------
// Prep: transpose + split all 4 W [k][n] fp32 -> g_wt{h,m}[z] as [n][k] fp16
// ---------------------------------------------------------------------------
__global__ __launch_bounds__(256)
void wsplit_all(const float* __restrict__ W0, const float* __restrict__ W1,
                const float* __restrict__ W2, const float* __restrict__ W3)
{
    const int widx = blockIdx.z;
    const float* W = (widx == 0) ? W0 : (widx == 1) ? W1 : (widx == 2) ? W2 : W3;
    __shared__ float t[32][33];
    const int kb = blockIdx.x * 32, nb = blockIdx.y * 32;
    const int r = threadIdx.x >> 3, c4 = (threadIdx.x & 7) * 4;
    float4 v = *reinterpret_cast<const float4*>(W + (size_t)(kb + r) * DD + nb + c4);
    t[r][c4 + 0] = v.x; t[r][c4 + 1] = v.y; t[r][c4 + 2] = v.z; t[r][c4 + 3] = v.w;
    __syncthreads();
    __half* oh = g_wth + (size_t)widx * DD * DD;
    __half* om = g_wtm + (size_t)widx * DD * DD;
    uint2 uh, um;
    uh.x = packHMh(t[c4 + 0][r], t[c4 + 1][r], um.x);
    uh.y = packHMh(t[c4 + 2][r], t[c4 + 3][r], um.y);
    size_t o = (size_t)(nb + r) * DD + kb + c4;
    *reinterpret_cast<uint2*>(oh + o) = uh;
    *reinterpret_cast<uint2*>(om + o) = um;
}

// ---------------------------------------------------------------------------
// GEMM (2-term fp16, m16n8k16 + ldmatrix): C = A * W^T' + bias, M=8192, N=K=1024
// A single fp16, W 2-term (hi/mid). CTA 128x128, kstep 32, 256 thr, cp.async dbuf.
// mode -1: md=blockIdx.z (Q: single fp16 scaled 1/8; K,V: fp16 hi/mid)
// mode  3: A=g_a (attended), out fp32 to outF
// ---------------------------------------------------------------------------
#define KS 32
#define AST 40
#define SLAB (2 * 128 * AST)                 // halves per (dbuf) array
#define GEMM_SMEM (3 * SLAB * 2)             // 61440 bytes (sA, sBh, sBm)
#define GMOFF (SLAB * 2)                     // sBh->sBm byte offset

__global__ __launch_bounds__(256, 2)
void gemm_k(const float* __restrict__ b0, const float* __restrict__ b1,
            const float* __restrict__ b2, float* __restrict__ outF, int mode)
{
    const int md = (mode < 0) ? (int)blockIdx.z : mode;
    const __half* A = (md < 3) ? g_x : g_a;
    const __half* Wh = g_wth + (size_t)md * DD * DD;
    const __half* Wm = g_wtm + (size_t)md * DD * DD;
    const float* bias = (md == 1) ? b1 : (md == 2) ? b2 : b0;
    const float scale = (md == 0) ? 0.125f : 1.0f;

    extern __shared__ __half sm[];
    __half* sA  = sm;
    __half* sBh = sm + SLAB;
    __half* sBm = sm + 2 * SLAB;
    const uint32_t uA  = smem_u32(sA);
    const uint32_t uBh = smem_u32(sBh);

    const int tid  = threadIdx.x;
    const int lane = tid & 31;
    const int warp = tid >> 5;
    const int wm = warp & 3, wn = warp >> 2;
    const int cm = blockIdx.x * 128, cn = blockIdx.y * 128;
    const int rq = lane >> 2, cq = lane & 3;

    // ldmatrix lane->row mappings
    const int a_r = lane & 15, a_k = (lane >> 4) * 8;               // A x4
    const int b_n = ((lane >> 3) & 1) * 8 + (lane & 7);             // B x4 (pair of n-tiles)
    const int b_k = (lane >> 4) * 8;

    auto issue = [&](int kt, int buf) {
        const int k0 = kt * KS;
        #pragma unroll
        for (int i = 0; i < 2; i++) {
            int idx = i * 256 + tid;
            int r = idx >> 2, c8 = (idx & 3) * 8;
            size_t ga = (size_t)(cm + r) * DD + k0 + c8;
            size_t gb = (size_t)(cn + r) * DD + k0 + c8;
            int so = buf * 128 * AST + r * AST + c8;
            cpa16(&sA[so],  A + ga);
            cpa16(&sBh[so], Wh + gb);
            cpa16(&sBm[so], Wm + gb);
        }
        cpa_commit();
    };

    float acc[2][8][4];
    #pragma unroll
    for (int mt = 0; mt < 2; mt++)
        #pragma unroll
        for (int nt = 0; nt < 8; nt++)
            #pragma unroll
            for (int j = 0; j < 4; j++) acc[mt][nt][j] = 0.f;

    const int NK = DD / KS;  // 32
    issue(0, 0);

    for (int kt = 0; kt < NK; ++kt) {
        const int cur = kt & 1;
        cpa_wait<0>();
        __syncthreads();
        if (kt + 1 < NK) issue(kt + 1, cur ^ 1);

        const uint32_t bufOff = (uint32_t)(cur * 128 * AST * 2);
        const uint32_t abase = uA  + bufOff + (uint32_t)(((wm * 32 + a_r) * AST + a_k) * 2);
        const uint32_t bbase = uBh + bufOff + (uint32_t)(((wn * 64 + b_n) * AST + b_k) * 2);
        #pragma unroll
        for (int ch = 0; ch < 2; ++ch) {
            const uint32_t kc2 = (uint32_t)(ch * 32);   // kc * 2 bytes
            unsigned ah[2][4];
            #pragma unroll
            for (int mt = 0; mt < 2; mt++)
                ldm_x4(ah[mt], abase + (uint32_t)(mt * 16 * AST * 2) + kc2);
            // pass A: a * wH
            #pragma unroll
            for (int ntp = 0; ntp < 4; ntp++) {
                unsigned kf[4];
                ldm_x4(kf, bbase + (uint32_t)(ntp * 16 * AST * 2) + kc2);
                unsigned bb0[2] = {kf[0], kf[2]}, bb1[2] = {kf[1], kf[3]};
                mma_f16(acc[0][2 * ntp],     ah[0], bb0);
                mma_f16(acc[1][2 * ntp],     ah[1], bb0);
                mma_f16(acc[0][2 * ntp + 1], ah[0], bb1);
                mma_f16(acc[1][2 * ntp + 1], ah[1], bb1);
            }
            // pass B: a * wM
            #pragma unroll
            for (int ntp = 0; ntp < 4; ntp++) {
                unsigned kf[4];
                ldm_x4(kf, bbase + (uint32_t)(ntp * 16 * AST * 2) + kc2 + GMOFF);
                unsigned bb0[2] = {kf[0], kf[2]}, bb1[2] = {kf[1], kf[3]};
                mma_f16(acc[0][2 * ntp],     ah[0], bb0);
                mma_f16(acc[1][2 * ntp],     ah[1], bb0);
                mma_f16(acc[0][2 * ntp + 1], ah[0], bb1);
                mma_f16(acc[1][2 * ntp + 1], ah[1], bb1);
            }
        }
    }

    // epilogue
    #pragma unroll
    for (int mt = 0; mt < 2; mt++) {
        int r = cm + wm * 32 + mt * 16 + rq;
        #pragma unroll
        for (int nt = 0; nt < 8; nt++) {
            int c = cn + wn * 64 + nt * 8 + cq * 2;
            float bb0 = bias[c], bb1 = bias[c + 1];
            float v0 = (acc[mt][nt][0] + bb0) * scale;
            float v1 = (acc[mt][nt][1] + bb1) * scale;
            float v2 = (acc[mt][nt][2] + bb0) * scale;
            float v3 = (acc[mt][nt][3] + bb1) * scale;
            if (md == 3) {
                *reinterpret_cast<float2*>(outF + (size_t)r * DD + c) = make_float2(v0, v1);
                *reinterpret_cast<float2*>(outF + (size_t)(r + 8) * DD + c) = make_float2(v2, v3);
            } else if (md == 0) {   // Q: single fp16 (pre-scaled)
                *reinterpret_cast<unsigned*>(g_q + (size_t)r * DD + c) = f16x2_of(v1, v0);
                *reinterpret_cast<unsigned*>(g_q + (size_t)(r + 8) * DD + c) = f16x2_of(v3, v2);
            } else {                // K/V: fp16 hi/mid
                __half* OH = (md == 1) ? g_kh : g_vh;
                __half* OM = (md == 1) ? g_km : g_vm;
                unsigned mp0, mp1, hp0, hp1;
                hp0 = packHMh(v0, v1, mp0);
                hp1 = packHMh(v2, v3, mp1);
                *reinterpret_cast<unsigned*>(OH + (size_t)r * DD + c) = hp0;
                *reinterpret_cast<unsigned*>(OM + (size_t)r * DD + c) = mp0;
                *reinterpret_cast<unsigned*>(OH + (size_t)(r + 8) * DD + c) = hp1;
                *reinterpret_cast<unsigned*>(OM + (size_t)(r + 8) * DD + c) = mp1;
            }
        }
    }
}

// ---------------------------------------------------------------------------
// Flash attention, 128-row Q tiles, 8 warps. QK: Q single fp16 x K 2-term fp16.
// PV: fp16 P (exact pack) x V 2-term fp16. Mask fast-path; diag-skip warps.
// smem halves: Q (128xFST) | KH0,KM0,KH1,KM1 | VH0,VM0,VH1,VM1 (64xFST) | Ms[2][64]
// ---------------------------------------------------------------------------
#define FST 72                                // smem k-stride (halves)
#define F64 (64 * FST)                        // halves per 64-row array
#define QFQ (128 * FST)                       // Q halves
#define KOFF QFQ
#define VOFF (QFQ + 4 * F64)
#define KVMOFF (F64 * 2)                      // hi->mid byte offset
#define FLASH_SMEM ((QFQ + 8 * F64) * 2 + 2 * 64 * 4)   // 92672 bytes

__global__ __launch_bounds__(256, 2)
void flash_attn_kernel(const int* __restrict__ pmask)
{
    extern __shared__ __half fsm[];
    int* Ms0 = reinterpret_cast<int*>(fsm + QFQ + 8 * F64);
    const uint32_t uQ = smem_u32(fsm);

    const int tid = threadIdx.x, lane = tid & 31, warp = tid >> 5;
    const int qb = (int)(gridDim.x - 1) - (int)blockIdx.x;  // heavy tiles first
    const int bh = blockIdx.y;
    const int b = bh >> 4, h = bh & 15;
    const size_t head_off = ((size_t)b * SS) * DD + (size_t)h * DHH;
    const int nkb = 2 * qb + 2;               // 64-wide key blocks needed

    const int rq = lane >> 2, cq = lane & 3;
    const int row0 = warp * 16 + rq;

    // ldmatrix lane->row mappings
    const int a_r = lane & 15, a_k = (lane >> 4) * 8;      // Q (A, x4)
    const int b_n = ((lane >> 3) & 1) * 8 + (lane & 7);    // K (B, x4 pair)
    const int b_k = (lane >> 4) * 8;
    const int v_k = ((lane >> 3) & 1) * 8 + (lane & 7);    // V (B^T via x4.trans)
    const int v_n = (lane >> 4) * 8;

    auto issueKV = [&](int kb) {
        const int bsel = kb & 1;
        __half* KH = fsm + KOFF + 2 * F64 * bsel;
        __half* VH = fsm + VOFF + 2 * F64 * bsel;
        #pragma unroll
        for (int i = 0; i < 2; i++) {
            int idx = i * 256 + tid;
            int r = idx >> 3, c8 = (idx & 7) * 8;
            size_t g = head_off + (size_t)(kb * 64 + r) * DD + c8;
            cpa16(&KH[r * FST + c8], g_kh + g);
            cpa16(&KH[F64 + r * FST + c8], g_km + g);
            cpa16(&VH[r * FST + c8], g_vh + g);
            cpa16(&VH[F64 + r * FST + c8], g_vm + g);
        }
        if (tid < 64) cpa4(&Ms0[bsel * 64 + tid], pmask + b * SS + kb * 64 + tid);
        cpa_commit();
    };

    // Prologue: Q (128x64 single fp16) + K0/V0/mask0 in ONE group
    #pragma unroll
    for (int i = 0; i < 4; i++) {
        int idx = i * 256 + tid;
        int r = idx >> 3, c8 = (idx & 7) * 8;
        size_t g = head_off + (size_t)(qb * 128 + r) * DD + c8;
        cpa16(&fsm[r * FST + c8], g_q + g);
    }
    {
        __half* KH = fsm + KOFF;
        __half* VH = fsm + VOFF;
        #pragma unroll
        for (int i = 0; i < 2; i++) {
            int idx = i * 256 + tid;
            int r = idx >> 3, c8 = (idx & 7) * 8;
            size_t g = head_off + (size_t)r * DD + c8;
            cpa16(&KH[r * FST + c8], g_kh + g);
            cpa16(&KH[F64 + r * FST + c8], g_km + g);
            cpa16(&VH[r * FST + c8], g_vh + g);
            cpa16(&VH[F64 + r * FST + c8], g_vm + g);
        }
        if (tid < 64) cpa4(&Ms0[tid], pmask + b * SS + tid);
        cpa_commit();
    }

    float o[8][4];
    #pragma unroll
    for (int nt = 0; nt < 8; nt++)
        #pragma unroll
        for (int j = 0; j < 4; j++) o[nt][j] = 0.f;
    float m0 = -1e30f, m1 = -1e30f, l0 = 0.f, l1 = 0.f;

    const uint32_t qbase = uQ + (uint32_t)(((warp * 16 + a_r) * FST + a_k) * 2);

    for (int kb = 0; kb < nkb; ++kb) {
        cpa_wait<0>();
        __syncthreads();
        if (kb + 1 < nkb) issueKV(kb + 1);

        // warp-uniform skip: entire kv-block above this warp's rows
        if (kb * 64 > qb * 128 + warp * 16 + 15) continue;

        const uint32_t uKH = smem_u32(fsm + KOFF + 2 * F64 * (kb & 1));
        const uint32_t uVH = smem_u32(fsm + VOFF + 2 * F64 * (kb & 1));
        const int* Ms = Ms0 + (kb & 1) * 64;

        // mask fast-path detection (warp-uniform)
        unsigned mw0 = __ballot_sync(0xffffffffu, Ms[lane] != 0);
        unsigned mw1 = __ballot_sync(0xffffffffu, Ms[32 + lane] != 0);
        const bool needmask = ((mw0 & mw1) != 0xffffffffu) ||
                              (kb * 64 + 63 > qb * 128 + warp * 16);

        // --- S = Q K^T (warp: 16 x 64): q x (kH, kM), term-major ---
        float sc[8][4];
        #pragma unroll
        for (int nt = 0; nt < 8; nt++)
            #pragma unroll
            for (int j = 0; j < 4; j++) sc[nt][j] = 0.f;

        const uint32_t kbase = uKH + (uint32_t)((b_n * FST + b_k) * 2);
        #pragma unroll
        for (int ch = 0; ch < 4; ++ch) {
            const uint32_t kc2 = (uint32_t)(ch * 32);
            unsigned ah[4];
            ldm_x4(ah, qbase + kc2);
            // pass A: q * kH
            #pragma unroll
            for (int ntp = 0; ntp < 4; ntp++) {
                unsigned kf[4];
                ldm_x4(kf, kbase + (uint32_t)(ntp * 16 * FST * 2) + kc2);
                unsigned bb0[2] = {kf[0], kf[2]}, bb1[2] = {kf[1], kf[3]};
                mma_f16(sc[2 * ntp],     ah, bb0);
                mma_f16(sc[2 * ntp + 1], ah, bb1);
            }
            // pass B: q * kM
            #pragma unroll
            for (int ntp = 0; ntp < 4; ntp++) {
                unsigned kf[4];
                ldm_x4(kf, kbase + (uint32_t)(ntp * 16 * FST * 2) + kc2 + KVMOFF);
                unsigned bb0[2] = {kf[0], kf[2]}, bb1[2] = {kf[1], kf[3]};
                mma_f16(sc[2 * ntp],     ah, bb0);
                mma_f16(sc[2 * ntp + 1], ah, bb1);
            }
        }

        // --- mask (slow path only; Q pre-scaled; sentinel -1e30) ---
        if (needmask) {
            const int gm0 = qb * 128 + row0, gm1 = gm0 + 8;
            #pragma unroll
            for (int nt = 0; nt < 8; nt++) {
                int nloc = nt * 8 + cq * 2;
                int gn = kb * 64 + nloc;
                #pragma unroll
                for (int j = 0; j < 2; j++) {
                    bool pv = (Ms[nloc + j] != 0);
                    sc[nt][j]     = (pv && (gn + j) <= gm0) ? sc[nt][j]     : -1e30f;
                    sc[nt][2 + j] = (pv && (gn + j) <= gm1) ? sc[nt][2 + j] : -1e30f;
                }
            }
        }

        // --- online softmax ---
        float mx0 = -1e30f, mx1 = -1e30f;
        #pragma unroll
        for (int nt = 0; nt < 8; nt++) {
            mx0 = fmaxf(mx0, fmaxf(sc[nt][0], sc[nt][1]));
            mx1 = fmaxf(mx1, fmaxf(sc[nt][2], sc[nt][3]));
        }
        mx0 = fmaxf(mx0, __shfl_xor_sync(0xffffffffu, mx0, 1));
        mx0 = fmaxf(mx0, __shfl_xor_sync(0xffffffffu, mx0, 2));
        mx1 = fmaxf(mx1, __shfl_xor_sync(0xffffffffu, mx1, 1));
        mx1 = fmaxf(mx1, __shfl_xor_sync(0xffffffffu, mx1, 2));

        float mn0 = fmaxf(m0, mx0), mn1 = fmaxf(m1, mx1);
        float al0 = ex2f((m0 - mn0) * LOG2E);
        float al1 = ex2f((m1 - mn1) * LOG2E);
        const float c0 = mn0 * LOG2E, c1 = mn1 * LOG2E;

        float s0 = 0.f, s1 = 0.f;
        #pragma unroll
        for (int nt = 0; nt < 8; nt++) {
            sc[nt][0] = ex2f(fmaf(sc[nt][0], LOG2E, -c0));
            sc[nt][1] = ex2f(fmaf(sc[nt][1], LOG2E, -c0));
            sc[nt][2] = ex2f(fmaf(sc[nt][2], LOG2E, -c1));
            sc[nt][3] = ex2f(fmaf(sc[nt][3], LOG2E, -c1));
            s0 += sc[nt][0] + sc[nt][1];
            s1 += sc[nt][2] + sc[nt][3];
        }
        s0 += __shfl_xor_sync(0xffffffffu, s0, 1);
        s0 += __shfl_xor_sync(0xffffffffu, s0, 2);
        s1 += __shfl_xor_sync(0xffffffffu, s1, 1);
        s1 += __shfl_xor_sync(0xffffffffu, s1, 2);

        l0 = l0 * al0 + s0;
        l1 = l1 * al1 + s1;
        m0 = mn0; m1 = mn1;

        #pragma unroll
        for (int nt = 0; nt < 8; nt++) {
            o[nt][0] *= al0; o[nt][1] *= al0;
            o[nt][2] *= al1; o[nt][3] *= al1;
        }

        // --- P -> fp16x2 fragments (exact pack) ---
        unsigned pf[16];
        #pragma unroll
        for (int nt = 0; nt < 8; nt++) {
            pf[2 * nt]     = f16x2_of(sc[nt][1], sc[nt][0]);
            pf[2 * nt + 1] = f16x2_of(sc[nt][3], sc[nt][2]);
        }

        // --- O += P V (fp16, 2-term), term-major ---
        const uint32_t vbase = uVH + (uint32_t)((v_k * FST + v_n) * 2);
        #pragma unroll
        for (int ch = 0; ch < 4; ++ch) {
            unsigned* af = &pf[4 * ch];
            const uint32_t cOff = (uint32_t)(ch * 16 * FST * 2);
            // pass A: p * vH
            #pragma unroll
            for (int ntp = 0; ntp < 4; ntp++) {
                unsigned vf[4];
                ldm_x4t(vf, vbase + cOff + (uint32_t)(ntp * 16 * 2));
                unsigned bb0[2] = {vf[0], vf[1]}, bb1[2] = {vf[2], vf[3]};
                mma_f16(o[2 * ntp],     af, bb0);
                mma_f16(o[2 * ntp + 1], af, bb1);
            }
            // pass B: p * vM
            #pragma unroll
            for (int ntp = 0; ntp < 4; ntp++) {
                unsigned vf[4];
                ldm_x4t(vf, vbase + cOff + (uint32_t)(ntp * 16 * 2) + KVMOFF);
                unsigned bb0[2] = {vf[0], vf[1]}, bb1[2] = {vf[2], vf[3]};
                mma_f16(o[2 * ntp],     af, bb0);
                mma_f16(o[2 * ntp + 1], af, bb1);
            }
        }
    }

    // --- epilogue: normalize, store single fp16 to g_a [b, s, h, dh] ---
    float i0 = (l0 > 0.f) ? 1.f / l0 : 0.f;
    float i1 = (l1 > 0.f) ? 1.f / l1 : 0.f;
    size_t ob = head_off + (size_t)(qb * 128) * DD;
    #pragma unroll
    for (int nt = 0; nt < 8; nt++) {
        int c = nt * 8 + cq * 2;
        *reinterpret_cast<unsigned*>(g_a + ob + (size_t)row0 * DD + c) =
            f16x2_of(o[nt][1] * i0, o[nt][0] * i0);
        *reinterpret_cast<unsigned*>(g_a + ob + (size_t)(row0 + 8) * DD + c) =
            f16x2_of(o[nt][3] * i1, o[nt][2] * i1);
    }
}

// ---------------------------------------------------------------------------
extern "C" void kernel_launch(void* const* d_in, const int* in_sizes, int n_in,
                              void* d_out, int out_size)
{
    (void)in_sizes; (void)n_in; (void)out_size;
    const float* x  = (const float*)d_in[0];
    const float* Wq = (const float*)d_in[1];
    const float* bq = (const float*)d_in[2];
    const float* Wk = (const float*)d_in[3];
    const float* bk = (const float*)d_in[4];
    const float* Wv = (const float*)d_in[5];
    const float* bv = (const float*)d_in[6];
    const float* Wo = (const float*)d_in[7];
    const float* bo = (const float*)d_in[8];
    const int*   pm = (const int*)d_in[9];
    float* out = (float*)d_out;

    cudaFuncSetAttribute(gemm_k, cudaFuncAttributeMaxDynamicSharedMemorySize, GEMM_SMEM);
    cudaFuncSetAttribute(flash_attn_kernel, cudaFuncAttributeMaxDynamicSharedMemorySize, FLASH_SMEM);

    split_src<<<(BSROWS * DD / 4) / 256, 256>>>(x);
    dim3 wgrid(32, 32, 4);
    wsplit_all<<<wgrid, 256>>>(Wq, Wk, Wv, Wo);

    dim3 qkvgrid(BSROWS / 128, DD / 128, 3);    // (64, 8, 3)
    gemm_k<<<qkvgrid, 256, GEMM_SMEM>>>(bq, bk, bv, nullptr, -1);

    dim3 fgrid(SS / 128, BB * HH);              // (16, 64)
    flash_attn_kernel<<<fgrid, 256, FLASH_SMEM>>>(pm);

    dim3 ogrid(BSROWS / 128, DD / 128, 1);
    gemm_k<<<ogrid, 256, GEMM_SMEM>>>(bo, nullptr, nullptr, out, 3);
}

// round 10
// speedup vs baseline: 1.5560x; 1.0454x over previous
#include <cuda_runtime.h>
#include <cuda_bf16.h>
#include <cuda_fp16.h>
#include <cstdint>

// Problem constants
#define BB 4
#define SS 2048
#define DD 1024
#define HH 16
#define DHH 64
#define BSROWS (BB * SS)          // 8192

// ---------------------------------------------------------------------------
// Device-global scratch (allocation-free). fp16:
// x, q, v, attended: single; K, W: hi/mid 2-term.
// ---------------------------------------------------------------------------
__device__ __half g_x[(size_t)BSROWS * DD];
__device__ __half g_q[(size_t)BSROWS * DD];
__device__ __half g_kh[(size_t)BSROWS * DD], g_km[(size_t)BSROWS * DD];
__device__ __half g_v[(size_t)BSROWS * DD];
__device__ __half g_a[(size_t)BSROWS * DD];
__device__ __half g_wth[4 * (size_t)DD * DD], g_wtm[4 * (size_t)DD * DD];  // W^T [n][k]

#define LOG2E 1.4426950408889634f

// ---------------------------------------------------------------------------
// Helpers
// ---------------------------------------------------------------------------
__device__ __forceinline__ void mma_f16(float* c, const unsigned* a, const unsigned* b) {
    asm volatile(
        "mma.sync.aligned.m16n8k16.row.col.f32.f16.f16.f32 "
        "{%0,%1,%2,%3}, {%4,%5,%6,%7}, {%8,%9}, {%0,%1,%2,%3};\n"
        : "+f"(c[0]), "+f"(c[1]), "+f"(c[2]), "+f"(c[3])
        : "r"(a[0]), "r"(a[1]), "r"(a[2]), "r"(a[3]),
          "r"(b[0]), "r"(b[1]));
}

__device__ __forceinline__ void ldm_x4(unsigned* r, uint32_t addr) {
    asm volatile("ldmatrix.sync.aligned.m8n8.x4.shared.b16 {%0,%1,%2,%3}, [%4];"
        : "=r"(r[0]), "=r"(r[1]), "=r"(r[2]), "=r"(r[3]) : "r"(addr));
}
__device__ __forceinline__ void ldm_x4t(unsigned* r, uint32_t addr) {
    asm volatile("ldmatrix.sync.aligned.m8n8.x4.trans.shared.b16 {%0,%1,%2,%3}, [%4];"
        : "=r"(r[0]), "=r"(r[1]), "=r"(r[2]), "=r"(r[3]) : "r"(addr));
}

// fp16 split/pack
__device__ __forceinline__ unsigned packh2(__half lo, __half hi) {
    unsigned l = __half_as_ushort(lo), h = __half_as_ushort(hi);
    return l | (h << 16);
}
__device__ __forceinline__ void hsplit(float x, __half& h, __half& m) {
    h = __float2half_rn(x);
    m = __float2half_rn(x - __half2float(h));
}
__device__ __forceinline__ unsigned packHMh(float x, float y, unsigned& mp) {
    __half hx, mx, hy, my;
    hsplit(x, hx, mx);
    hsplit(y, hy, my);
    mp = packh2(mx, my);
    return packh2(hx, hy);
}
// f32 pair -> f16x2 (hi arg -> upper half)
__device__ __forceinline__ unsigned f16x2_of(float hi, float lo) {
    unsigned r;
    asm("cvt.rn.f16x2.f32 %0, %1, %2;" : "=r"(r) : "f"(hi), "f"(lo));
    return r;
}
__device__ __forceinline__ float ex2f(float x) {
    float r;
    asm("ex2.approx.ftz.f32 %0, %1;" : "=f"(r) : "f"(x));
    return r;
}

__device__ __forceinline__ void cpa16(void* s, const void* g) {
    unsigned sa = (unsigned)__cvta_generic_to_shared(s);
    asm volatile("cp.async.cg.shared.global [%0], [%1], 16;\n" :: "r"(sa), "l"(g));
}
__device__ __forceinline__ void cpa4(void* s, const void* g) {
    unsigned sa = (unsigned)__cvta_generic_to_shared(s);
    asm volatile("cp.async.ca.shared.global [%0], [%1], 4;\n" :: "r"(sa), "l"(g));
}
__device__ __forceinline__ void cpa_commit() {
    asm volatile("cp.async.commit_group;\n");
}
template <int N>
__device__ __forceinline__ void cpa_wait() {
    asm volatile("cp.async.wait_group %0;\n" :: "n"(N));
}
__device__ __forceinline__ uint32_t smem_u32(const void* p) {
    return (uint32_t)__cvta_generic_to_shared(p);
}

// ---------------------------------------------------------------------------
// Prep: x fp32 -> single fp16
// ---------------------------------------------------------------------------
__global__ __launch_bounds__(256)
void split_src(const float* __restrict__ x)
{
    int i = blockIdx.x * 256 + threadIdx.x;            // over float4s: 2M
    float4 v = reinterpret_cast<const float4*>(x)[i];
    uint2 u;
    u.x = f16x2_of(v.y, v.x);
    u.y = f16x2_of(v.w, v.z);
    reinterpret_cast<uint2*>(g_x)[i] = u;
}

// ---------------------------------------------------------------------------
// Prep: transpose + split all 4 W [k][n] fp32 -> g_wt{h,m}[z] as [n][k] fp16
// ---------------------------------------------------------------------------
__global__ __launch_bounds__(256)
void wsplit_all(const float* __restrict__ W0, const float* __restrict__ W1,
                const float* __restrict__ W2, const float* __restrict__ W3)
{
    const int widx = blockIdx.z;
    const float* W = (widx == 0) ? W0 : (widx == 1) ? W1 : (widx == 2) ? W2 : W3;
    __shared__ float t[32][33];
    const int kb = blockIdx.x * 32, nb = blockIdx.y * 32;
    const int r = threadIdx.x >> 3, c4 = (threadIdx.x & 7) * 4;
    float4 v = *reinterpret_cast<const float4*>(W + (size_t)(kb + r) * DD + nb + c4);
    t[r][c4 + 0] = v.x; t[r][c4 + 1] = v.y; t[r][c4 + 2] = v.z; t[r][c4 + 3] = v.w;
    __syncthreads();
    __half* oh = g_wth + (size_t)widx * DD * DD;
    __half* om = g_wtm + (size_t)widx * DD * DD;
    uint2 uh, um;
    uh.x = packHMh(t[c4 + 0][r], t[c4 + 1][r], um.x);
    uh.y = packHMh(t[c4 + 2][r], t[c4 + 3][r], um.y);
    size_t o = (size_t)(nb + r) * DD + kb + c4;
    *reinterpret_cast<uint2*>(oh + o) = uh;
    *reinterpret_cast<uint2*>(om + o) = um;
}

// ---------------------------------------------------------------------------
// GEMM (2-term fp16, m16n8k16 + ldmatrix): C = A * W^T' + bias, M=8192, N=K=1024
// A single fp16, W 2-term (hi/mid). CTA 128x128, kstep 32, 256 thr.
// 3-stage cp.async pipeline (prefetch distance 2 iterations).
// mode -1: md=blockIdx.z (Q: fp16 scaled 1/8; K: fp16 hi/mid; V: single fp16)
// mode  3: A=g_a (attended), out fp32 to outF
// ---------------------------------------------------------------------------
#define KS 32
#define AST 40
#define NSTG 3
#define SLAB (NSTG * 128 * AST)              // halves per (3-buf) array
#define GEMM_SMEM (3 * SLAB * 2)             // 92160 bytes (sA, sBh, sBm)
#define GMOFF (SLAB * 2)                     // sBh->sBm byte offset

__global__ __launch_bounds__(256, 2)
void gemm_k(const float* __restrict__ b0, const float* __restrict__ b1,
            const float* __restrict__ b2, float* __restrict__ outF, int mode)
{
    const int md = (mode < 0) ? (int)blockIdx.z : mode;
    const __half* A = (md < 3) ? g_x : g_a;
    const __half* Wh = g_wth + (size_t)md * DD * DD;
    const __half* Wm = g_wtm + (size_t)md * DD * DD;
    const float* bias = (md == 1) ? b1 : (md == 2) ? b2 : b0;
    const float scale = (md == 0) ? 0.125f : 1.0f;

    extern __shared__ __half sm[];
    __half* sA  = sm;
    __half* sBh = sm + SLAB;
    __half* sBm = sm + 2 * SLAB;
    const uint32_t uA  = smem_u32(sA);
    const uint32_t uBh = smem_u32(sBh);

    const int tid  = threadIdx.x;
    const int lane = tid & 31;
    const int warp = tid >> 5;
    const int wm = warp & 3, wn = warp >> 2;
    const int cm = blockIdx.x * 128, cn = blockIdx.y * 128;
    const int rq = lane >> 2, cq = lane & 3;

    // ldmatrix lane->row mappings
    const int a_r = lane & 15, a_k = (lane >> 4) * 8;               // A x4
    const int b_n = ((lane >> 3) & 1) * 8 + (lane & 7);             // B x4 (pair of n-tiles)
    const int b_k = (lane >> 4) * 8;

    auto issue = [&](int kt, int buf) {
        const int k0 = kt * KS;
        #pragma unroll
        for (int i = 0; i < 2; i++) {
            int idx = i * 256 + tid;
            int r = idx >> 2, c8 = (idx & 3) * 8;
            size_t ga = (size_t)(cm + r) * DD + k0 + c8;
            size_t gb = (size_t)(cn + r) * DD + k0 + c8;
            int so = buf * 128 * AST + r * AST + c8;
            cpa16(&sA[so],  A + ga);
            cpa16(&sBh[so], Wh + gb);
            cpa16(&sBm[so], Wm + gb);
        }
        cpa_commit();
    };

    float acc[2][8][4];
    #pragma unroll
    for (int mt = 0; mt < 2; mt++)
        #pragma unroll
        for (int nt = 0; nt < 8; nt++)
            #pragma unroll
            for (int j = 0; j < 4; j++) acc[mt][nt][j] = 0.f;

    const int NK = DD / KS;  // 32
    issue(0, 0);
    issue(1, 1);

    int cur = 0;
    for (int kt = 0; kt < NK; ++kt) {
        // group kt done; group kt+1 may stay in flight (except last iter).
        if (kt + 1 < NK) cpa_wait<1>();
        else             cpa_wait<0>();
        __syncthreads();   // also retires readers of buffer (kt+2)%3 (iter kt-1)
        if (kt + 2 < NK) issue(kt + 2, (cur + 2 >= NSTG) ? cur + 2 - NSTG : cur + 2);

        const uint32_t bufOff = (uint32_t)(cur * 128 * AST * 2);
        const uint32_t abase = uA  + bufOff + (uint32_t)(((wm * 32 + a_r) * AST + a_k) * 2);
        const uint32_t bbase = uBh + bufOff + (uint32_t)(((wn * 64 + b_n) * AST + b_k) * 2);
        #pragma unroll
        for (int ch = 0; ch < 2; ++ch) {
            const uint32_t kc2 = (uint32_t)(ch * 32);   // kc * 2 bytes
            unsigned ah[2][4];
            #pragma unroll
            for (int mt = 0; mt < 2; mt++)
                ldm_x4(ah[mt], abase + (uint32_t)(mt * 16 * AST * 2) + kc2);
            // pass A: a * wH
            #pragma unroll
            for (int ntp = 0; ntp < 4; ntp++) {
                unsigned kf[4];
                ldm_x4(kf, bbase + (uint32_t)(ntp * 16 * AST * 2) + kc2);
                unsigned bb0[2] = {kf[0], kf[2]}, bb1[2] = {kf[1], kf[3]};
                mma_f16(acc[0][2 * ntp],     ah[0], bb0);
                mma_f16(acc[1][2 * ntp],     ah[1], bb0);
                mma_f16(acc[0][2 * ntp + 1], ah[0], bb1);
                mma_f16(acc[1][2 * ntp + 1], ah[1], bb1);
            }
            // pass B: a * wM
            #pragma unroll
            for (int ntp = 0; ntp < 4; ntp++) {
                unsigned kf[4];
                ldm_x4(kf, bbase + (uint32_t)(ntp * 16 * AST * 2) + kc2 + GMOFF);
                unsigned bb0[2] = {kf[0], kf[2]}, bb1[2] = {kf[1], kf[3]};
                mma_f16(acc[0][2 * ntp],     ah[0], bb0);
                mma_f16(acc[1][2 * ntp],     ah[1], bb0);
                mma_f16(acc[0][2 * ntp + 1], ah[0], bb1);
                mma_f16(acc[1][2 * ntp + 1], ah[1], bb1);
            }
        }
        cur = (cur + 1 >= NSTG) ? 0 : cur + 1;
    }

    // epilogue
    #pragma unroll
    for (int mt = 0; mt < 2; mt++) {
        int r = cm + wm * 32 + mt * 16 + rq;
        #pragma unroll
        for (int nt = 0; nt < 8; nt++) {
            int c = cn + wn * 64 + nt * 8 + cq * 2;
            float bb0 = bias[c], bb1 = bias[c + 1];
            float v0 = (acc[mt][nt][0] + bb0) * scale;
            float v1 = (acc[mt][nt][1] + bb1) * scale;
            float v2 = (acc[mt][nt][2] + bb0) * scale;
            float v3 = (acc[mt][nt][3] + bb1) * scale;
            if (md == 3) {
                *reinterpret_cast<float2*>(outF + (size_t)r * DD + c) = make_float2(v0, v1);
                *reinterpret_cast<float2*>(outF + (size_t)(r + 8) * DD + c) = make_float2(v2, v3);
            } else if (md == 1) {   // K: fp16 hi/mid
                unsigned mp0, mp1, hp0, hp1;
                hp0 = packHMh(v0, v1, mp0);
                hp1 = packHMh(v2, v3, mp1);
                *reinterpret_cast<unsigned*>(g_kh + (size_t)r * DD + c) = hp0;
                *reinterpret_cast<unsigned*>(g_km + (size_t)r * DD + c) = mp0;
                *reinterpret_cast<unsigned*>(g_kh + (size_t)(r + 8) * DD + c) = hp1;
                *reinterpret_cast<unsigned*>(g_km + (size_t)(r + 8) * DD + c) = mp1;
            } else {                // Q (pre-scaled) or V: single fp16
                __half* O = (md == 0) ? g_q : g_v;
                *reinterpret_cast<unsigned*>(O + (size_t)r * DD + c) = f16x2_of(v1, v0);
                *reinterpret_cast<unsigned*>(O + (size_t)(r + 8) * DD + c) = f16x2_of(v3, v2);
            }
        }
    }
}

// ---------------------------------------------------------------------------
// Flash attention, 128-row Q tiles, 8 warps. QK: Q single fp16 x K 2-term fp16.
// PV: fp16 P (exact pack) x V single fp16. Mask fast-path; diag-skip warps.
// smem halves: Q (128xFST) | KH0,KM0,KH1,KM1 | V0,V1 (64xFST) | Ms[2][64]
// ---------------------------------------------------------------------------
#define FST 72                                // smem k-stride (halves)
#define F64 (64 * FST)                        // halves per 64-row array
#define QFQ (128 * FST)                       // Q halves
#define KOFF QFQ
#define VOFF (QFQ + 4 * F64)
#define KMOFF (F64 * 2)                       // K hi->mid byte offset
#define FLASH_SMEM ((QFQ + 6 * F64) * 2 + 2 * 64 * 4)   // 74240 bytes

__global__ __launch_bounds__(256, 2)
void flash_attn_kernel(const int* __restrict__ pmask)
{
    extern __shared__ __half fsm[];
    int* Ms0 = reinterpret_cast<int*>(fsm + QFQ + 6 * F64);
    const uint32_t uQ = smem_u32(fsm);

    const int tid = threadIdx.x, lane = tid & 31, warp = tid >> 5;
    const int qb = (int)(gridDim.x - 1) - (int)blockIdx.x;  // heavy tiles first
    const int bh = blockIdx.y;
    const int b = bh >> 4, h = bh & 15;
    const size_t head_off = ((size_t)b * SS) * DD + (size_t)h * DHH;
    const int nkb = 2 * qb + 2;               // 64-wide key blocks needed

    const int rq = lane >> 2, cq = lane & 3;
    const int row0 = warp * 16 + rq;

    // ldmatrix lane->row mappings
    const int a_r = lane & 15, a_k = (lane >> 4) * 8;      // Q (A, x4)
    const int b_n = ((lane >> 3) & 1) * 8 + (lane & 7);    // K (B, x4 pair)
    const int b_k = (lane >> 4) * 8;
    const int v_k = ((lane >> 3) & 1) * 8 + (lane & 7);    // V (B^T via x4.trans)
    const int v_n = (lane >> 4) * 8;

    auto issueKV = [&](int kb) {
        const int bsel = kb & 1;
        __half* KH = fsm + KOFF + 2 * F64 * bsel;
        __half* VS = fsm + VOFF + F64 * bsel;
        #pragma unroll
        for (int i = 0; i < 2; i++) {
            int idx = i * 256 + tid;
            int r = idx >> 3, c8 = (idx & 7) * 8;
            size_t g = head_off + (size_t)(kb * 64 + r) * DD + c8;
            cpa16(&KH[r * FST + c8], g_kh + g);
            cpa16(&KH[F64 + r * FST + c8], g_km + g);
            cpa16(&VS[r * FST + c8], g_v + g);
        }
        if (tid < 64) cpa4(&Ms0[bsel * 64 + tid], pmask + b * SS + kb * 64 + tid);
        cpa_commit();
    };

    // Prologue: Q (128x64 single fp16) + K0/V0/mask0 in ONE group
    #pragma unroll
    for (int i = 0; i < 4; i++) {
        int idx = i * 256 + tid;
        int r = idx >> 3, c8 = (idx & 7) * 8;
        size_t g = head_off + (size_t)(qb * 128 + r) * DD + c8;
        cpa16(&fsm[r * FST + c8], g_q + g);
    }
    {
        __half* KH = fsm + KOFF;
        __half* VS = fsm + VOFF;
        #pragma unroll
        for (int i = 0; i < 2; i++) {
            int idx = i * 256 + tid;
            int r = idx >> 3, c8 = (idx & 7) * 8;
            size_t g = head_off + (size_t)r * DD + c8;
            cpa16(&KH[r * FST + c8], g_kh + g);
            cpa16(&KH[F64 + r * FST + c8], g_km + g);
            cpa16(&VS[r * FST + c8], g_v + g);
        }
        if (tid < 64) cpa4(&Ms0[tid], pmask + b * SS + tid);
        cpa_commit();
    }

    float o[8][4];
    #pragma unroll
    for (int nt = 0; nt < 8; nt++)
        #pragma unroll
        for (int j = 0; j < 4; j++) o[nt][j] = 0.f;
    float m0 = -1e30f, m1 = -1e30f, l0 = 0.f, l1 = 0.f;

    const uint32_t qbase = uQ + (uint32_t)(((warp * 16 + a_r) * FST + a_k) * 2);

    for (int kb = 0; kb < nkb; ++kb) {
        cpa_wait<0>();
        __syncthreads();
        if (kb + 1 < nkb) issueKV(kb + 1);

        // warp-uniform skip: entire kv-block above this warp's rows
        if (kb * 64 > qb * 128 + warp * 16 + 15) continue;

        const uint32_t uKH = smem_u32(fsm + KOFF + 2 * F64 * (kb & 1));
        const uint32_t uVS = smem_u32(fsm + VOFF + F64 * (kb & 1));
        const int* Ms = Ms0 + (kb & 1) * 64;

        // mask fast-path detection (warp-uniform)
        unsigned mw0 = __ballot_sync(0xffffffffu, Ms[lane] != 0);
        unsigned mw1 = __ballot_sync(0xffffffffu, Ms[32 + lane] != 0);
        const bool needmask = ((mw0 & mw1) != 0xffffffffu) ||
                              (kb * 64 + 63 > qb * 128 + warp * 16);

        // --- S = Q K^T (warp: 16 x 64): q x (kH, kM), term-major ---
        float sc[8][4];
        #pragma unroll
        for (int nt = 0; nt < 8; nt++)
            #pragma unroll
            for (int j = 0; j < 4; j++) sc[nt][j] = 0.f;

        const uint32_t kbase = uKH + (uint32_t)((b_n * FST + b_k) * 2);
        #pragma unroll
        for (int ch = 0; ch < 4; ++ch) {
            const uint32_t kc2 = (uint32_t)(ch * 32);
            unsigned ah[4];
            ldm_x4(ah, qbase + kc2);
            // pass A: q * kH
            #pragma unroll
            for (int ntp = 0; ntp < 4; ntp++) {
                unsigned kf[4];
                ldm_x4(kf, kbase + (uint32_t)(ntp * 16 * FST * 2) + kc2);
                unsigned bb0[2] = {kf[0], kf[2]}, bb1[2] = {kf[1], kf[3]};
                mma_f16(sc[2 * ntp],     ah, bb0);
                mma_f16(sc[2 * ntp + 1], ah, bb1);
            }
            // pass B: q * kM
            #pragma unroll
            for (int ntp = 0; ntp < 4; ntp++) {
                unsigned kf[4];
                ldm_x4(kf, kbase + (uint32_t)(ntp * 16 * FST * 2) + kc2 + KMOFF);
                unsigned bb0[2] = {kf[0], kf[2]}, bb1[2] = {kf[1], kf[3]};
                mma_f16(sc[2 * ntp],     ah, bb0);
                mma_f16(sc[2 * ntp + 1], ah, bb1);
            }
        }

        // --- mask (slow path only; Q pre-scaled; sentinel -1e30) ---
        if (needmask) {
            const int gm0 = qb * 128 + row0, gm1 = gm0 + 8;
            #pragma unroll
            for (int nt = 0; nt < 8; nt++) {
                int nloc = nt * 8 + cq * 2;
                int gn = kb * 64 + nloc;
                #pragma unroll
                for (int j = 0; j < 2; j++) {
                    bool pv = (Ms[nloc + j] != 0);
                    sc[nt][j]     = (pv && (gn + j) <= gm0) ? sc[nt][j]     : -1e30f;
                    sc[nt][2 + j] = (pv && (gn + j) <= gm1) ? sc[nt][2 + j] : -1e30f;
                }
            }
        }

        // --- online softmax ---
        float mx0 = -1e30f, mx1 = -1e30f;
        #pragma unroll
        for (int nt = 0; nt < 8; nt++) {
            mx0 = fmaxf(mx0, fmaxf(sc[nt][0], sc[nt][1]));
            mx1 = fmaxf(mx1, fmaxf(sc[nt][2], sc[nt][3]));
        }
        mx0 = fmaxf(mx0, __shfl_xor_sync(0xffffffffu, mx0, 1));
        mx0 = fmaxf(mx0, __shfl_xor_sync(0xffffffffu, mx0, 2));
        mx1 = fmaxf(mx1, __shfl_xor_sync(0xffffffffu, mx1, 1));
        mx1 = fmaxf(mx1, __shfl_xor_sync(0xffffffffu, mx1, 2));

        float mn0 = fmaxf(m0, mx0), mn1 = fmaxf(m1, mx1);
        float al0 = ex2f((m0 - mn0) * LOG2E);
        float al1 = ex2f((m1 - mn1) * LOG2E);
        const float c0 = mn0 * LOG2E, c1 = mn1 * LOG2E;

        float s0 = 0.f, s1 = 0.f;
        #pragma unroll
        for (int nt = 0; nt < 8; nt++) {
            sc[nt][0] = ex2f(fmaf(sc[nt][0], LOG2E, -c0));
            sc[nt][1] = ex2f(fmaf(sc[nt][1], LOG2E, -c0));
            sc[nt][2] = ex2f(fmaf(sc[nt][2], LOG2E, -c1));
            sc[nt][3] = ex2f(fmaf(sc[nt][3], LOG2E, -c1));
            s0 += sc[nt][0] + sc[nt][1];
            s1 += sc[nt][2] + sc[nt][3];
        }
        s0 += __shfl_xor_sync(0xffffffffu, s0, 1);
        s0 += __shfl_xor_sync(0xffffffffu, s0, 2);
        s1 += __shfl_xor_sync(0xffffffffu, s1, 1);
        s1 += __shfl_xor_sync(0xffffffffu, s1, 2);

        l0 = l0 * al0 + s0;
        l1 = l1 * al1 + s1;
        m0 = mn0; m1 = mn1;

        #pragma unroll
        for (int nt = 0; nt < 8; nt++) {
            o[nt][0] *= al0; o[nt][1] *= al0;
            o[nt][2] *= al1; o[nt][3] *= al1;
        }

        // --- P -> fp16x2 fragments (exact pack) ---
        unsigned pf[16];
        #pragma unroll
        for (int nt = 0; nt < 8; nt++) {
            pf[2 * nt]     = f16x2_of(sc[nt][1], sc[nt][0]);
            pf[2 * nt + 1] = f16x2_of(sc[nt][3], sc[nt][2]);
        }

        // --- O += P V (fp16, single V term) ---
        const uint32_t vbase = uVS + (uint32_t)((v_k * FST + v_n) * 2);
        #pragma unroll
        for (int ch = 0; ch < 4; ++ch) {
            unsigned* af = &pf[4 * ch];
            const uint32_t cOff = (uint32_t)(ch * 16 * FST * 2);
            #pragma unroll
            for (int ntp = 0; ntp < 4; ntp++) {
                unsigned vf[4];
                ldm_x4t(vf, vbase + cOff + (uint32_t)(ntp * 16 * 2));
                unsigned bb0[2] = {vf[0], vf[1]}, bb1[2] = {vf[2], vf[3]};
                mma_f16(o[2 * ntp],     af, bb0);
                mma_f16(o[2 * ntp + 1], af, bb1);
            }
        }
    }

    // --- epilogue: normalize, store single fp16 to g_a [b, s, h, dh] ---
    float i0 = (l0 > 0.f) ? 1.f / l0 : 0.f;
    float i1 = (l1 > 0.f) ? 1.f / l1 : 0.f;
    size_t ob = head_off + (size_t)(qb * 128) * DD;
    #pragma unroll
    for (int nt = 0; nt < 8; nt++) {
        int c = nt * 8 + cq * 2;
        *reinterpret_cast<unsigned*>(g_a + ob + (size_t)row0 * DD + c) =
            f16x2_of(o[nt][1] * i0, o[nt][0] * i0);
        *reinterpret_cast<unsigned*>(g_a + ob + (size_t)(row0 + 8) * DD + c) =
            f16x2_of(o[nt][3] * i1, o[nt][2] * i1);
    }
}

// ---------------------------------------------------------------------------
extern "C" void kernel_launch(void* const* d_in, const int* in_sizes, int n_in,
                              void* d_out, int out_size)
{
    (void)in_sizes; (void)n_in; (void)out_size;
    const float* x  = (const float*)d_in[0];
    const float* Wq = (const float*)d_in[1];
    const float* bq = (const float*)d_in[2];
    const float* Wk = (const float*)d_in[3];
    const float* bk = (const float*)d_in[4];
    const float* Wv = (const float*)d_in[5];
    const float* bv = (const float*)d_in[6];
    const float* Wo = (const float*)d_in[7];
    const float* bo = (const float*)d_in[8];
    const int*   pm = (const int*)d_in[9];
    float* out = (float*)d_out;

    cudaFuncSetAttribute(gemm_k, cudaFuncAttributeMaxDynamicSharedMemorySize, GEMM_SMEM);
    cudaFuncSetAttribute(flash_attn_kernel, cudaFuncAttributeMaxDynamicSharedMemorySize, FLASH_SMEM);

    split_src<<<(BSROWS * DD / 4) / 256, 256>>>(x);
    dim3 wgrid(32, 32, 4);
    wsplit_all<<<wgrid, 256>>>(Wq, Wk, Wv, Wo);

    dim3 qkvgrid(BSROWS / 128, DD / 128, 3);    // (64, 8, 3)
    gemm_k<<<qkvgrid, 256, GEMM_SMEM>>>(bq, bk, bv, nullptr, -1);

    dim3 fgrid(SS / 128, BB * HH);              // (16, 64)
    flash_attn_kernel<<<fgrid, 256, FLASH_SMEM>>>(pm);

    dim3 ogrid(BSROWS / 128, DD / 128, 1);
    gemm_k<<<ogrid, 256, GEMM_SMEM>>>(bo, nullptr, nullptr, out, 3);
}

// round 11
// speedup vs baseline: 1.8341x; 1.1787x over previous
#include <cuda_runtime.h>
#include <cuda_bf16.h>
#include <cuda_fp16.h>
#include <cstdint>

// Problem constants
#define BB 4
#define SS 2048
#define DD 1024
#define HH 16
#define DHH 64
#define BSROWS (BB * SS)          // 8192

// ---------------------------------------------------------------------------
// Device-global scratch (allocation-free). fp16:
// x, q, k, v, attended: single; W: hi/mid 2-term.
// ---------------------------------------------------------------------------
__device__ __half g_x[(size_t)BSROWS * DD];
__device__ __half g_q[(size_t)BSROWS * DD];
__device__ __half g_k[(size_t)BSROWS * DD];
__device__ __half g_v[(size_t)BSROWS * DD];
__device__ __half g_a[(size_t)BSROWS * DD];
__device__ __half g_wth[4 * (size_t)DD * DD], g_wtm[4 * (size_t)DD * DD];  // W^T [n][k]

#define LOG2E 1.4426950408889634f

// ---------------------------------------------------------------------------
// Helpers
// ---------------------------------------------------------------------------
__device__ __forceinline__ void mma_f16(float* c, const unsigned* a, const unsigned* b) {
    asm volatile(
        "mma.sync.aligned.m16n8k16.row.col.f32.f16.f16.f32 "
        "{%0,%1,%2,%3}, {%4,%5,%6,%7}, {%8,%9}, {%0,%1,%2,%3};\n"
        : "+f"(c[0]), "+f"(c[1]), "+f"(c[2]), "+f"(c[3])
        : "r"(a[0]), "r"(a[1]), "r"(a[2]), "r"(a[3]),
          "r"(b[0]), "r"(b[1]));
}

__device__ __forceinline__ void ldm_x4(unsigned* r, uint32_t addr) {
    asm volatile("ldmatrix.sync.aligned.m8n8.x4.shared.b16 {%0,%1,%2,%3}, [%4];"
        : "=r"(r[0]), "=r"(r[1]), "=r"(r[2]), "=r"(r[3]) : "r"(addr));
}
__device__ __forceinline__ void ldm_x4t(unsigned* r, uint32_t addr) {
    asm volatile("ldmatrix.sync.aligned.m8n8.x4.trans.shared.b16 {%0,%1,%2,%3}, [%4];"
        : "=r"(r[0]), "=r"(r[1]), "=r"(r[2]), "=r"(r[3]) : "r"(addr));
}

// fp16 split/pack
__device__ __forceinline__ unsigned packh2(__half lo, __half hi) {
    unsigned l = __half_as_ushort(lo), h = __half_as_ushort(hi);
    return l | (h << 16);
}
__device__ __forceinline__ void hsplit(float x, __half& h, __half& m) {
    h = __float2half_rn(x);
    m = __float2half_rn(x - __half2float(h));
}
__device__ __forceinline__ unsigned packHMh(float x, float y, unsigned& mp) {
    __half hx, mx, hy, my;
    hsplit(x, hx, mx);
    hsplit(y, hy, my);
    mp = packh2(mx, my);
    return packh2(hx, hy);
}
// f32 pair -> f16x2 (hi arg -> upper half)
__device__ __forceinline__ unsigned f16x2_of(float hi, float lo) {
    unsigned r;
    asm("cvt.rn.f16x2.f32 %0, %1, %2;" : "=r"(r) : "f"(hi), "f"(lo));
    return r;
}
__device__ __forceinline__ float ex2f(float x) {
    float r;
    asm("ex2.approx.ftz.f32 %0, %1;" : "=f"(r) : "f"(x));
    return r;
}

__device__ __forceinline__ void cpa16(void* s, const void* g) {
    unsigned sa = (unsigned)__cvta_generic_to_shared(s);
    asm volatile("cp.async.cg.shared.global [%0], [%1], 16;\n" :: "r"(sa), "l"(g));
}
__device__ __forceinline__ void cpa4(void* s, const void* g) {
    unsigned sa = (unsigned)__cvta_generic_to_shared(s);
    asm volatile("cp.async.ca.shared.global [%0], [%1], 4;\n" :: "r"(sa), "l"(g));
}
__device__ __forceinline__ void cpa_commit() {
    asm volatile("cp.async.commit_group;\n");
}
template <int N>
__device__ __forceinline__ void cpa_wait() {
    asm volatile("cp.async.wait_group %0;\n" :: "n"(N));
}
__device__ __forceinline__ uint32_t smem_u32(const void* p) {
    return (uint32_t)__cvta_generic_to_shared(p);
}

// ---------------------------------------------------------------------------
// Prep: x fp32 -> single fp16
// ---------------------------------------------------------------------------
__global__ __launch_bounds__(256)
void split_src(const float* __restrict__ x)
{
    int i = blockIdx.x * 256 + threadIdx.x;            // over float4s: 2M
    float4 v = reinterpret_cast<const float4*>(x)[i];
    uint2 u;
    u.x = f16x2_of(v.y, v.x);
    u.y = f16x2_of(v.w, v.z);
    reinterpret_cast<uint2*>(g_x)[i] = u;
}

// ---------------------------------------------------------------------------
// Prep: transpose + split all 4 W [k][n] fp32 -> g_wt{h,m}[z] as [n][k] fp16
// ---------------------------------------------------------------------------
__global__ __launch_bounds__(256)
void wsplit_all(const float* __restrict__ W0, const float* __restrict__ W1,
                const float* __restrict__ W2, const float* __restrict__ W3)
{
    const int widx = blockIdx.z;
    const float* W = (widx == 0) ? W0 : (widx == 1) ? W1 : (widx == 2) ? W2 : W3;
    __shared__ float t[32][33];
    const int kb = blockIdx.x * 32, nb = blockIdx.y * 32;
    const int r = threadIdx.x >> 3, c4 = (threadIdx.x & 7) * 4;
    float4 v = *reinterpret_cast<const float4*>(W + (size_t)(kb + r) * DD + nb + c4);
    t[r][c4 + 0] = v.x; t[r][c4 + 1] = v.y; t[r][c4 + 2] = v.z; t[r][c4 + 3] = v.w;
    __syncthreads();
    __half* oh = g_wth + (size_t)widx * DD * DD;
    __half* om = g_wtm + (size_t)widx * DD * DD;
    uint2 uh, um;
    uh.x = packHMh(t[c4 + 0][r], t[c4 + 1][r], um.x);
    uh.y = packHMh(t[c4 + 2][r], t[c4 + 3][r], um.y);
    size_t o = (size_t)(nb + r) * DD + kb + c4;
    *reinterpret_cast<uint2*>(oh + o) = uh;
    *reinterpret_cast<uint2*>(om + o) = um;
}

// ---------------------------------------------------------------------------
// GEMM (2-term fp16, m16n8k16 + ldmatrix): C = A * W^T' + bias, M=8192, N=K=1024
// A single fp16, W 2-term (hi/mid). CTA 128x128, kstep 64, 256 thr, 2-stage
// cp.async double buffer, distance-1 prefetch, ONE sync per k-iteration (16).
// mode -1: md=blockIdx.z (Q scaled 1/8; K, V single fp16 out)
// mode  3: A=g_a (attended), out fp32 to outF
// ---------------------------------------------------------------------------
#define KS 64
#define AST 72
#define SLAB (2 * 128 * AST)                 // halves per (dbuf) array
#define GEMM_SMEM (3 * SLAB * 2)             // 110592 bytes (sA, sBh, sBm)
#define GMOFF (SLAB * 2)                     // sBh->sBm byte offset

__global__ __launch_bounds__(256, 2)
void gemm_k(const float* __restrict__ b0, const float* __restrict__ b1,
            const float* __restrict__ b2, float* __restrict__ outF, int mode)
{
    const int md = (mode < 0) ? (int)blockIdx.z : mode;
    const __half* A = (md < 3) ? g_x : g_a;
    const __half* Wh = g_wth + (size_t)md * DD * DD;
    const __half* Wm = g_wtm + (size_t)md * DD * DD;
    const float* bias = (md == 1) ? b1 : (md == 2) ? b2 : b0;
    const float scale = (md == 0) ? 0.125f : 1.0f;

    extern __shared__ __half sm[];
    __half* sA  = sm;
    __half* sBh = sm + SLAB;
    __half* sBm = sm + 2 * SLAB;
    const uint32_t uA  = smem_u32(sA);
    const uint32_t uBh = smem_u32(sBh);

    const int tid  = threadIdx.x;
    const int lane = tid & 31;
    const int warp = tid >> 5;
    const int wm = warp & 3, wn = warp >> 2;
    const int cm = blockIdx.x * 128, cn = blockIdx.y * 128;
    const int rq = lane >> 2, cq = lane & 3;

    // ldmatrix lane->row mappings
    const int a_r = lane & 15, a_k = (lane >> 4) * 8;               // A x4
    const int b_n = ((lane >> 3) & 1) * 8 + (lane & 7);             // B x4 (pair of n-tiles)
    const int b_k = (lane >> 4) * 8;

    // stage kt (64 k-columns) into buffer buf
    auto issue = [&](int kt, int buf) {
        const int k0 = kt * KS;
        #pragma unroll
        for (int i = 0; i < 4; i++) {
            int idx = i * 256 + tid;
            int r = idx >> 3, c8 = (idx & 7) * 8;
            size_t ga = (size_t)(cm + r) * DD + k0 + c8;
            size_t gb = (size_t)(cn + r) * DD + k0 + c8;
            int so = buf * 128 * AST + r * AST + c8;
            cpa16(&sA[so],  A + ga);
            cpa16(&sBh[so], Wh + gb);
            cpa16(&sBm[so], Wm + gb);
        }
        cpa_commit();
    };

    float acc[2][8][4];
    #pragma unroll
    for (int mt = 0; mt < 2; mt++)
        #pragma unroll
        for (int nt = 0; nt < 8; nt++)
            #pragma unroll
            for (int j = 0; j < 4; j++) acc[mt][nt][j] = 0.f;

    const int NK = DD / KS;  // 16
    issue(0, 0);

    for (int kt = 0; kt < NK; ++kt) {
        const int cur = kt & 1;
        cpa_wait<0>();
        __syncthreads();            // stage kt visible; readers of buf cur^1 retired
        if (kt + 1 < NK) issue(kt + 1, cur ^ 1);   // overlaps all compute below

        const uint32_t bufOff = (uint32_t)(cur * 128 * AST * 2);
        const uint32_t abase = uA  + bufOff + (uint32_t)(((wm * 32 + a_r) * AST + a_k) * 2);
        const uint32_t bbase = uBh + bufOff + (uint32_t)(((wn * 64 + b_n) * AST + b_k) * 2);
        #pragma unroll
        for (int ch = 0; ch < 4; ++ch) {
            const uint32_t kc2 = (uint32_t)(ch * 32);   // 16 halves per chunk
            unsigned ah[2][4];
            #pragma unroll
            for (int mt = 0; mt < 2; mt++)
                ldm_x4(ah[mt], abase + (uint32_t)(mt * 16 * AST * 2) + kc2);
            // pass A: a * wH
            #pragma unroll
            for (int ntp = 0; ntp < 4; ntp++) {
                unsigned kf[4];
                ldm_x4(kf, bbase + (uint32_t)(ntp * 16 * AST * 2) + kc2);
                unsigned bb0[2] = {kf[0], kf[2]}, bb1[2] = {kf[1], kf[3]};
                mma_f16(acc[0][2 * ntp],     ah[0], bb0);
                mma_f16(acc[1][2 * ntp],     ah[1], bb0);
                mma_f16(acc[0][2 * ntp + 1], ah[0], bb1);
                mma_f16(acc[1][2 * ntp + 1], ah[1], bb1);
            }
            // pass B: a * wM
            #pragma unroll
            for (int ntp = 0; ntp < 4; ntp++) {
                unsigned kf[4];
                ldm_x4(kf, bbase + (uint32_t)(ntp * 16 * AST * 2) + kc2 + GMOFF);
                unsigned bb0[2] = {kf[0], kf[2]}, bb1[2] = {kf[1], kf[3]};
                mma_f16(acc[0][2 * ntp],     ah[0], bb0);
                mma_f16(acc[1][2 * ntp],     ah[1], bb0);
                mma_f16(acc[0][2 * ntp + 1], ah[0], bb1);
                mma_f16(acc[1][2 * ntp + 1], ah[1], bb1);
            }
        }
    }

    // epilogue
    #pragma unroll
    for (int mt = 0; mt < 2; mt++) {
        int r = cm + wm * 32 + mt * 16 + rq;
        #pragma unroll
        for (int nt = 0; nt < 8; nt++) {
            int c = cn + wn * 64 + nt * 8 + cq * 2;
            float bb0 = bias[c], bb1 = bias[c + 1];
            float v0 = (acc[mt][nt][0] + bb0) * scale;
            float v1 = (acc[mt][nt][1] + bb1) * scale;
            float v2 = (acc[mt][nt][2] + bb0) * scale;
            float v3 = (acc[mt][nt][3] + bb1) * scale;
            if (md == 3) {
                *reinterpret_cast<float2*>(outF + (size_t)r * DD + c) = make_float2(v0, v1);
                *reinterpret_cast<float2*>(outF + (size_t)(r + 8) * DD + c) = make_float2(v2, v3);
            } else {                // Q (pre-scaled) / K / V: single fp16
                __half* O = (md == 0) ? g_q : (md == 1) ? g_k : g_v;
                *reinterpret_cast<unsigned*>(O + (size_t)r * DD + c) = f16x2_of(v1, v0);
                *reinterpret_cast<unsigned*>(O + (size_t)(r + 8) * DD + c) = f16x2_of(v3, v2);
            }
        }
    }
}

// ---------------------------------------------------------------------------
// Flash attention, 128-row Q tiles, 8 warps. QK: single fp16 x single fp16.
// PV: fp16 P (exact pack) x V single fp16. Mask fast-path; diag-skip warps.
// smem halves: Q (128xFST) | K0,K1 | V0,V1 (64xFST) | Ms[2][64]
// ---------------------------------------------------------------------------
#define FST 72                                // smem k-stride (halves)
#define F64 (64 * FST)                        // halves per 64-row array
#define QFQ (128 * FST)                       // Q halves
#define KOFF QFQ
#define VOFF (QFQ + 2 * F64)
#define FLASH_SMEM ((QFQ + 4 * F64) * 2 + 2 * 64 * 4)   // 55808 bytes

__global__ __launch_bounds__(256, 2)
void flash_attn_kernel(const int* __restrict__ pmask)
{
    extern __shared__ __half fsm[];
    int* Ms0 = reinterpret_cast<int*>(fsm + QFQ + 4 * F64);
    const uint32_t uQ = smem_u32(fsm);

    const int tid = threadIdx.x, lane = tid & 31, warp = tid >> 5;
    const int qb = (int)(gridDim.x - 1) - (int)blockIdx.x;  // heavy tiles first
    const int bh = blockIdx.y;
    const int b = bh >> 4, h = bh & 15;
    const size_t head_off = ((size_t)b * SS) * DD + (size_t)h * DHH;
    const int nkb = 2 * qb + 2;               // 64-wide key blocks needed

    const int rq = lane >> 2, cq = lane & 3;
    const int row0 = warp * 16 + rq;

    // ldmatrix lane->row mappings
    const int a_r = lane & 15, a_k = (lane >> 4) * 8;      // Q (A, x4)
    const int b_n = ((lane >> 3) & 1) * 8 + (lane & 7);    // K (B, x4 pair)
    const int b_k = (lane >> 4) * 8;
    const int v_k = ((lane >> 3) & 1) * 8 + (lane & 7);    // V (B^T via x4.trans)
    const int v_n = (lane >> 4) * 8;

    auto issueKV = [&](int kb) {
        const int bsel = kb & 1;
        __half* KS_ = fsm + KOFF + F64 * bsel;
        __half* VS = fsm + VOFF + F64 * bsel;
        #pragma unroll
        for (int i = 0; i < 2; i++) {
            int idx = i * 256 + tid;
            int r = idx >> 3, c8 = (idx & 7) * 8;
            size_t g = head_off + (size_t)(kb * 64 + r) * DD + c8;
            cpa16(&KS_[r * FST + c8], g_k + g);
            cpa16(&VS[r * FST + c8], g_v + g);
        }
        if (tid < 64) cpa4(&Ms0[bsel * 64 + tid], pmask + b * SS + kb * 64 + tid);
        cpa_commit();
    };

    // Prologue: Q (128x64 single fp16) + K0/V0/mask0 in ONE group
    #pragma unroll
    for (int i = 0; i < 4; i++) {
        int idx = i * 256 + tid;
        int r = idx >> 3, c8 = (idx & 7) * 8;
        size_t g = head_off + (size_t)(qb * 128 + r) * DD + c8;
        cpa16(&fsm[r * FST + c8], g_q + g);
    }
    {
        __half* KS_ = fsm + KOFF;
        __half* VS = fsm + VOFF;
        #pragma unroll
        for (int i = 0; i < 2; i++) {
            int idx = i * 256 + tid;
            int r = idx >> 3, c8 = (idx & 7) * 8;
            size_t g = head_off + (size_t)r * DD + c8;
            cpa16(&KS_[r * FST + c8], g_k + g);
            cpa16(&VS[r * FST + c8], g_v + g);
        }
        if (tid < 64) cpa4(&Ms0[tid], pmask + b * SS + tid);
        cpa_commit();
    }

    float o[8][4];
    #pragma unroll
    for (int nt = 0; nt < 8; nt++)
        #pragma unroll
        for (int j = 0; j < 4; j++) o[nt][j] = 0.f;
    float m0 = -1e30f, m1 = -1e30f, l0 = 0.f, l1 = 0.f;

    const uint32_t qbase = uQ + (uint32_t)(((warp * 16 + a_r) * FST + a_k) * 2);

    for (int kb = 0; kb < nkb; ++kb) {
        cpa_wait<0>();
        __syncthreads();
        if (kb + 1 < nkb) issueKV(kb + 1);

        // warp-uniform skip: entire kv-block above this warp's rows
        if (kb * 64 > qb * 128 + warp * 16 + 15) continue;

        const uint32_t uKH = smem_u32(fsm + KOFF + F64 * (kb & 1));
        const uint32_t uVS = smem_u32(fsm + VOFF + F64 * (kb & 1));
        const int* Ms = Ms0 + (kb & 1) * 64;

        // mask fast-path detection (warp-uniform)
        unsigned mw0 = __ballot_sync(0xffffffffu, Ms[lane] != 0);
        unsigned mw1 = __ballot_sync(0xffffffffu, Ms[32 + lane] != 0);
        const bool needmask = ((mw0 & mw1) != 0xffffffffu) ||
                              (kb * 64 + 63 > qb * 128 + warp * 16);

        // --- S = Q K^T (warp: 16 x 64), single-term fp16 ---
        float sc[8][4];
        #pragma unroll
        for (int nt = 0; nt < 8; nt++)
            #pragma unroll
            for (int j = 0; j < 4; j++) sc[nt][j] = 0.f;

        const uint32_t kbase = uKH + (uint32_t)((b_n * FST + b_k) * 2);
        #pragma unroll
        for (int ch = 0; ch < 4; ++ch) {
            const uint32_t kc2 = (uint32_t)(ch * 32);
            unsigned ah[4];
            ldm_x4(ah, qbase + kc2);
            #pragma unroll
            for (int ntp = 0; ntp < 4; ntp++) {
                unsigned kf[4];
                ldm_x4(kf, kbase + (uint32_t)(ntp * 16 * FST * 2) + kc2);
                unsigned bb0[2] = {kf[0], kf[2]}, bb1[2] = {kf[1], kf[3]};
                mma_f16(sc[2 * ntp],     ah, bb0);
                mma_f16(sc[2 * ntp + 1], ah, bb1);
            }
        }

        // --- mask (slow path only; Q pre-scaled; sentinel -1e30) ---
        if (needmask) {
            const int gm0 = qb * 128 + row0, gm1 = gm0 + 8;
            #pragma unroll
            for (int nt = 0; nt < 8; nt++) {
                int nloc = nt * 8 + cq * 2;
                int gn = kb * 64 + nloc;
                #pragma unroll
                for (int j = 0; j < 2; j++) {
                    bool pv = (Ms[nloc + j] != 0);
                    sc[nt][j]     = (pv && (gn + j) <= gm0) ? sc[nt][j]     : -1e30f;
                    sc[nt][2 + j] = (pv && (gn + j) <= gm1) ? sc[nt][2 + j] : -1e30f;
                }
            }
        }

        // --- online softmax ---
        float mx0 = -1e30f, mx1 = -1e30f;
        #pragma unroll
        for (int nt = 0; nt < 8; nt++) {
            mx0 = fmaxf(mx0, fmaxf(sc[nt][0], sc[nt][1]));
            mx1 = fmaxf(mx1, fmaxf(sc[nt][2], sc[nt][3]));
        }
        mx0 = fmaxf(mx0, __shfl_xor_sync(0xffffffffu, mx0, 1));
        mx0 = fmaxf(mx0, __shfl_xor_sync(0xffffffffu, mx0, 2));
        mx1 = fmaxf(mx1, __shfl_xor_sync(0xffffffffu, mx1, 1));
        mx1 = fmaxf(mx1, __shfl_xor_sync(0xffffffffu, mx1, 2));

        float mn0 = fmaxf(m0, mx0), mn1 = fmaxf(m1, mx1);
        float al0 = ex2f((m0 - mn0) * LOG2E);
        float al1 = ex2f((m1 - mn1) * LOG2E);
        const float c0 = mn0 * LOG2E, c1 = mn1 * LOG2E;

        float s0 = 0.f, s1 = 0.f;
        #pragma unroll
        for (int nt = 0; nt < 8; nt++) {
            sc[nt][0] = ex2f(fmaf(sc[nt][0], LOG2E, -c0));
            sc[nt][1] = ex2f(fmaf(sc[nt][1], LOG2E, -c0));
            sc[nt][2] = ex2f(fmaf(sc[nt][2], LOG2E, -c1));
            sc[nt][3] = ex2f(fmaf(sc[nt][3], LOG2E, -c1));
            s0 += sc[nt][0] + sc[nt][1];
            s1 += sc[nt][2] + sc[nt][3];
        }
        s0 += __shfl_xor_sync(0xffffffffu, s0, 1);
        s0 += __shfl_xor_sync(0xffffffffu, s0, 2);
        s1 += __shfl_xor_sync(0xffffffffu, s1, 1);
        s1 += __shfl_xor_sync(0xffffffffu, s1, 2);

        l0 = l0 * al0 + s0;
        l1 = l1 * al1 + s1;
        m0 = mn0; m1 = mn1;

        #pragma unroll
        for (int nt = 0; nt < 8; nt++) {
            o[nt][0] *= al0; o[nt][1] *= al0;
            o[nt][2] *= al1; o[nt][3] *= al1;
        }

        // --- P -> fp16x2 fragments (exact pack) ---
        unsigned pf[16];
        #pragma unroll
        for (int nt = 0; nt < 8; nt++) {
            pf[2 * nt]     = f16x2_of(sc[nt][1], sc[nt][0]);
            pf[2 * nt + 1] = f16x2_of(sc[nt][3], sc[nt][2]);
        }

        // --- O += P V (fp16, single V term) ---
        const uint32_t vbase = uVS + (uint32_t)((v_k * FST + v_n) * 2);
        #pragma unroll
        for (int ch = 0; ch < 4; ++ch) {
            unsigned* af = &pf[4 * ch];
            const uint32_t cOff = (uint32_t)(ch * 16 * FST * 2);
            #pragma unroll
            for (int ntp = 0; ntp < 4; ntp++) {
                unsigned vf[4];
                ldm_x4t(vf, vbase + cOff + (uint32_t)(ntp * 16 * 2));
                unsigned bb0[2] = {vf[0], vf[1]}, bb1[2] = {vf[2], vf[3]};
                mma_f16(o[2 * ntp],     af, bb0);
                mma_f16(o[2 * ntp + 1], af, bb1);
            }
        }
    }

    // --- epilogue: normalize, store single fp16 to g_a [b, s, h, dh] ---
    float i0 = (l0 > 0.f) ? 1.f / l0 : 0.f;
    float i1 = (l1 > 0.f) ? 1.f / l1 : 0.f;
    size_t ob = head_off + (size_t)(qb * 128) * DD;
    #pragma unroll
    for (int nt = 0; nt < 8; nt++) {
        int c = nt * 8 + cq * 2;
        *reinterpret_cast<unsigned*>(g_a + ob + (size_t)row0 * DD + c) =
            f16x2_of(o[nt][1] * i0, o[nt][0] * i0);
        *reinterpret_cast<unsigned*>(g_a + ob + (size_t)(row0 + 8) * DD + c) =
            f16x2_of(o[nt][3] * i1, o[nt][2] * i1);
    }
}

// ---------------------------------------------------------------------------
extern "C" void kernel_launch(void* const* d_in, const int* in_sizes, int n_in,
                              void* d_out, int out_size)
{
    (void)in_sizes; (void)n_in; (void)out_size;
    const float* x  = (const float*)d_in[0];
    const float* Wq = (const float*)d_in[1];
    const float* bq = (const float*)d_in[2];
    const float* Wk = (const float*)d_in[3];
    const float* bk = (const float*)d_in[4];
    const float* Wv = (const float*)d_in[5];
    const float* bv = (const float*)d_in[6];
    const float* Wo = (const float*)d_in[7];
    const float* bo = (const float*)d_in[8];
    const int*   pm = (const int*)d_in[9];
    float* out = (float*)d_out;

    cudaFuncSetAttribute(gemm_k, cudaFuncAttributeMaxDynamicSharedMemorySize, GEMM_SMEM);
    cudaFuncSetAttribute(flash_attn_kernel, cudaFuncAttributeMaxDynamicSharedMemorySize, FLASH_SMEM);

    split_src<<<(BSROWS * DD / 4) / 256, 256>>>(x);
    dim3 wgrid(32, 32, 4);
    wsplit_all<<<wgrid, 256>>>(Wq, Wk, Wv, Wo);

    dim3 qkvgrid(BSROWS / 128, DD / 128, 3);    // (64, 8, 3)
    gemm_k<<<qkvgrid, 256, GEMM_SMEM>>>(bq, bk, bv, nullptr, -1);

    dim3 fgrid(SS / 128, BB * HH);              // (16, 64)
    flash_attn_kernel<<<fgrid, 256, FLASH_SMEM>>>(pm);

    dim3 ogrid(BSROWS / 128, DD / 128, 1);
    gemm_k<<<ogrid, 256, GEMM_SMEM>>>(bo, nullptr, nullptr, out, 3);
}

// round 12
// speedup vs baseline: 1.8720x; 1.0207x over previous
#include <cuda_runtime.h>
#include <cuda_bf16.h>
#include <cuda_fp16.h>
#include <cstdint>

// Problem constants
#define BB 4
#define SS 2048
#define DD 1024
#define HH 16
#define DHH 64
#define BSROWS (BB * SS)          // 8192

// ---------------------------------------------------------------------------
// Device-global scratch (allocation-free). fp16:
// x, q, k, v, attended: single; W: hi/mid 2-term.
// ---------------------------------------------------------------------------
__device__ __half g_x[(size_t)BSROWS * DD];
__device__ __half g_q[(size_t)BSROWS * DD];
__device__ __half g_k[(size_t)BSROWS * DD];
__device__ __half g_v[(size_t)BSROWS * DD];
__device__ __half g_a[(size_t)BSROWS * DD];
__device__ __half g_wth[4 * (size_t)DD * DD], g_wtm[4 * (size_t)DD * DD];  // W^T [n][k]

#define LOG2E 1.4426950408889634f

// ---------------------------------------------------------------------------
// Helpers
// ---------------------------------------------------------------------------
__device__ __forceinline__ void mma_f16(float* c, const unsigned* a, const unsigned* b) {
    asm volatile(
        "mma.sync.aligned.m16n8k16.row.col.f32.f16.f16.f32 "
        "{%0,%1,%2,%3}, {%4,%5,%6,%7}, {%8,%9}, {%0,%1,%2,%3};\n"
        : "+f"(c[0]), "+f"(c[1]), "+f"(c[2]), "+f"(c[3])
        : "r"(a[0]), "r"(a[1]), "r"(a[2]), "r"(a[3]),
          "r"(b[0]), "r"(b[1]));
}

__device__ __forceinline__ void ldm_x4(unsigned* r, uint32_t addr) {
    asm volatile("ldmatrix.sync.aligned.m8n8.x4.shared.b16 {%0,%1,%2,%3}, [%4];"
        : "=r"(r[0]), "=r"(r[1]), "=r"(r[2]), "=r"(r[3]) : "r"(addr));
}
__device__ __forceinline__ void ldm_x4t(unsigned* r, uint32_t addr) {
    asm volatile("ldmatrix.sync.aligned.m8n8.x4.trans.shared.b16 {%0,%1,%2,%3}, [%4];"
        : "=r"(r[0]), "=r"(r[1]), "=r"(r[2]), "=r"(r[3]) : "r"(addr));
}

// fp16 split/pack
__device__ __forceinline__ unsigned packh2(__half lo, __half hi) {
    unsigned l = __half_as_ushort(lo), h = __half_as_ushort(hi);
    return l | (h << 16);
}
__device__ __forceinline__ void hsplit(float x, __half& h, __half& m) {
    h = __float2half_rn(x);
    m = __float2half_rn(x - __half2float(h));
}
__device__ __forceinline__ unsigned packHMh(float x, float y, unsigned& mp) {
    __half hx, mx, hy, my;
    hsplit(x, hx, mx);
    hsplit(y, hy, my);
    mp = packh2(mx, my);
    return packh2(hx, hy);
}
// f32 pair -> f16x2 (hi arg -> upper half)
__device__ __forceinline__ unsigned f16x2_of(float hi, float lo) {
    unsigned r;
    asm("cvt.rn.f16x2.f32 %0, %1, %2;" : "=r"(r) : "f"(hi), "f"(lo));
    return r;
}
__device__ __forceinline__ float ex2f(float x) {
    float r;
    asm("ex2.approx.ftz.f32 %0, %1;" : "=f"(r) : "f"(x));
    return r;
}

__device__ __forceinline__ void cpa16(void* s, const void* g) {
    unsigned sa = (unsigned)__cvta_generic_to_shared(s);
    asm volatile("cp.async.cg.shared.global [%0], [%1], 16;\n" :: "r"(sa), "l"(g));
}
__device__ __forceinline__ void cpa4(void* s, const void* g) {
    unsigned sa = (unsigned)__cvta_generic_to_shared(s);
    asm volatile("cp.async.ca.shared.global [%0], [%1], 4;\n" :: "r"(sa), "l"(g));
}
__device__ __forceinline__ void cpa_commit() {
    asm volatile("cp.async.commit_group;\n");
}
template <int N>
__device__ __forceinline__ void cpa_wait() {
    asm volatile("cp.async.wait_group %0;\n" :: "n"(N));
}
__device__ __forceinline__ uint32_t smem_u32(const void* p) {
    return (uint32_t)__cvta_generic_to_shared(p);
}

// ---------------------------------------------------------------------------
// Prep: x fp32 -> single fp16
// ---------------------------------------------------------------------------
__global__ __launch_bounds__(256)
void split_src(const float* __restrict__ x)
{
    int i = blockIdx.x * 256 + threadIdx.x;            // over float4s: 2M
    float4 v = reinterpret_cast<const float4*>(x)[i];
    uint2 u;
    u.x = f16x2_of(v.y, v.x);
    u.y = f16x2_of(v.w, v.z);
    reinterpret_cast<uint2*>(g_x)[i] = u;
}

// ---------------------------------------------------------------------------
// Prep: transpose + split all 4 W [k][n] fp32 -> g_wt{h,m}[z] as [n][k] fp16
// ---------------------------------------------------------------------------
__global__ __launch_bounds__(256)
void wsplit_all(const float* __restrict__ W0, const float* __restrict__ W1,
                const float* __restrict__ W2, const float* __restrict__ W3)
{
    const int widx = blockIdx.z;
    const float* W = (widx == 0) ? W0 : (widx == 1) ? W1 : (widx == 2) ? W2 : W3;
    __shared__ float t[32][33];
    const int kb = blockIdx.x * 32, nb = blockIdx.y * 32;
    const int r = threadIdx.x >> 3, c4 = (threadIdx.x & 7) * 4;
    float4 v = *reinterpret_cast<const float4*>(W + (size_t)(kb + r) * DD + nb + c4);
    t[r][c4 + 0] = v.x; t[r][c4 + 1] = v.y; t[r][c4 + 2] = v.z; t[r][c4 + 3] = v.w;
    __syncthreads();
    __half* oh = g_wth + (size_t)widx * DD * DD;
    __half* om = g_wtm + (size_t)widx * DD * DD;
    uint2 uh, um;
    uh.x = packHMh(t[c4 + 0][r], t[c4 + 1][r], um.x);
    uh.y = packHMh(t[c4 + 2][r], t[c4 + 3][r], um.y);
    size_t o = (size_t)(nb + r) * DD + kb + c4;
    *reinterpret_cast<uint2*>(oh + o) = uh;
    *reinterpret_cast<uint2*>(om + o) = um;
}

// ---------------------------------------------------------------------------
// GEMM (2-term fp16, m16n8k16 + ldmatrix): C = A * W^T' + bias, M=8192, N=K=1024
// A single fp16, W 2-term (hi/mid). CTA tile 128x64, 8 warps (4 M x 2 N),
// warp tile 32x32 (32-reg acc). KS=64, 2-stage cp.async, one sync/iter.
// 3 CTAs/SM (smem 73.7KB, launch_bounds(256,3)) -> 24 warps/SM.
// mode -1: md=blockIdx.z (Q scaled 1/8; K, V single fp16 out)
// mode  3: A=g_a (attended), out fp32 to outF
// ---------------------------------------------------------------------------
#define KS 64
#define AST 72
#define ASLAB (2 * 128 * AST)                // A halves (both stages) = 18432
#define BSLAB (2 * 64 * AST)                 // per-term B halves      = 9216
#define GEMM_SMEM ((ASLAB + 2 * BSLAB) * 2)  // 73728 bytes
#define GMOFF (BSLAB * 2)                    // sBh->sBm byte offset

__global__ __launch_bounds__(256, 3)
void gemm_k(const float* __restrict__ b0, const float* __restrict__ b1,
            const float* __restrict__ b2, float* __restrict__ outF, int mode)
{
    const int md = (mode < 0) ? (int)blockIdx.z : mode;
    const __half* A = (md < 3) ? g_x : g_a;
    const __half* Wh = g_wth + (size_t)md * DD * DD;
    const __half* Wm = g_wtm + (size_t)md * DD * DD;
    const float* bias = (md == 1) ? b1 : (md == 2) ? b2 : b0;
    const float scale = (md == 0) ? 0.125f : 1.0f;

    extern __shared__ __half sm[];
    __half* sA  = sm;
    __half* sBh = sm + ASLAB;
    __half* sBm = sm + ASLAB + BSLAB;
    const uint32_t uA  = smem_u32(sA);
    const uint32_t uBh = smem_u32(sBh);

    const int tid  = threadIdx.x;
    const int lane = tid & 31;
    const int warp = tid >> 5;
    const int wm = warp & 3, wn = warp >> 2;
    const int cm = blockIdx.x * 128, cn = blockIdx.y * 64;
    const int rq = lane >> 2, cq = lane & 3;

    // ldmatrix lane->row mappings
    const int a_r = lane & 15, a_k = (lane >> 4) * 8;               // A x4
    const int b_n = ((lane >> 3) & 1) * 8 + (lane & 7);             // B x4 (pair of n-tiles)
    const int b_k = (lane >> 4) * 8;

    // stage kt (64 k-columns) into buffer buf
    auto issue = [&](int kt, int buf) {
        const int k0 = kt * KS;
        #pragma unroll
        for (int i = 0; i < 4; i++) {                // A: 128 rows
            int idx = i * 256 + tid;
            int r = idx >> 3, c8 = (idx & 7) * 8;
            size_t ga = (size_t)(cm + r) * DD + k0 + c8;
            int so = buf * 128 * AST + r * AST + c8;
            cpa16(&sA[so], A + ga);
        }
        #pragma unroll
        for (int i = 0; i < 2; i++) {                // B: 64 rows, 2 terms
            int idx = i * 256 + tid;
            int r = idx >> 3, c8 = (idx & 7) * 8;
            size_t gb = (size_t)(cn + r) * DD + k0 + c8;
            int so = buf * 64 * AST + r * AST + c8;
            cpa16(&sBh[so], Wh + gb);
            cpa16(&sBm[so], Wm + gb);
        }
        cpa_commit();
    };

    float acc[2][4][4];
    #pragma unroll
    for (int mt = 0; mt < 2; mt++)
        #pragma unroll
        for (int nt = 0; nt < 4; nt++)
            #pragma unroll
            for (int j = 0; j < 4; j++) acc[mt][nt][j] = 0.f;

    const int NK = DD / KS;  // 16
    issue(0, 0);

    for (int kt = 0; kt < NK; ++kt) {
        const int cur = kt & 1;
        cpa_wait<0>();
        __syncthreads();            // stage kt visible; readers of buf cur^1 retired
        if (kt + 1 < NK) issue(kt + 1, cur ^ 1);   // overlaps all compute below

        const uint32_t abase = uA + (uint32_t)(cur * 128 * AST * 2) +
                               (uint32_t)(((wm * 32 + a_r) * AST + a_k) * 2);
        const uint32_t bbase = uBh + (uint32_t)(cur * 64 * AST * 2) +
                               (uint32_t)(((wn * 32 + b_n) * AST + b_k) * 2);
        #pragma unroll
        for (int ch = 0; ch < 4; ++ch) {
            const uint32_t kc2 = (uint32_t)(ch * 32);   // 16 halves per chunk
            unsigned ah[2][4];
            #pragma unroll
            for (int mt = 0; mt < 2; mt++)
                ldm_x4(ah[mt], abase + (uint32_t)(mt * 16 * AST * 2) + kc2);
            // pass A: a * wH
            #pragma unroll
            for (int ntp = 0; ntp < 2; ntp++) {
                unsigned kf[4];
                ldm_x4(kf, bbase + (uint32_t)(ntp * 16 * AST * 2) + kc2);
                unsigned bb0[2] = {kf[0], kf[2]}, bb1[2] = {kf[1], kf[3]};
                mma_f16(acc[0][2 * ntp],     ah[0], bb0);
                mma_f16(acc[1][2 * ntp],     ah[1], bb0);
                mma_f16(acc[0][2 * ntp + 1], ah[0], bb1);
                mma_f16(acc[1][2 * ntp + 1], ah[1], bb1);
            }
            // pass B: a * wM
            #pragma unroll
            for (int ntp = 0; ntp < 2; ntp++) {
                unsigned kf[4];
                ldm_x4(kf, bbase + (uint32_t)(ntp * 16 * AST * 2) + kc2 + GMOFF);
                unsigned bb0[2] = {kf[0], kf[2]}, bb1[2] = {kf[1], kf[3]};
                mma_f16(acc[0][2 * ntp],     ah[0], bb0);
                mma_f16(acc[1][2 * ntp],     ah[1], bb0);
                mma_f16(acc[0][2 * ntp + 1], ah[0], bb1);
                mma_f16(acc[1][2 * ntp + 1], ah[1], bb1);
            }
        }
    }

    // epilogue
    #pragma unroll
    for (int mt = 0; mt < 2; mt++) {
        int r = cm + wm * 32 + mt * 16 + rq;
        #pragma unroll
        for (int nt = 0; nt < 4; nt++) {
            int c = cn + wn * 32 + nt * 8 + cq * 2;
            float bb0 = bias[c], bb1 = bias[c + 1];
            float v0 = (acc[mt][nt][0] + bb0) * scale;
            float v1 = (acc[mt][nt][1] + bb1) * scale;
            float v2 = (acc[mt][nt][2] + bb0) * scale;
            float v3 = (acc[mt][nt][3] + bb1) * scale;
            if (md == 3) {
                *reinterpret_cast<float2*>(outF + (size_t)r * DD + c) = make_float2(v0, v1);
                *reinterpret_cast<float2*>(outF + (size_t)(r + 8) * DD + c) = make_float2(v2, v3);
            } else {                // Q (pre-scaled) / K / V: single fp16
                __half* O = (md == 0) ? g_q : (md == 1) ? g_k : g_v;
                *reinterpret_cast<unsigned*>(O + (size_t)r * DD + c) = f16x2_of(v1, v0);
                *reinterpret_cast<unsigned*>(O + (size_t)(r + 8) * DD + c) = f16x2_of(v3, v2);
            }
        }
    }
}

// ---------------------------------------------------------------------------
// Flash attention (UNCHANGED from round 11 — near multi-pipe roofline).
// 128-row Q tiles, 8 warps. QK: fp16 x fp16. PV: fp16 P x fp16 V.
// smem halves: Q (128xFST) | K0,K1 | V0,V1 (64xFST) | Ms[2][64]
// ---------------------------------------------------------------------------
#define FST 72                                // smem k-stride (halves)
#define F64 (64 * FST)                        // halves per 64-row array
#define QFQ (128 * FST)                       // Q halves
#define KOFF QFQ
#define VOFF (QFQ + 2 * F64)
#define FLASH_SMEM ((QFQ + 4 * F64) * 2 + 2 * 64 * 4)   // 55808 bytes

__global__ __launch_bounds__(256, 2)
void flash_attn_kernel(const int* __restrict__ pmask)
{
    extern __shared__ __half fsm[];
    int* Ms0 = reinterpret_cast<int*>(fsm + QFQ + 4 * F64);
    const uint32_t uQ = smem_u32(fsm);

    const int tid = threadIdx.x, lane = tid & 31, warp = tid >> 5;
    const int qb = (int)(gridDim.x - 1) - (int)blockIdx.x;  // heavy tiles first
    const int bh = blockIdx.y;
    const int b = bh >> 4, h = bh & 15;
    const size_t head_off = ((size_t)b * SS) * DD + (size_t)h * DHH;
    const int nkb = 2 * qb + 2;               // 64-wide key blocks needed

    const int rq = lane >> 2, cq = lane & 3;
    const int row0 = warp * 16 + rq;

    // ldmatrix lane->row mappings
    const int a_r = lane & 15, a_k = (lane >> 4) * 8;      // Q (A, x4)
    const int b_n = ((lane >> 3) & 1) * 8 + (lane & 7);    // K (B, x4 pair)
    const int b_k = (lane >> 4) * 8;
    const int v_k = ((lane >> 3) & 1) * 8 + (lane & 7);    // V (B^T via x4.trans)
    const int v_n = (lane >> 4) * 8;

    auto issueKV = [&](int kb) {
        const int bsel = kb & 1;
        __half* KS_ = fsm + KOFF + F64 * bsel;
        __half* VS = fsm + VOFF + F64 * bsel;
        #pragma unroll
        for (int i = 0; i < 2; i++) {
            int idx = i * 256 + tid;
            int r = idx >> 3, c8 = (idx & 7) * 8;
            size_t g = head_off + (size_t)(kb * 64 + r) * DD + c8;
            cpa16(&KS_[r * FST + c8], g_k + g);
            cpa16(&VS[r * FST + c8], g_v + g);
        }
        if (tid < 64) cpa4(&Ms0[bsel * 64 + tid], pmask + b * SS + kb * 64 + tid);
        cpa_commit();
    };

    // Prologue: Q (128x64 single fp16) + K0/V0/mask0 in ONE group
    #pragma unroll
    for (int i = 0; i < 4; i++) {
        int idx = i * 256 + tid;
        int r = idx >> 3, c8 = (idx & 7) * 8;
        size_t g = head_off + (size_t)(qb * 128 + r) * DD + c8;
        cpa16(&fsm[r * FST + c8], g_q + g);
    }
    {
        __half* KS_ = fsm + KOFF;
        __half* VS = fsm + VOFF;
        #pragma unroll
        for (int i = 0; i < 2; i++) {
            int idx = i * 256 + tid;
            int r = idx >> 3, c8 = (idx & 7) * 8;
            size_t g = head_off + (size_t)r * DD + c8;
            cpa16(&KS_[r * FST + c8], g_k + g);
            cpa16(&VS[r * FST + c8], g_v + g);
        }
        if (tid < 64) cpa4(&Ms0[tid], pmask + b * SS + tid);
        cpa_commit();
    }

    float o[8][4];
    #pragma unroll
    for (int nt = 0; nt < 8; nt++)
        #pragma unroll
        for (int j = 0; j < 4; j++) o[nt][j] = 0.f;
    float m0 = -1e30f, m1 = -1e30f, l0 = 0.f, l1 = 0.f;

    const uint32_t qbase = uQ + (uint32_t)(((warp * 16 + a_r) * FST + a_k) * 2);

    for (int kb = 0; kb < nkb; ++kb) {
        cpa_wait<0>();
        __syncthreads();
        if (kb + 1 < nkb) issueKV(kb + 1);

        // warp-uniform skip: entire kv-block above this warp's rows
        if (kb * 64 > qb * 128 + warp * 16 + 15) continue;

        const uint32_t uKH = smem_u32(fsm + KOFF + F64 * (kb & 1));
        const uint32_t uVS = smem_u32(fsm + VOFF + F64 * (kb & 1));
        const int* Ms = Ms0 + (kb & 1) * 64;

        // mask fast-path detection (warp-uniform)
        unsigned mw0 = __ballot_sync(0xffffffffu, Ms[lane] != 0);
        unsigned mw1 = __ballot_sync(0xffffffffu, Ms[32 + lane] != 0);
        const bool needmask = ((mw0 & mw1) != 0xffffffffu) ||
                              (kb * 64 + 63 > qb * 128 + warp * 16);

        // --- S = Q K^T (warp: 16 x 64), single-term fp16 ---
        float sc[8][4];
        #pragma unroll
        for (int nt = 0; nt < 8; nt++)
            #pragma unroll
            for (int j = 0; j < 4; j++) sc[nt][j] = 0.f;

        const uint32_t kbase = uKH + (uint32_t)((b_n * FST + b_k) * 2);
        #pragma unroll
        for (int ch = 0; ch < 4; ++ch) {
            const uint32_t kc2 = (uint32_t)(ch * 32);
            unsigned ah[4];
            ldm_x4(ah, qbase + kc2);
            #pragma unroll
            for (int ntp = 0; ntp < 4; ntp++) {
                unsigned kf[4];
                ldm_x4(kf, kbase + (uint32_t)(ntp * 16 * FST * 2) + kc2);
                unsigned bb0[2] = {kf[0], kf[2]}, bb1[2] = {kf[1], kf[3]};
                mma_f16(sc[2 * ntp],     ah, bb0);
                mma_f16(sc[2 * ntp + 1], ah, bb1);
            }
        }

        // --- mask (slow path only; Q pre-scaled; sentinel -1e30) ---
        if (needmask) {
            const int gm0 = qb * 128 + row0, gm1 = gm0 + 8;
            #pragma unroll
            for (int nt = 0; nt < 8; nt++) {
                int nloc = nt * 8 + cq * 2;
                int gn = kb * 64 + nloc;
                #pragma unroll
                for (int j = 0; j < 2; j++) {
                    bool pv = (Ms[nloc + j] != 0);
                    sc[nt][j]     = (pv && (gn + j) <= gm0) ? sc[nt][j]     : -1e30f;
                    sc[nt][2 + j] = (pv && (gn + j) <= gm1) ? sc[nt][2 + j] : -1e30f;
                }
            }
        }

        // --- online softmax ---
        float mx0 = -1e30f, mx1 = -1e30f;
        #pragma unroll
        for (int nt = 0; nt < 8; nt++) {
            mx0 = fmaxf(mx0, fmaxf(sc[nt][0], sc[nt][1]));
            mx1 = fmaxf(mx1, fmaxf(sc[nt][2], sc[nt][3]));
        }
        mx0 = fmaxf(mx0, __shfl_xor_sync(0xffffffffu, mx0, 1));
        mx0 = fmaxf(mx0, __shfl_xor_sync(0xffffffffu, mx0, 2));
        mx1 = fmaxf(mx1, __shfl_xor_sync(0xffffffffu, mx1, 1));
        mx1 = fmaxf(mx1, __shfl_xor_sync(0xffffffffu, mx1, 2));

        float mn0 = fmaxf(m0, mx0), mn1 = fmaxf(m1, mx1);
        float al0 = ex2f((m0 - mn0) * LOG2E);
        float al1 = ex2f((m1 - mn1) * LOG2E);
        const float c0 = mn0 * LOG2E, c1 = mn1 * LOG2E;

        float s0 = 0.f, s1 = 0.f;
        #pragma unroll
        for (int nt = 0; nt < 8; nt++) {
            sc[nt][0] = ex2f(fmaf(sc[nt][0], LOG2E, -c0));
            sc[nt][1] = ex2f(fmaf(sc[nt][1], LOG2E, -c0));
            sc[nt][2] = ex2f(fmaf(sc[nt][2], LOG2E, -c1));
            sc[nt][3] = ex2f(fmaf(sc[nt][3], LOG2E, -c1));
            s0 += sc[nt][0] + sc[nt][1];
            s1 += sc[nt][2] + sc[nt][3];
        }
        s0 += __shfl_xor_sync(0xffffffffu, s0, 1);
        s0 += __shfl_xor_sync(0xffffffffu, s0, 2);
        s1 += __shfl_xor_sync(0xffffffffu, s1, 1);
        s1 += __shfl_xor_sync(0xffffffffu, s1, 2);

        l0 = l0 * al0 + s0;
        l1 = l1 * al1 + s1;
        m0 = mn0; m1 = mn1;

        #pragma unroll
        for (int nt = 0; nt < 8; nt++) {
            o[nt][0] *= al0; o[nt][1] *= al0;
            o[nt][2] *= al1; o[nt][3] *= al1;
        }

        // --- P -> fp16x2 fragments (exact pack) ---
        unsigned pf[16];
        #pragma unroll
        for (int nt = 0; nt < 8; nt++) {
            pf[2 * nt]     = f16x2_of(sc[nt][1], sc[nt][0]);
            pf[2 * nt + 1] = f16x2_of(sc[nt][3], sc[nt][2]);
        }

        // --- O += P V (fp16, single V term) ---
        const uint32_t vbase = uVS + (uint32_t)((v_k * FST + v_n) * 2);
        #pragma unroll
        for (int ch = 0; ch < 4; ++ch) {
            unsigned* af = &pf[4 * ch];
            const uint32_t cOff = (uint32_t)(ch * 16 * FST * 2);
            #pragma unroll
            for (int ntp = 0; ntp < 4; ntp++) {
                unsigned vf[4];
                ldm_x4t(vf, vbase + cOff + (uint32_t)(ntp * 16 * 2));
                unsigned bb0[2] = {vf[0], vf[1]}, bb1[2] = {vf[2], vf[3]};
                mma_f16(o[2 * ntp],     af, bb0);
                mma_f16(o[2 * ntp + 1], af, bb1);
            }
        }
    }

    // --- epilogue: normalize, store single fp16 to g_a [b, s, h, dh] ---
    float i0 = (l0 > 0.f) ? 1.f / l0 : 0.f;
    float i1 = (l1 > 0.f) ? 1.f / l1 : 0.f;
    size_t ob = head_off + (size_t)(qb * 128) * DD;
    #pragma unroll
    for (int nt = 0; nt < 8; nt++) {
        int c = nt * 8 + cq * 2;
        *reinterpret_cast<unsigned*>(g_a + ob + (size_t)row0 * DD + c) =
            f16x2_of(o[nt][1] * i0, o[nt][0] * i0);
        *reinterpret_cast<unsigned*>(g_a + ob + (size_t)(row0 + 8) * DD + c) =
            f16x2_of(o[nt][3] * i1, o[nt][2] * i1);
    }
}

// ---------------------------------------------------------------------------
extern "C" void kernel_launch(void* const* d_in, const int* in_sizes, int n_in,
                              void* d_out, int out_size)
{
    (void)in_sizes; (void)n_in; (void)out_size;
    const float* x  = (const float*)d_in[0];
    const float* Wq = (const float*)d_in[1];
    const float* bq = (const float*)d_in[2];
    const float* Wk = (const float*)d_in[3];
    const float* bk = (const float*)d_in[4];
    const float* Wv = (const float*)d_in[5];
    const float* bv = (const float*)d_in[6];
    const float* Wo = (const float*)d_in[7];
    const float* bo = (const float*)d_in[8];
    const int*   pm = (const int*)d_in[9];
    float* out = (float*)d_out;

    cudaFuncSetAttribute(gemm_k, cudaFuncAttributeMaxDynamicSharedMemorySize, GEMM_SMEM);
    cudaFuncSetAttribute(flash_attn_kernel, cudaFuncAttributeMaxDynamicSharedMemorySize, FLASH_SMEM);

    split_src<<<(BSROWS * DD / 4) / 256, 256>>>(x);
    dim3 wgrid(32, 32, 4);
    wsplit_all<<<wgrid, 256>>>(Wq, Wk, Wv, Wo);

    dim3 qkvgrid(BSROWS / 128, DD / 64, 3);     // (64, 16, 3)
    gemm_k<<<qkvgrid, 256, GEMM_SMEM>>>(bq, bk, bv, nullptr, -1);

    dim3 fgrid(SS / 128, BB * HH);              // (16, 64)
    flash_attn_kernel<<<fgrid, 256, FLASH_SMEM>>>(pm);

    dim3 ogrid(BSROWS / 128, DD / 64, 1);       // (64, 16, 1)
    gemm_k<<<ogrid, 256, GEMM_SMEM>>>(bo, nullptr, nullptr, out, 3);
}

// round 13
// speedup vs baseline: 2.3099x; 1.2339x over previous
#include <cuda_runtime.h>
#include <cuda_bf16.h>
#include <cuda_fp16.h>
#include <cstdint>

// Problem constants
#define BB 4
#define SS 2048
#define DD 1024
#define HH 16
#define DHH 64
#define BSROWS (BB * SS)          // 8192

// ---------------------------------------------------------------------------
// Device-global scratch (allocation-free). fp16:
// x, q, k, v, attended: single; W: hi/mid 2-term (mid used only by out-proj).
// ---------------------------------------------------------------------------
__device__ __half g_x[(size_t)BSROWS * DD];
__device__ __half g_q[(size_t)BSROWS * DD];
__device__ __half g_k[(size_t)BSROWS * DD];
__device__ __half g_v[(size_t)BSROWS * DD];
__device__ __half g_a[(size_t)BSROWS * DD];
__device__ __half g_wth[4 * (size_t)DD * DD], g_wtm[4 * (size_t)DD * DD];  // W^T [n][k]

#define LOG2E 1.4426950408889634f

// ---------------------------------------------------------------------------
// Helpers
// ---------------------------------------------------------------------------
__device__ __forceinline__ void mma_f16(float* c, const unsigned* a, const unsigned* b) {
    asm volatile(
        "mma.sync.aligned.m16n8k16.row.col.f32.f16.f16.f32 "
        "{%0,%1,%2,%3}, {%4,%5,%6,%7}, {%8,%9}, {%0,%1,%2,%3};\n"
        : "+f"(c[0]), "+f"(c[1]), "+f"(c[2]), "+f"(c[3])
        : "r"(a[0]), "r"(a[1]), "r"(a[2]), "r"(a[3]),
          "r"(b[0]), "r"(b[1]));
}

__device__ __forceinline__ void ldm_x4(unsigned* r, uint32_t addr) {
    asm volatile("ldmatrix.sync.aligned.m8n8.x4.shared.b16 {%0,%1,%2,%3}, [%4];"
        : "=r"(r[0]), "=r"(r[1]), "=r"(r[2]), "=r"(r[3]) : "r"(addr));
}
__device__ __forceinline__ void ldm_x4t(unsigned* r, uint32_t addr) {
    asm volatile("ldmatrix.sync.aligned.m8n8.x4.trans.shared.b16 {%0,%1,%2,%3}, [%4];"
        : "=r"(r[0]), "=r"(r[1]), "=r"(r[2]), "=r"(r[3]) : "r"(addr));
}

// fp16 split/pack
__device__ __forceinline__ unsigned packh2(__half lo, __half hi) {
    unsigned l = __half_as_ushort(lo), h = __half_as_ushort(hi);
    return l | (h << 16);
}
__device__ __forceinline__ void hsplit(float x, __half& h, __half& m) {
    h = __float2half_rn(x);
    m = __float2half_rn(x - __half2float(h));
}
__device__ __forceinline__ unsigned packHMh(float x, float y, unsigned& mp) {
    __half hx, mx, hy, my;
    hsplit(x, hx, mx);
    hsplit(y, hy, my);
    mp = packh2(mx, my);
    return packh2(hx, hy);
}
// f32 pair -> f16x2 (hi arg -> upper half)
__device__ __forceinline__ unsigned f16x2_of(float hi, float lo) {
    unsigned r;
    asm("cvt.rn.f16x2.f32 %0, %1, %2;" : "=r"(r) : "f"(hi), "f"(lo));
    return r;
}
__device__ __forceinline__ float ex2f(float x) {
    float r;
    asm("ex2.approx.ftz.f32 %0, %1;" : "=f"(r) : "f"(x));
    return r;
}

__device__ __forceinline__ void cpa16(void* s, const void* g) {
    unsigned sa = (unsigned)__cvta_generic_to_shared(s);
    asm volatile("cp.async.cg.shared.global [%0], [%1], 16;\n" :: "r"(sa), "l"(g));
}
__device__ __forceinline__ void cpa4(void* s, const void* g) {
    unsigned sa = (unsigned)__cvta_generic_to_shared(s);
    asm volatile("cp.async.ca.shared.global [%0], [%1], 4;\n" :: "r"(sa), "l"(g));
}
__device__ __forceinline__ void cpa_commit() {
    asm volatile("cp.async.commit_group;\n");
}
template <int N>
__device__ __forceinline__ void cpa_wait() {
    asm volatile("cp.async.wait_group %0;\n" :: "n"(N));
}
__device__ __forceinline__ uint32_t smem_u32(const void* p) {
    return (uint32_t)__cvta_generic_to_shared(p);
}

// ---------------------------------------------------------------------------
// Prep: x fp32 -> single fp16
// ---------------------------------------------------------------------------
__global__ __launch_bounds__(256)
void split_src(const float* __restrict__ x)
{
    int i = blockIdx.x * 256 + threadIdx.x;            // over float4s: 2M
    float4 v = reinterpret_cast<const float4*>(x)[i];
    uint2 u;
    u.x = f16x2_of(v.y, v.x);
    u.y = f16x2_of(v.w, v.z);
    reinterpret_cast<uint2*>(g_x)[i] = u;
}

// ---------------------------------------------------------------------------
// Prep: transpose + split all 4 W [k][n] fp32 -> g_wt{h,m}[z] as [n][k] fp16
// ---------------------------------------------------------------------------
__global__ __launch_bounds__(256)
void wsplit_all(const float* __restrict__ W0, const float* __restrict__ W1,
                const float* __restrict__ W2, const float* __restrict__ W3)
{
    const int widx = blockIdx.z;
    const float* W = (widx == 0) ? W0 : (widx == 1) ? W1 : (widx == 2) ? W2 : W3;
    __shared__ float t[32][33];
    const int kb = blockIdx.x * 32, nb = blockIdx.y * 32;
    const int r = threadIdx.x >> 3, c4 = (threadIdx.x & 7) * 4;
    float4 v = *reinterpret_cast<const float4*>(W + (size_t)(kb + r) * DD + nb + c4);
    t[r][c4 + 0] = v.x; t[r][c4 + 1] = v.y; t[r][c4 + 2] = v.z; t[r][c4 + 3] = v.w;
    __syncthreads();
    __half* oh = g_wth + (size_t)widx * DD * DD;
    __half* om = g_wtm + (size_t)widx * DD * DD;
    uint2 uh, um;
    uh.x = packHMh(t[c4 + 0][r], t[c4 + 1][r], um.x);
    uh.y = packHMh(t[c4 + 2][r], t[c4 + 3][r], um.y);
    size_t o = (size_t)(nb + r) * DD + kb + c4;
    *reinterpret_cast<uint2*>(oh + o) = uh;
    *reinterpret_cast<uint2*>(om + o) = um;
}

// ---------------------------------------------------------------------------
// GEMM (fp16, m16n8k16 + ldmatrix): C = A * W^T' + bias, M=8192, N=K=1024
// A single fp16. W: QKV -> SINGLE term (wH only); out-proj -> 2-term (hi/mid).
// CTA tile 128x64, 8 warps (4 M x 2 N), warp tile 32x32. KS=64, 2-stage
// cp.async, one sync/iter. 3 CTAs/SM.
// mode -1: md=blockIdx.z (Q scaled 1/8; K, V single fp16 out)
// mode  3: A=g_a (attended), out fp32 to outF
// ---------------------------------------------------------------------------
#define KS 64
#define AST 72
#define ASLAB (2 * 128 * AST)                // A halves (both stages) = 18432
#define BSLAB (2 * 64 * AST)                 // per-term B halves      = 9216
#define GEMM_SMEM ((ASLAB + 2 * BSLAB) * 2)  // 73728 bytes
#define GMOFF (BSLAB * 2)                    // sBh->sBm byte offset

__global__ __launch_bounds__(256, 3)
void gemm_k(const float* __restrict__ b0, const float* __restrict__ b1,
            const float* __restrict__ b2, float* __restrict__ outF, int mode)
{
    const int md = (mode < 0) ? (int)blockIdx.z : mode;
    const bool twoterm = (md == 3);
    const __half* A = (md < 3) ? g_x : g_a;
    const __half* Wh = g_wth + (size_t)md * DD * DD;
    const __half* Wm = g_wtm + (size_t)md * DD * DD;
    const float* bias = (md == 1) ? b1 : (md == 2) ? b2 : b0;
    const float scale = (md == 0) ? 0.125f : 1.0f;

    extern __shared__ __half sm[];
    __half* sA  = sm;
    __half* sBh = sm + ASLAB;
    __half* sBm = sm + ASLAB + BSLAB;
    const uint32_t uA  = smem_u32(sA);
    const uint32_t uBh = smem_u32(sBh);

    const int tid  = threadIdx.x;
    const int lane = tid & 31;
    const int warp = tid >> 5;
    const int wm = warp & 3, wn = warp >> 2;
    const int cm = blockIdx.x * 128, cn = blockIdx.y * 64;
    const int rq = lane >> 2, cq = lane & 3;

    // ldmatrix lane->row mappings
    const int a_r = lane & 15, a_k = (lane >> 4) * 8;               // A x4
    const int b_n = ((lane >> 3) & 1) * 8 + (lane & 7);             // B x4 (pair of n-tiles)
    const int b_k = (lane >> 4) * 8;

    // stage kt (64 k-columns) into buffer buf
    auto issue = [&](int kt, int buf) {
        const int k0 = kt * KS;
        #pragma unroll
        for (int i = 0; i < 4; i++) {                // A: 128 rows
            int idx = i * 256 + tid;
            int r = idx >> 3, c8 = (idx & 7) * 8;
            size_t ga = (size_t)(cm + r) * DD + k0 + c8;
            int so = buf * 128 * AST + r * AST + c8;
            cpa16(&sA[so], A + ga);
        }
        #pragma unroll
        for (int i = 0; i < 2; i++) {                // B: 64 rows
            int idx = i * 256 + tid;
            int r = idx >> 3, c8 = (idx & 7) * 8;
            size_t gb = (size_t)(cn + r) * DD + k0 + c8;
            int so = buf * 64 * AST + r * AST + c8;
            cpa16(&sBh[so], Wh + gb);
            if (twoterm) cpa16(&sBm[so], Wm + gb);
        }
        cpa_commit();
    };

    float acc[2][4][4];
    #pragma unroll
    for (int mt = 0; mt < 2; mt++)
        #pragma unroll
        for (int nt = 0; nt < 4; nt++)
            #pragma unroll
            for (int j = 0; j < 4; j++) acc[mt][nt][j] = 0.f;

    const int NK = DD / KS;  // 16
    issue(0, 0);

    for (int kt = 0; kt < NK; ++kt) {
        const int cur = kt & 1;
        cpa_wait<0>();
        __syncthreads();            // stage kt visible; readers of buf cur^1 retired
        if (kt + 1 < NK) issue(kt + 1, cur ^ 1);   // overlaps all compute below

        const uint32_t abase = uA + (uint32_t)(cur * 128 * AST * 2) +
                               (uint32_t)(((wm * 32 + a_r) * AST + a_k) * 2);
        const uint32_t bbase = uBh + (uint32_t)(cur * 64 * AST * 2) +
                               (uint32_t)(((wn * 32 + b_n) * AST + b_k) * 2);
        #pragma unroll
        for (int ch = 0; ch < 4; ++ch) {
            const uint32_t kc2 = (uint32_t)(ch * 32);   // 16 halves per chunk
            unsigned ah[2][4];
            #pragma unroll
            for (int mt = 0; mt < 2; mt++)
                ldm_x4(ah[mt], abase + (uint32_t)(mt * 16 * AST * 2) + kc2);
            // pass A: a * wH
            #pragma unroll
            for (int ntp = 0; ntp < 2; ntp++) {
                unsigned kf[4];
                ldm_x4(kf, bbase + (uint32_t)(ntp * 16 * AST * 2) + kc2);
                unsigned bb0[2] = {kf[0], kf[2]}, bb1[2] = {kf[1], kf[3]};
                mma_f16(acc[0][2 * ntp],     ah[0], bb0);
                mma_f16(acc[1][2 * ntp],     ah[1], bb0);
                mma_f16(acc[0][2 * ntp + 1], ah[0], bb1);
                mma_f16(acc[1][2 * ntp + 1], ah[1], bb1);
            }
            // pass B: a * wM (out-proj only)
            if (twoterm) {
                #pragma unroll
                for (int ntp = 0; ntp < 2; ntp++) {
                    unsigned kf[4];
                    ldm_x4(kf, bbase + (uint32_t)(ntp * 16 * AST * 2) + kc2 + GMOFF);
                    unsigned bb0[2] = {kf[0], kf[2]}, bb1[2] = {kf[1], kf[3]};
                    mma_f16(acc[0][2 * ntp],     ah[0], bb0);
                    mma_f16(acc[1][2 * ntp],     ah[1], bb0);
                    mma_f16(acc[0][2 * ntp + 1], ah[0], bb1);
                    mma_f16(acc[1][2 * ntp + 1], ah[1], bb1);
                }
            }
        }
    }

    // epilogue
    #pragma unroll
    for (int mt = 0; mt < 2; mt++) {
        int r = cm + wm * 32 + mt * 16 + rq;
        #pragma unroll
        for (int nt = 0; nt < 4; nt++) {
            int c = cn + wn * 32 + nt * 8 + cq * 2;
            float bb0 = bias[c], bb1 = bias[c + 1];
            float v0 = (acc[mt][nt][0] + bb0) * scale;
            float v1 = (acc[mt][nt][1] + bb1) * scale;
            float v2 = (acc[mt][nt][2] + bb0) * scale;
            float v3 = (acc[mt][nt][3] + bb1) * scale;
            if (md == 3) {
                *reinterpret_cast<float2*>(outF + (size_t)r * DD + c) = make_float2(v0, v1);
                *reinterpret_cast<float2*>(outF + (size_t)(r + 8) * DD + c) = make_float2(v2, v3);
            } else {                // Q (pre-scaled) / K / V: single fp16
                __half* O = (md == 0) ? g_q : (md == 1) ? g_k : g_v;
                *reinterpret_cast<unsigned*>(O + (size_t)r * DD + c) = f16x2_of(v1, v0);
                *reinterpret_cast<unsigned*>(O + (size_t)(r + 8) * DD + c) = f16x2_of(v3, v2);
            }
        }
    }
}

// ---------------------------------------------------------------------------
// Flash attention (UNCHANGED — near multi-pipe roofline).
// 128-row Q tiles, 8 warps. QK: fp16 x fp16. PV: fp16 P x fp16 V.
// smem halves: Q (128xFST) | K0,K1 | V0,V1 (64xFST) | Ms[2][64]
// ---------------------------------------------------------------------------
#define FST 72                                // smem k-stride (halves)
#define F64 (64 * FST)                        // halves per 64-row array
#define QFQ (128 * FST)                       // Q halves
#define KOFF QFQ
#define VOFF (QFQ + 2 * F64)
#define FLASH_SMEM ((QFQ + 4 * F64) * 2 + 2 * 64 * 4)   // 55808 bytes

__global__ __launch_bounds__(256, 2)
void flash_attn_kernel(const int* __restrict__ pmask)
{
    extern __shared__ __half fsm[];
    int* Ms0 = reinterpret_cast<int*>(fsm + QFQ + 4 * F64);
    const uint32_t uQ = smem_u32(fsm);

    const int tid = threadIdx.x, lane = tid & 31, warp = tid >> 5;
    const int qb = (int)(gridDim.x - 1) - (int)blockIdx.x;  // heavy tiles first
    const int bh = blockIdx.y;
    const int b = bh >> 4, h = bh & 15;
    const size_t head_off = ((size_t)b * SS) * DD + (size_t)h * DHH;
    const int nkb = 2 * qb + 2;               // 64-wide key blocks needed

    const int rq = lane >> 2, cq = lane & 3;
    const int row0 = warp * 16 + rq;

    // ldmatrix lane->row mappings
    const int a_r = lane & 15, a_k = (lane >> 4) * 8;      // Q (A, x4)
    const int b_n = ((lane >> 3) & 1) * 8 + (lane & 7);    // K (B, x4 pair)
    const int b_k = (lane >> 4) * 8;
    const int v_k = ((lane >> 3) & 1) * 8 + (lane & 7);    // V (B^T via x4.trans)
    const int v_n = (lane >> 4) * 8;

    auto issueKV = [&](int kb) {
        const int bsel = kb & 1;
        __half* KS_ = fsm + KOFF + F64 * bsel;
        __half* VS = fsm + VOFF + F64 * bsel;
        #pragma unroll
        for (int i = 0; i < 2; i++) {
            int idx = i * 256 + tid;
            int r = idx >> 3, c8 = (idx & 7) * 8;
            size_t g = head_off + (size_t)(kb * 64 + r) * DD + c8;
            cpa16(&KS_[r * FST + c8], g_k + g);
            cpa16(&VS[r * FST + c8], g_v + g);
        }
        if (tid < 64) cpa4(&Ms0[bsel * 64 + tid], pmask + b * SS + kb * 64 + tid);
        cpa_commit();
    };

    // Prologue: Q (128x64 single fp16) + K0/V0/mask0 in ONE group
    #pragma unroll
    for (int i = 0; i < 4; i++) {
        int idx = i * 256 + tid;
        int r = idx >> 3, c8 = (idx & 7) * 8;
        size_t g = head_off + (size_t)(qb * 128 + r) * DD + c8;
        cpa16(&fsm[r * FST + c8], g_q + g);
    }
    {
        __half* KS_ = fsm + KOFF;
        __half* VS = fsm + VOFF;
        #pragma unroll
        for (int i = 0; i < 2; i++) {
            int idx = i * 256 + tid;
            int r = idx >> 3, c8 = (idx & 7) * 8;
            size_t g = head_off + (size_t)r * DD + c8;
            cpa16(&KS_[r * FST + c8], g_k + g);
            cpa16(&VS[r * FST + c8], g_v + g);
        }
        if (tid < 64) cpa4(&Ms0[tid], pmask + b * SS + tid);
        cpa_commit();
    }

    float o[8][4];
    #pragma unroll
    for (int nt = 0; nt < 8; nt++)
        #pragma unroll
        for (int j = 0; j < 4; j++) o[nt][j] = 0.f;
    float m0 = -1e30f, m1 = -1e30f, l0 = 0.f, l1 = 0.f;

    const uint32_t qbase = uQ + (uint32_t)(((warp * 16 + a_r) * FST + a_k) * 2);

    for (int kb = 0; kb < nkb; ++kb) {
        cpa_wait<0>();
        __syncthreads();
        if (kb + 1 < nkb) issueKV(kb + 1);

        // warp-uniform skip: entire kv-block above this warp's rows
        if (kb * 64 > qb * 128 + warp * 16 + 15) continue;

        const uint32_t uKH = smem_u32(fsm + KOFF + F64 * (kb & 1));
        const uint32_t uVS = smem_u32(fsm + VOFF + F64 * (kb & 1));
        const int* Ms = Ms0 + (kb & 1) * 64;

        // mask fast-path detection (warp-uniform)
        unsigned mw0 = __ballot_sync(0xffffffffu, Ms[lane] != 0);
        unsigned mw1 = __ballot_sync(0xffffffffu, Ms[32 + lane] != 0);
        const bool needmask = ((mw0 & mw1) != 0xffffffffu) ||
                              (kb * 64 + 63 > qb * 128 + warp * 16);

        // --- S = Q K^T (warp: 16 x 64), single-term fp16 ---
        float sc[8][4];
        #pragma unroll
        for (int nt = 0; nt < 8; nt++)
            #pragma unroll
            for (int j = 0; j < 4; j++) sc[nt][j] = 0.f;

        const uint32_t kbase = uKH + (uint32_t)((b_n * FST + b_k) * 2);
        #pragma unroll
        for (int ch = 0; ch < 4; ++ch) {
            const uint32_t kc2 = (uint32_t)(ch * 32);
            unsigned ah[4];
            ldm_x4(ah, qbase + kc2);
            #pragma unroll
            for (int ntp = 0; ntp < 4; ntp++) {
                unsigned kf[4];
                ldm_x4(kf, kbase + (uint32_t)(ntp * 16 * FST * 2) + kc2);
                unsigned bb0[2] = {kf[0], kf[2]}, bb1[2] = {kf[1], kf[3]};
                mma_f16(sc[2 * ntp],     ah, bb0);
                mma_f16(sc[2 * ntp + 1], ah, bb1);
            }
        }

        // --- mask (slow path only; Q pre-scaled; sentinel -1e30) ---
        if (needmask) {
            const int gm0 = qb * 128 + row0, gm1 = gm0 + 8;
            #pragma unroll
            for (int nt = 0; nt < 8; nt++) {
                int nloc = nt * 8 + cq * 2;
                int gn = kb * 64 + nloc;
                #pragma unroll
                for (int j = 0; j < 2; j++) {
                    bool pv = (Ms[nloc + j] != 0);
                    sc[nt][j]     = (pv && (gn + j) <= gm0) ? sc[nt][j]     : -1e30f;
                    sc[nt][2 + j] = (pv && (gn + j) <= gm1) ? sc[nt][2 + j] : -1e30f;
                }
            }
        }

        // --- online softmax ---
        float mx0 = -1e30f, mx1 = -1e30f;
        #pragma unroll
        for (int nt = 0; nt < 8; nt++) {
            mx0 = fmaxf(mx0, fmaxf(sc[nt][0], sc[nt][1]));
            mx1 = fmaxf(mx1, fmaxf(sc[nt][2], sc[nt][3]));
        }
        mx0 = fmaxf(mx0, __shfl_xor_sync(0xffffffffu, mx0, 1));
        mx0 = fmaxf(mx0, __shfl_xor_sync(0xffffffffu, mx0, 2));
        mx1 = fmaxf(mx1, __shfl_xor_sync(0xffffffffu, mx1, 1));
        mx1 = fmaxf(mx1, __shfl_xor_sync(0xffffffffu, mx1, 2));

        float mn0 = fmaxf(m0, mx0), mn1 = fmaxf(m1, mx1);
        float al0 = ex2f((m0 - mn0) * LOG2E);
        float al1 = ex2f((m1 - mn1) * LOG2E);
        const float c0 = mn0 * LOG2E, c1 = mn1 * LOG2E;

        float s0 = 0.f, s1 = 0.f;
        #pragma unroll
        for (int nt = 0; nt < 8; nt++) {
            sc[nt][0] = ex2f(fmaf(sc[nt][0], LOG2E, -c0));
            sc[nt][1] = ex2f(fmaf(sc[nt][1], LOG2E, -c0));
            sc[nt][2] = ex2f(fmaf(sc[nt][2], LOG2E, -c1));
            sc[nt][3] = ex2f(fmaf(sc[nt][3], LOG2E, -c1));
            s0 += sc[nt][0] + sc[nt][1];
            s1 += sc[nt][2] + sc[nt][3];
        }
        s0 += __shfl_xor_sync(0xffffffffu, s0, 1);
        s0 += __shfl_xor_sync(0xffffffffu, s0, 2);
        s1 += __shfl_xor_sync(0xffffffffu, s1, 1);
        s1 += __shfl_xor_sync(0xffffffffu, s1, 2);

        l0 = l0 * al0 + s0;
        l1 = l1 * al1 + s1;
        m0 = mn0; m1 = mn1;

        #pragma unroll
        for (int nt = 0; nt < 8; nt++) {
            o[nt][0] *= al0; o[nt][1] *= al0;
            o[nt][2] *= al1; o[nt][3] *= al1;
        }

        // --- P -> fp16x2 fragments (exact pack) ---
        unsigned pf[16];
        #pragma unroll
        for (int nt = 0; nt < 8; nt++) {
            pf[2 * nt]     = f16x2_of(sc[nt][1], sc[nt][0]);
            pf[2 * nt + 1] = f16x2_of(sc[nt][3], sc[nt][2]);
        }

        // --- O += P V (fp16, single V term) ---
        const uint32_t vbase = uVS + (uint32_t)((v_k * FST + v_n) * 2);
        #pragma unroll
        for (int ch = 0; ch < 4; ++ch) {
            unsigned* af = &pf[4 * ch];
            const uint32_t cOff = (uint32_t)(ch * 16 * FST * 2);
            #pragma unroll
            for (int ntp = 0; ntp < 4; ntp++) {
                unsigned vf[4];
                ldm_x4t(vf, vbase + cOff + (uint32_t)(ntp * 16 * 2));
                unsigned bb0[2] = {vf[0], vf[1]}, bb1[2] = {vf[2], vf[3]};
                mma_f16(o[2 * ntp],     af, bb0);
                mma_f16(o[2 * ntp + 1], af, bb1);
            }
        }
    }

    // --- epilogue: normalize, store single fp16 to g_a [b, s, h, dh] ---
    float i0 = (l0 > 0.f) ? 1.f / l0 : 0.f;
    float i1 = (l1 > 0.f) ? 1.f / l1 : 0.f;
    size_t ob = head_off + (size_t)(qb * 128) * DD;
    #pragma unroll
    for (int nt = 0; nt < 8; nt++) {
        int c = nt * 8 + cq * 2;
        *reinterpret_cast<unsigned*>(g_a + ob + (size_t)row0 * DD + c) =
            f16x2_of(o[nt][1] * i0, o[nt][0] * i0);
        *reinterpret_cast<unsigned*>(g_a + ob + (size_t)(row0 + 8) * DD + c) =
            f16x2_of(o[nt][3] * i1, o[nt][2] * i1);
    }
}

// ---------------------------------------------------------------------------
extern "C" void kernel_launch(void* const* d_in, const int* in_sizes, int n_in,
                              void* d_out, int out_size)
{
    (void)in_sizes; (void)n_in; (void)out_size;
    const float* x  = (const float*)d_in[0];
    const float* Wq = (const float*)d_in[1];
    const float* bq = (const float*)d_in[2];
    const float* Wk = (const float*)d_in[3];
    const float* bk = (const float*)d_in[4];
    const float* Wv = (const float*)d_in[5];
    const float* bv = (const float*)d_in[6];
    const float* Wo = (const float*)d_in[7];
    const float* bo = (const float*)d_in[8];
    const int*   pm = (const int*)d_in[9];
    float* out = (float*)d_out;

    cudaFuncSetAttribute(gemm_k, cudaFuncAttributeMaxDynamicSharedMemorySize, GEMM_SMEM);
    cudaFuncSetAttribute(flash_attn_kernel, cudaFuncAttributeMaxDynamicSharedMemorySize, FLASH_SMEM);

    split_src<<<(BSROWS * DD / 4) / 256, 256>>>(x);
    dim3 wgrid(32, 32, 4);
    wsplit_all<<<wgrid, 256>>>(Wq, Wk, Wv, Wo);

    dim3 qkvgrid(BSROWS / 128, DD / 64, 3);     // (64, 16, 3)
    gemm_k<<<qkvgrid, 256, GEMM_SMEM>>>(bq, bk, bv, nullptr, -1);

    dim3 fgrid(SS / 128, BB * HH);              // (16, 64)
    flash_attn_kernel<<<fgrid, 256, FLASH_SMEM>>>(pm);

    dim3 ogrid(BSROWS / 128, DD / 64, 1);       // (64, 16, 1)
    gemm_k<<<ogrid, 256, GEMM_SMEM>>>(bo, nullptr, nullptr, out, 3);
}

// round 14
// speedup vs baseline: 2.5725x; 1.1137x over previous
#include <cuda_runtime.h>
#include <cuda_bf16.h>
#include <cuda_fp16.h>
#include <cstdint>

// Problem constants
#define BB 4
#define SS 2048
#define DD 1024
#define HH 16
#define DHH 64
#define BSROWS (BB * SS)          // 8192

// ---------------------------------------------------------------------------
// Device-global scratch (allocation-free). All single fp16 now.
// ---------------------------------------------------------------------------
__device__ __half g_x[(size_t)BSROWS * DD];
__device__ __half g_q[(size_t)BSROWS * DD];
__device__ __half g_k[(size_t)BSROWS * DD];
__device__ __half g_v[(size_t)BSROWS * DD];
__device__ __half g_a[(size_t)BSROWS * DD];
__device__ __half g_wt[4 * (size_t)DD * DD];   // W^T [n][k], single fp16

#define LOG2E 1.4426950408889634f

// ---------------------------------------------------------------------------
// Helpers
// ---------------------------------------------------------------------------
__device__ __forceinline__ void mma_f16(float* c, const unsigned* a, const unsigned* b) {
    asm volatile(
        "mma.sync.aligned.m16n8k16.row.col.f32.f16.f16.f32 "
        "{%0,%1,%2,%3}, {%4,%5,%6,%7}, {%8,%9}, {%0,%1,%2,%3};\n"
        : "+f"(c[0]), "+f"(c[1]), "+f"(c[2]), "+f"(c[3])
        : "r"(a[0]), "r"(a[1]), "r"(a[2]), "r"(a[3]),
          "r"(b[0]), "r"(b[1]));
}

__device__ __forceinline__ void ldm_x4(unsigned* r, uint32_t addr) {
    asm volatile("ldmatrix.sync.aligned.m8n8.x4.shared.b16 {%0,%1,%2,%3}, [%4];"
        : "=r"(r[0]), "=r"(r[1]), "=r"(r[2]), "=r"(r[3]) : "r"(addr));
}
__device__ __forceinline__ void ldm_x4t(unsigned* r, uint32_t addr) {
    asm volatile("ldmatrix.sync.aligned.m8n8.x4.trans.shared.b16 {%0,%1,%2,%3}, [%4];"
        : "=r"(r[0]), "=r"(r[1]), "=r"(r[2]), "=r"(r[3]) : "r"(addr));
}

// f32 pair -> f16x2 (hi arg -> upper half)
__device__ __forceinline__ unsigned f16x2_of(float hi, float lo) {
    unsigned r;
    asm("cvt.rn.f16x2.f32 %0, %1, %2;" : "=r"(r) : "f"(hi), "f"(lo));
    return r;
}
__device__ __forceinline__ float ex2f(float x) {
    float r;
    asm("ex2.approx.ftz.f32 %0, %1;" : "=f"(r) : "f"(x));
    return r;
}

__device__ __forceinline__ void cpa16(void* s, const void* g) {
    unsigned sa = (unsigned)__cvta_generic_to_shared(s);
    asm volatile("cp.async.cg.shared.global [%0], [%1], 16;\n" :: "r"(sa), "l"(g));
}
__device__ __forceinline__ void cpa4(void* s, const void* g) {
    unsigned sa = (unsigned)__cvta_generic_to_shared(s);
    asm volatile("cp.async.ca.shared.global [%0], [%1], 4;\n" :: "r"(sa), "l"(g));
}
__device__ __forceinline__ void cpa_commit() {
    asm volatile("cp.async.commit_group;\n");
}
template <int N>
__device__ __forceinline__ void cpa_wait() {
    asm volatile("cp.async.wait_group %0;\n" :: "n"(N));
}
__device__ __forceinline__ uint32_t smem_u32(const void* p) {
    return (uint32_t)__cvta_generic_to_shared(p);
}

// ---------------------------------------------------------------------------
// Prep: x fp32 -> single fp16
// ---------------------------------------------------------------------------
__global__ __launch_bounds__(256)
void split_src(const float* __restrict__ x)
{
    int i = blockIdx.x * 256 + threadIdx.x;            // over float4s: 2M
    float4 v = reinterpret_cast<const float4*>(x)[i];
    uint2 u;
    u.x = f16x2_of(v.y, v.x);
    u.y = f16x2_of(v.w, v.z);
    reinterpret_cast<uint2*>(g_x)[i] = u;
}

// ---------------------------------------------------------------------------
// Prep: transpose all 4 W [k][n] fp32 -> g_wt[z] as [n][k] single fp16
// ---------------------------------------------------------------------------
__global__ __launch_bounds__(256)
void wsplit_all(const float* __restrict__ W0, const float* __restrict__ W1,
                const float* __restrict__ W2, const float* __restrict__ W3)
{
    const int widx = blockIdx.z;
    const float* W = (widx == 0) ? W0 : (widx == 1) ? W1 : (widx == 2) ? W2 : W3;
    __shared__ float t[32][33];
    const int kb = blockIdx.x * 32, nb = blockIdx.y * 32;
    const int r = threadIdx.x >> 3, c4 = (threadIdx.x & 7) * 4;
    float4 v = *reinterpret_cast<const float4*>(W + (size_t)(kb + r) * DD + nb + c4);
    t[r][c4 + 0] = v.x; t[r][c4 + 1] = v.y; t[r][c4 + 2] = v.z; t[r][c4 + 3] = v.w;
    __syncthreads();
    __half* oh = g_wt + (size_t)widx * DD * DD;
    uint2 uh;
    uh.x = f16x2_of(t[c4 + 1][r], t[c4 + 0][r]);
    uh.y = f16x2_of(t[c4 + 3][r], t[c4 + 2][r]);
    size_t o = (size_t)(nb + r) * DD + kb + c4;
    *reinterpret_cast<uint2*>(oh + o) = uh;
}

// ---------------------------------------------------------------------------
// GEMM (single fp16, m16n8k16 + ldmatrix): C = A * W^T' + bias, M=8192, N=K=1024
// CTA tile 128x64, 8 warps (4 M x 2 N), warp tile 32x32. KS=64, 2-stage
// cp.async, one sync/iter. 3 CTAs/SM.
// mode -1: md=blockIdx.z (Q scaled 1/8; K, V single fp16 out)
// mode  3: A=g_a (attended), out fp32 to outF
// ---------------------------------------------------------------------------
#define KS 64
#define AST 72
#define ASLAB (2 * 128 * AST)                // A halves (both stages) = 18432
#define BSLAB (2 * 64 * AST)                 // B halves               = 9216
#define GEMM_SMEM ((ASLAB + BSLAB) * 2)      // 55296 bytes

__global__ __launch_bounds__(256, 3)
void gemm_k(const float* __restrict__ b0, const float* __restrict__ b1,
            const float* __restrict__ b2, float* __restrict__ outF, int mode)
{
    const int md = (mode < 0) ? (int)blockIdx.z : mode;
    const __half* A = (md < 3) ? g_x : g_a;
    const __half* Wh = g_wt + (size_t)md * DD * DD;
    const float* bias = (md == 1) ? b1 : (md == 2) ? b2 : b0;
    const float scale = (md == 0) ? 0.125f : 1.0f;

    extern __shared__ __half sm[];
    __half* sA  = sm;
    __half* sBh = sm + ASLAB;
    const uint32_t uA  = smem_u32(sA);
    const uint32_t uBh = smem_u32(sBh);

    const int tid  = threadIdx.x;
    const int lane = tid & 31;
    const int warp = tid >> 5;
    const int wm = warp & 3, wn = warp >> 2;
    const int cm = blockIdx.x * 128, cn = blockIdx.y * 64;
    const int rq = lane >> 2, cq = lane & 3;

    // ldmatrix lane->row mappings
    const int a_r = lane & 15, a_k = (lane >> 4) * 8;               // A x4
    const int b_n = ((lane >> 3) & 1) * 8 + (lane & 7);             // B x4 (pair of n-tiles)
    const int b_k = (lane >> 4) * 8;

    // stage kt (64 k-columns) into buffer buf
    auto issue = [&](int kt, int buf) {
        const int k0 = kt * KS;
        #pragma unroll
        for (int i = 0; i < 4; i++) {                // A: 128 rows
            int idx = i * 256 + tid;
            int r = idx >> 3, c8 = (idx & 7) * 8;
            size_t ga = (size_t)(cm + r) * DD + k0 + c8;
            int so = buf * 128 * AST + r * AST + c8;
            cpa16(&sA[so], A + ga);
        }
        #pragma unroll
        for (int i = 0; i < 2; i++) {                // B: 64 rows
            int idx = i * 256 + tid;
            int r = idx >> 3, c8 = (idx & 7) * 8;
            size_t gb = (size_t)(cn + r) * DD + k0 + c8;
            int so = buf * 64 * AST + r * AST + c8;
            cpa16(&sBh[so], Wh + gb);
        }
        cpa_commit();
    };

    float acc[2][4][4];
    #pragma unroll
    for (int mt = 0; mt < 2; mt++)
        #pragma unroll
        for (int nt = 0; nt < 4; nt++)
            #pragma unroll
            for (int j = 0; j < 4; j++) acc[mt][nt][j] = 0.f;

    const int NK = DD / KS;  // 16
    issue(0, 0);

    for (int kt = 0; kt < NK; ++kt) {
        const int cur = kt & 1;
        cpa_wait<0>();
        __syncthreads();            // stage kt visible; readers of buf cur^1 retired
        if (kt + 1 < NK) issue(kt + 1, cur ^ 1);   // overlaps all compute below

        const uint32_t abase = uA + (uint32_t)(cur * 128 * AST * 2) +
                               (uint32_t)(((wm * 32 + a_r) * AST + a_k) * 2);
        const uint32_t bbase = uBh + (uint32_t)(cur * 64 * AST * 2) +
                               (uint32_t)(((wn * 32 + b_n) * AST + b_k) * 2);
        #pragma unroll
        for (int ch = 0; ch < 4; ++ch) {
            const uint32_t kc2 = (uint32_t)(ch * 32);   // 16 halves per chunk
            unsigned ah[2][4];
            #pragma unroll
            for (int mt = 0; mt < 2; mt++)
                ldm_x4(ah[mt], abase + (uint32_t)(mt * 16 * AST * 2) + kc2);
            #pragma unroll
            for (int ntp = 0; ntp < 2; ntp++) {
                unsigned kf[4];
                ldm_x4(kf, bbase + (uint32_t)(ntp * 16 * AST * 2) + kc2);
                unsigned bb0[2] = {kf[0], kf[2]}, bb1[2] = {kf[1], kf[3]};
                mma_f16(acc[0][2 * ntp],     ah[0], bb0);
                mma_f16(acc[1][2 * ntp],     ah[1], bb0);
                mma_f16(acc[0][2 * ntp + 1], ah[0], bb1);
                mma_f16(acc[1][2 * ntp + 1], ah[1], bb1);
            }
        }
    }

    // epilogue
    #pragma unroll
    for (int mt = 0; mt < 2; mt++) {
        int r = cm + wm * 32 + mt * 16 + rq;
        #pragma unroll
        for (int nt = 0; nt < 4; nt++) {
            int c = cn + wn * 32 + nt * 8 + cq * 2;
            float bb0 = bias[c], bb1 = bias[c + 1];
            float v0 = (acc[mt][nt][0] + bb0) * scale;
            float v1 = (acc[mt][nt][1] + bb1) * scale;
            float v2 = (acc[mt][nt][2] + bb0) * scale;
            float v3 = (acc[mt][nt][3] + bb1) * scale;
            if (md == 3) {
                *reinterpret_cast<float2*>(outF + (size_t)r * DD + c) = make_float2(v0, v1);
                *reinterpret_cast<float2*>(outF + (size_t)(r + 8) * DD + c) = make_float2(v2, v3);
            } else {                // Q (pre-scaled) / K / V: single fp16
                __half* O = (md == 0) ? g_q : (md == 1) ? g_k : g_v;
                *reinterpret_cast<unsigned*>(O + (size_t)r * DD + c) = f16x2_of(v1, v0);
                *reinterpret_cast<unsigned*>(O + (size_t)(r + 8) * DD + c) = f16x2_of(v3, v2);
            }
        }
    }
}

// ---------------------------------------------------------------------------
// Flash attention (UNCHANGED — near multi-pipe roofline).
// 128-row Q tiles, 8 warps. QK: fp16 x fp16. PV: fp16 P x fp16 V.
// smem halves: Q (128xFST) | K0,K1 | V0,V1 (64xFST) | Ms[2][64]
// ---------------------------------------------------------------------------
#define FST 72                                // smem k-stride (halves)
#define F64 (64 * FST)                        // halves per 64-row array
#define QFQ (128 * FST)                       // Q halves
#define KOFF QFQ
#define VOFF (QFQ + 2 * F64)
#define FLASH_SMEM ((QFQ + 4 * F64) * 2 + 2 * 64 * 4)   // 55808 bytes

__global__ __launch_bounds__(256, 2)
void flash_attn_kernel(const int* __restrict__ pmask)
{
    extern __shared__ __half fsm[];
    int* Ms0 = reinterpret_cast<int*>(fsm + QFQ + 4 * F64);
    const uint32_t uQ = smem_u32(fsm);

    const int tid = threadIdx.x, lane = tid & 31, warp = tid >> 5;
    const int qb = (int)(gridDim.x - 1) - (int)blockIdx.x;  // heavy tiles first
    const int bh = blockIdx.y;
    const int b = bh >> 4, h = bh & 15;
    const size_t head_off = ((size_t)b * SS) * DD + (size_t)h * DHH;
    const int nkb = 2 * qb + 2;               // 64-wide key blocks needed

    const int rq = lane >> 2, cq = lane & 3;
    const int row0 = warp * 16 + rq;

    // ldmatrix lane->row mappings
    const int a_r = lane & 15, a_k = (lane >> 4) * 8;      // Q (A, x4)
    const int b_n = ((lane >> 3) & 1) * 8 + (lane & 7);    // K (B, x4 pair)
    const int b_k = (lane >> 4) * 8;
    const int v_k = ((lane >> 3) & 1) * 8 + (lane & 7);    // V (B^T via x4.trans)
    const int v_n = (lane >> 4) * 8;

    auto issueKV = [&](int kb) {
        const int bsel = kb & 1;
        __half* KS_ = fsm + KOFF + F64 * bsel;
        __half* VS = fsm + VOFF + F64 * bsel;
        #pragma unroll
        for (int i = 0; i < 2; i++) {
            int idx = i * 256 + tid;
            int r = idx >> 3, c8 = (idx & 7) * 8;
            size_t g = head_off + (size_t)(kb * 64 + r) * DD + c8;
            cpa16(&KS_[r * FST + c8], g_k + g);
            cpa16(&VS[r * FST + c8], g_v + g);
        }
        if (tid < 64) cpa4(&Ms0[bsel * 64 + tid], pmask + b * SS + kb * 64 + tid);
        cpa_commit();
    };

    // Prologue: Q (128x64 single fp16) + K0/V0/mask0 in ONE group
    #pragma unroll
    for (int i = 0; i < 4; i++) {
        int idx = i * 256 + tid;
        int r = idx >> 3, c8 = (idx & 7) * 8;
        size_t g = head_off + (size_t)(qb * 128 + r) * DD + c8;
        cpa16(&fsm[r * FST + c8], g_q + g);
    }
    {
        __half* KS_ = fsm + KOFF;
        __half* VS = fsm + VOFF;
        #pragma unroll
        for (int i = 0; i < 2; i++) {
            int idx = i * 256 + tid;
            int r = idx >> 3, c8 = (idx & 7) * 8;
            size_t g = head_off + (size_t)r * DD + c8;
            cpa16(&KS_[r * FST + c8], g_k + g);
            cpa16(&VS[r * FST + c8], g_v + g);
        }
        if (tid < 64) cpa4(&Ms0[tid], pmask + b * SS + tid);
        cpa_commit();
    }

    float o[8][4];
    #pragma unroll
    for (int nt = 0; nt < 8; nt++)
        #pragma unroll
        for (int j = 0; j < 4; j++) o[nt][j] = 0.f;
    float m0 = -1e30f, m1 = -1e30f, l0 = 0.f, l1 = 0.f;

    const uint32_t qbase = uQ + (uint32_t)(((warp * 16 + a_r) * FST + a_k) * 2);

    for (int kb = 0; kb < nkb; ++kb) {
        cpa_wait<0>();
        __syncthreads();
        if (kb + 1 < nkb) issueKV(kb + 1);

        // warp-uniform skip: entire kv-block above this warp's rows
        if (kb * 64 > qb * 128 + warp * 16 + 15) continue;

        const uint32_t uKH = smem_u32(fsm + KOFF + F64 * (kb & 1));
        const uint32_t uVS = smem_u32(fsm + VOFF + F64 * (kb & 1));
        const int* Ms = Ms0 + (kb & 1) * 64;

        // mask fast-path detection (warp-uniform)
        unsigned mw0 = __ballot_sync(0xffffffffu, Ms[lane] != 0);
        unsigned mw1 = __ballot_sync(0xffffffffu, Ms[32 + lane] != 0);
        const bool needmask = ((mw0 & mw1) != 0xffffffffu) ||
                              (kb * 64 + 63 > qb * 128 + warp * 16);

        // --- S = Q K^T (warp: 16 x 64), single-term fp16 ---
        float sc[8][4];
        #pragma unroll
        for (int nt = 0; nt < 8; nt++)
            #pragma unroll
            for (int j = 0; j < 4; j++) sc[nt][j] = 0.f;

        const uint32_t kbase = uKH + (uint32_t)((b_n * FST + b_k) * 2);
        #pragma unroll
        for (int ch = 0; ch < 4; ++ch) {
            const uint32_t kc2 = (uint32_t)(ch * 32);
            unsigned ah[4];
            ldm_x4(ah, qbase + kc2);
            #pragma unroll
            for (int ntp = 0; ntp < 4; ntp++) {
                unsigned kf[4];
                ldm_x4(kf, kbase + (uint32_t)(ntp * 16 * FST * 2) + kc2);
                unsigned bb0[2] = {kf[0], kf[2]}, bb1[2] = {kf[1], kf[3]};
                mma_f16(sc[2 * ntp],     ah, bb0);
                mma_f16(sc[2 * ntp + 1], ah, bb1);
            }
        }

        // --- mask (slow path only; Q pre-scaled; sentinel -1e30) ---
        if (needmask) {
            const int gm0 = qb * 128 + row0, gm1 = gm0 + 8;
            #pragma unroll
            for (int nt = 0; nt < 8; nt++) {
                int nloc = nt * 8 + cq * 2;
                int gn = kb * 64 + nloc;
                #pragma unroll
                for (int j = 0; j < 2; j++) {
                    bool pv = (Ms[nloc + j] != 0);
                    sc[nt][j]     = (pv && (gn + j) <= gm0) ? sc[nt][j]     : -1e30f;
                    sc[nt][2 + j] = (pv && (gn + j) <= gm1) ? sc[nt][2 + j] : -1e30f;
                }
            }
        }

        // --- online softmax ---
        float mx0 = -1e30f, mx1 = -1e30f;
        #pragma unroll
        for (int nt = 0; nt < 8; nt++) {
            mx0 = fmaxf(mx0, fmaxf(sc[nt][0], sc[nt][1]));
            mx1 = fmaxf(mx1, fmaxf(sc[nt][2], sc[nt][3]));
        }
        mx0 = fmaxf(mx0, __shfl_xor_sync(0xffffffffu, mx0, 1));
        mx0 = fmaxf(mx0, __shfl_xor_sync(0xffffffffu, mx0, 2));
        mx1 = fmaxf(mx1, __shfl_xor_sync(0xffffffffu, mx1, 1));
        mx1 = fmaxf(mx1, __shfl_xor_sync(0xffffffffu, mx1, 2));

        float mn0 = fmaxf(m0, mx0), mn1 = fmaxf(m1, mx1);
        float al0 = ex2f((m0 - mn0) * LOG2E);
        float al1 = ex2f((m1 - mn1) * LOG2E);
        const float c0 = mn0 * LOG2E, c1 = mn1 * LOG2E;

        float s0 = 0.f, s1 = 0.f;
        #pragma unroll
        for (int nt = 0; nt < 8; nt++) {
            sc[nt][0] = ex2f(fmaf(sc[nt][0], LOG2E, -c0));
            sc[nt][1] = ex2f(fmaf(sc[nt][1], LOG2E, -c0));
            sc[nt][2] = ex2f(fmaf(sc[nt][2], LOG2E, -c1));
            sc[nt][3] = ex2f(fmaf(sc[nt][3], LOG2E, -c1));
            s0 += sc[nt][0] + sc[nt][1];
            s1 += sc[nt][2] + sc[nt][3];
        }
        s0 += __shfl_xor_sync(0xffffffffu, s0, 1);
        s0 += __shfl_xor_sync(0xffffffffu, s0, 2);
        s1 += __shfl_xor_sync(0xffffffffu, s1, 1);
        s1 += __shfl_xor_sync(0xffffffffu, s1, 2);

        l0 = l0 * al0 + s0;
        l1 = l1 * al1 + s1;
        m0 = mn0; m1 = mn1;

        #pragma unroll
        for (int nt = 0; nt < 8; nt++) {
            o[nt][0] *= al0; o[nt][1] *= al0;
            o[nt][2] *= al1; o[nt][3] *= al1;
        }

        // --- P -> fp16x2 fragments (exact pack) ---
        unsigned pf[16];
        #pragma unroll
        for (int nt = 0; nt < 8; nt++) {
            pf[2 * nt]     = f16x2_of(sc[nt][1], sc[nt][0]);
            pf[2 * nt + 1] = f16x2_of(sc[nt][3], sc[nt][2]);
        }

        // --- O += P V (fp16, single V term) ---
        const uint32_t vbase = uVS + (uint32_t)((v_k * FST + v_n) * 2);
        #pragma unroll
        for (int ch = 0; ch < 4; ++ch) {
            unsigned* af = &pf[4 * ch];
            const uint32_t cOff = (uint32_t)(ch * 16 * FST * 2);
            #pragma unroll
            for (int ntp = 0; ntp < 4; ntp++) {
                unsigned vf[4];
                ldm_x4t(vf, vbase + cOff + (uint32_t)(ntp * 16 * 2));
                unsigned bb0[2] = {vf[0], vf[1]}, bb1[2] = {vf[2], vf[3]};
                mma_f16(o[2 * ntp],     af, bb0);
                mma_f16(o[2 * ntp + 1], af, bb1);
            }
        }
    }

    // --- epilogue: normalize, store single fp16 to g_a [b, s, h, dh] ---
    float i0 = (l0 > 0.f) ? 1.f / l0 : 0.f;
    float i1 = (l1 > 0.f) ? 1.f / l1 : 0.f;
    size_t ob = head_off + (size_t)(qb * 128) * DD;
    #pragma unroll
    for (int nt = 0; nt < 8; nt++) {
        int c = nt * 8 + cq * 2;
        *reinterpret_cast<unsigned*>(g_a + ob + (size_t)row0 * DD + c) =
            f16x2_of(o[nt][1] * i0, o[nt][0] * i0);
        *reinterpret_cast<unsigned*>(g_a + ob + (size_t)(row0 + 8) * DD + c) =
            f16x2_of(o[nt][3] * i1, o[nt][2] * i1);
    }
}

// ---------------------------------------------------------------------------
extern "C" void kernel_launch(void* const* d_in, const int* in_sizes, int n_in,
                              void* d_out, int out_size)
{
    (void)in_sizes; (void)n_in; (void)out_size;
    const float* x  = (const float*)d_in[0];
    const float* Wq = (const float*)d_in[1];
    const float* bq = (const float*)d_in[2];
    const float* Wk = (const float*)d_in[3];
    const float* bk = (const float*)d_in[4];
    const float* Wv = (const float*)d_in[5];
    const float* bv = (const float*)d_in[6];
    const float* Wo = (const float*)d_in[7];
    const float* bo = (const float*)d_in[8];
    const int*   pm = (const int*)d_in[9];
    float* out = (float*)d_out;

    cudaFuncSetAttribute(gemm_k, cudaFuncAttributeMaxDynamicSharedMemorySize, GEMM_SMEM);
    cudaFuncSetAttribute(flash_attn_kernel, cudaFuncAttributeMaxDynamicSharedMemorySize, FLASH_SMEM);

    split_src<<<(BSROWS * DD / 4) / 256, 256>>>(x);
    dim3 wgrid(32, 32, 4);
    wsplit_all<<<wgrid, 256>>>(Wq, Wk, Wv, Wo);

    dim3 qkvgrid(BSROWS / 128, DD / 64, 3);     // (64, 16, 3)
    gemm_k<<<qkvgrid, 256, GEMM_SMEM>>>(bq, bk, bv, nullptr, -1);

    dim3 fgrid(SS / 128, BB * HH);              // (16, 64)
    flash_attn_kernel<<<fgrid, 256, FLASH_SMEM>>>(pm);

    dim3 ogrid(BSROWS / 128, DD / 64, 1);       // (64, 16, 1)
    gemm_k<<<ogrid, 256, GEMM_SMEM>>>(bo, nullptr, nullptr, out, 3);
}

// round 15
// speedup vs baseline: 2.5856x; 1.0051x over previous
#include <cuda_runtime.h>
#include <cuda_bf16.h>
#include <cuda_fp16.h>
#include <cstdint>

// Problem constants
#define BB 4
#define SS 2048
#define DD 1024
#define HH 16
#define DHH 64
#define BSROWS (BB * SS)          // 8192

// ---------------------------------------------------------------------------
// Device-global scratch (allocation-free). All single fp16.
// ---------------------------------------------------------------------------
__device__ __half g_x[(size_t)BSROWS * DD];
__device__ __half g_q[(size_t)BSROWS * DD];
__device__ __half g_k[(size_t)BSROWS * DD];
__device__ __half g_v[(size_t)BSROWS * DD];
__device__ __half g_a[(size_t)BSROWS * DD];
__device__ __half g_wt[4 * (size_t)DD * DD];   // W^T [n][k], single fp16

#define LOG2E 1.4426950408889634f

// ---------------------------------------------------------------------------
// Helpers
// ---------------------------------------------------------------------------
__device__ __forceinline__ void mma_f16(float* c, const unsigned* a, const unsigned* b) {
    asm volatile(
        "mma.sync.aligned.m16n8k16.row.col.f32.f16.f16.f32 "
        "{%0,%1,%2,%3}, {%4,%5,%6,%7}, {%8,%9}, {%0,%1,%2,%3};\n"
        : "+f"(c[0]), "+f"(c[1]), "+f"(c[2]), "+f"(c[3])
        : "r"(a[0]), "r"(a[1]), "r"(a[2]), "r"(a[3]),
          "r"(b[0]), "r"(b[1]));
}

__device__ __forceinline__ void ldm_x4(unsigned* r, uint32_t addr) {
    asm volatile("ldmatrix.sync.aligned.m8n8.x4.shared.b16 {%0,%1,%2,%3}, [%4];"
        : "=r"(r[0]), "=r"(r[1]), "=r"(r[2]), "=r"(r[3]) : "r"(addr));
}
__device__ __forceinline__ void ldm_x4t(unsigned* r, uint32_t addr) {
    asm volatile("ldmatrix.sync.aligned.m8n8.x4.trans.shared.b16 {%0,%1,%2,%3}, [%4];"
        : "=r"(r[0]), "=r"(r[1]), "=r"(r[2]), "=r"(r[3]) : "r"(addr));
}

// f32 pair -> f16x2 (hi arg -> upper half)
__device__ __forceinline__ unsigned f16x2_of(float hi, float lo) {
    unsigned r;
    asm("cvt.rn.f16x2.f32 %0, %1, %2;" : "=r"(r) : "f"(hi), "f"(lo));
    return r;
}
__device__ __forceinline__ float ex2f(float x) {
    float r;
    asm("ex2.approx.ftz.f32 %0, %1;" : "=f"(r) : "f"(x));
    return r;
}

__device__ __forceinline__ void cpa16(void* s, const void* g) {
    unsigned sa = (unsigned)__cvta_generic_to_shared(s);
    asm volatile("cp.async.cg.shared.global [%0], [%1], 16;\n" :: "r"(sa), "l"(g));
}
__device__ __forceinline__ void cpa4(void* s, const void* g) {
    unsigned sa = (unsigned)__cvta_generic_to_shared(s);
    asm volatile("cp.async.ca.shared.global [%0], [%1], 4;\n" :: "r"(sa), "l"(g));
}
__device__ __forceinline__ void cpa_commit() {
    asm volatile("cp.async.commit_group;\n");
}
template <int N>
__device__ __forceinline__ void cpa_wait() {
    asm volatile("cp.async.wait_group %0;\n" :: "n"(N));
}
__device__ __forceinline__ uint32_t smem_u32(const void* p) {
    return (uint32_t)__cvta_generic_to_shared(p);
}

// ---------------------------------------------------------------------------
// Prep: x fp32 -> single fp16
// ---------------------------------------------------------------------------
__global__ __launch_bounds__(256)
void split_src(const float* __restrict__ x)
{
    int i = blockIdx.x * 256 + threadIdx.x;            // over float4s: 2M
    float4 v = reinterpret_cast<const float4*>(x)[i];
    uint2 u;
    u.x = f16x2_of(v.y, v.x);
    u.y = f16x2_of(v.w, v.z);
    reinterpret_cast<uint2*>(g_x)[i] = u;
}

// ---------------------------------------------------------------------------
// Prep: transpose all 4 W [k][n] fp32 -> g_wt[z] as [n][k] single fp16
// ---------------------------------------------------------------------------
__global__ __launch_bounds__(256)
void wsplit_all(const float* __restrict__ W0, const float* __restrict__ W1,
                const float* __restrict__ W2, const float* __restrict__ W3)
{
    const int widx = blockIdx.z;
    const float* W = (widx == 0) ? W0 : (widx == 1) ? W1 : (widx == 2) ? W2 : W3;
    __shared__ float t[32][33];
    const int kb = blockIdx.x * 32, nb = blockIdx.y * 32;
    const int r = threadIdx.x >> 3, c4 = (threadIdx.x & 7) * 4;
    float4 v = *reinterpret_cast<const float4*>(W + (size_t)(kb + r) * DD + nb + c4);
    t[r][c4 + 0] = v.x; t[r][c4 + 1] = v.y; t[r][c4 + 2] = v.z; t[r][c4 + 3] = v.w;
    __syncthreads();
    __half* oh = g_wt + (size_t)widx * DD * DD;
    uint2 uh;
    uh.x = f16x2_of(t[c4 + 1][r], t[c4 + 0][r]);
    uh.y = f16x2_of(t[c4 + 3][r], t[c4 + 2][r]);
    size_t o = (size_t)(nb + r) * DD + kb + c4;
    *reinterpret_cast<uint2*>(oh + o) = uh;
}

// ---------------------------------------------------------------------------
// GEMM (single fp16, m16n8k16 + ldmatrix): C = A * W^T' + bias, M=8192, N=K=1024
// CTA tile 128x128, 8 warps (4 M x 2 N), warp tile 32x64 (64-reg acc).
// KS=64, 2-stage cp.async, one sync/iter. 2 CTAs/SM. Halves A re-reads vs N=64.
// mode -1: md=blockIdx.z (Q scaled 1/8; K, V single fp16 out)
// mode  3: A=g_a (attended), out fp32 to outF
// ---------------------------------------------------------------------------
#define KS 64
#define AST 72
#define SLAB (2 * 128 * AST)                 // halves per (dbuf) array = 18432
#define GEMM_SMEM (2 * SLAB * 2)             // 73728 bytes (sA, sB)

__global__ __launch_bounds__(256, 2)
void gemm_k(const float* __restrict__ b0, const float* __restrict__ b1,
            const float* __restrict__ b2, float* __restrict__ outF, int mode)
{
    const int md = (mode < 0) ? (int)blockIdx.z : mode;
    const __half* A = (md < 3) ? g_x : g_a;
    const __half* Wh = g_wt + (size_t)md * DD * DD;
    const float* bias = (md == 1) ? b1 : (md == 2) ? b2 : b0;
    const float scale = (md == 0) ? 0.125f : 1.0f;

    extern __shared__ __half sm[];
    __half* sA = sm;
    __half* sB = sm + SLAB;
    const uint32_t uA = smem_u32(sA);
    const uint32_t uB = smem_u32(sB);

    const int tid  = threadIdx.x;
    const int lane = tid & 31;
    const int warp = tid >> 5;
    const int wm = warp & 3, wn = warp >> 2;
    const int cm = blockIdx.x * 128, cn = blockIdx.y * 128;
    const int rq = lane >> 2, cq = lane & 3;

    // ldmatrix lane->row mappings
    const int a_r = lane & 15, a_k = (lane >> 4) * 8;               // A x4
    const int b_n = ((lane >> 3) & 1) * 8 + (lane & 7);             // B x4 (pair of n-tiles)
    const int b_k = (lane >> 4) * 8;

    // stage kt (64 k-columns) into buffer buf
    auto issue = [&](int kt, int buf) {
        const int k0 = kt * KS;
        #pragma unroll
        for (int i = 0; i < 4; i++) {                // A: 128 rows
            int idx = i * 256 + tid;
            int r = idx >> 3, c8 = (idx & 7) * 8;
            size_t ga = (size_t)(cm + r) * DD + k0 + c8;
            int so = buf * 128 * AST + r * AST + c8;
            cpa16(&sA[so], A + ga);
        }
        #pragma unroll
        for (int i = 0; i < 4; i++) {                // B: 128 rows
            int idx = i * 256 + tid;
            int r = idx >> 3, c8 = (idx & 7) * 8;
            size_t gb = (size_t)(cn + r) * DD + k0 + c8;
            int so = buf * 128 * AST + r * AST + c8;
            cpa16(&sB[so], Wh + gb);
        }
        cpa_commit();
    };

    float acc[2][8][4];
    #pragma unroll
    for (int mt = 0; mt < 2; mt++)
        #pragma unroll
        for (int nt = 0; nt < 8; nt++)
            #pragma unroll
            for (int j = 0; j < 4; j++) acc[mt][nt][j] = 0.f;

    const int NK = DD / KS;  // 16
    issue(0, 0);

    for (int kt = 0; kt < NK; ++kt) {
        const int cur = kt & 1;
        cpa_wait<0>();
        __syncthreads();            // stage kt visible; readers of buf cur^1 retired
        if (kt + 1 < NK) issue(kt + 1, cur ^ 1);   // overlaps all compute below

        const uint32_t bufOff = (uint32_t)(cur * 128 * AST * 2);
        const uint32_t abase = uA + bufOff + (uint32_t)(((wm * 32 + a_r) * AST + a_k) * 2);
        const uint32_t bbase = uB + bufOff + (uint32_t)(((wn * 64 + b_n) * AST + b_k) * 2);
        #pragma unroll
        for (int ch = 0; ch < 4; ++ch) {
            const uint32_t kc2 = (uint32_t)(ch * 32);   // 16 halves per chunk
            unsigned ah[2][4];
            #pragma unroll
            for (int mt = 0; mt < 2; mt++)
                ldm_x4(ah[mt], abase + (uint32_t)(mt * 16 * AST * 2) + kc2);
            #pragma unroll
            for (int ntp = 0; ntp < 4; ntp++) {
                unsigned kf[4];
                ldm_x4(kf, bbase + (uint32_t)(ntp * 16 * AST * 2) + kc2);
                unsigned bb0[2] = {kf[0], kf[2]}, bb1[2] = {kf[1], kf[3]};
                mma_f16(acc[0][2 * ntp],     ah[0], bb0);
                mma_f16(acc[1][2 * ntp],     ah[1], bb0);
                mma_f16(acc[0][2 * ntp + 1], ah[0], bb1);
                mma_f16(acc[1][2 * ntp + 1], ah[1], bb1);
            }
        }
    }

    // epilogue
    #pragma unroll
    for (int mt = 0; mt < 2; mt++) {
        int r = cm + wm * 32 + mt * 16 + rq;
        #pragma unroll
        for (int nt = 0; nt < 8; nt++) {
            int c = cn + wn * 64 + nt * 8 + cq * 2;
            float bb0 = bias[c], bb1 = bias[c + 1];
            float v0 = (acc[mt][nt][0] + bb0) * scale;
            float v1 = (acc[mt][nt][1] + bb1) * scale;
            float v2 = (acc[mt][nt][2] + bb0) * scale;
            float v3 = (acc[mt][nt][3] + bb1) * scale;
            if (md == 3) {
                *reinterpret_cast<float2*>(outF + (size_t)r * DD + c) = make_float2(v0, v1);
                *reinterpret_cast<float2*>(outF + (size_t)(r + 8) * DD + c) = make_float2(v2, v3);
            } else {                // Q (pre-scaled) / K / V: single fp16
                __half* O = (md == 0) ? g_q : (md == 1) ? g_k : g_v;
                *reinterpret_cast<unsigned*>(O + (size_t)r * DD + c) = f16x2_of(v1, v0);
                *reinterpret_cast<unsigned*>(O + (size_t)(r + 8) * DD + c) = f16x2_of(v3, v2);
            }
        }
    }
}

// ---------------------------------------------------------------------------
// Flash attention (UNCHANGED — near multi-pipe roofline).
// 128-row Q tiles, 8 warps. QK: fp16 x fp16. PV: fp16 P x fp16 V.
// smem halves: Q (128xFST) | K0,K1 | V0,V1 (64xFST) | Ms[2][64]
// ---------------------------------------------------------------------------
#define FST 72                                // smem k-stride (halves)
#define F64 (64 * FST)                        // halves per 64-row array
#define QFQ (128 * FST)                       // Q halves
#define KOFF QFQ
#define VOFF (QFQ + 2 * F64)
#define FLASH_SMEM ((QFQ + 4 * F64) * 2 + 2 * 64 * 4)   // 55808 bytes

__global__ __launch_bounds__(256, 2)
void flash_attn_kernel(const int* __restrict__ pmask)
{
    extern __shared__ __half fsm[];
    int* Ms0 = reinterpret_cast<int*>(fsm + QFQ + 4 * F64);
    const uint32_t uQ = smem_u32(fsm);

    const int tid = threadIdx.x, lane = tid & 31, warp = tid >> 5;
    const int qb = (int)(gridDim.x - 1) - (int)blockIdx.x;  // heavy tiles first
    const int bh = blockIdx.y;
    const int b = bh >> 4, h = bh & 15;
    const size_t head_off = ((size_t)b * SS) * DD + (size_t)h * DHH;
    const int nkb = 2 * qb + 2;               // 64-wide key blocks needed

    const int rq = lane >> 2, cq = lane & 3;
    const int row0 = warp * 16 + rq;

    // ldmatrix lane->row mappings
    const int a_r = lane & 15, a_k = (lane >> 4) * 8;      // Q (A, x4)
    const int b_n = ((lane >> 3) & 1) * 8 + (lane & 7);    // K (B, x4 pair)
    const int b_k = (lane >> 4) * 8;
    const int v_k = ((lane >> 3) & 1) * 8 + (lane & 7);    // V (B^T via x4.trans)
    const int v_n = (lane >> 4) * 8;

    auto issueKV = [&](int kb) {
        const int bsel = kb & 1;
        __half* KS_ = fsm + KOFF + F64 * bsel;
        __half* VS = fsm + VOFF + F64 * bsel;
        #pragma unroll
        for (int i = 0; i < 2; i++) {
            int idx = i * 256 + tid;
            int r = idx >> 3, c8 = (idx & 7) * 8;
            size_t g = head_off + (size_t)(kb * 64 + r) * DD + c8;
            cpa16(&KS_[r * FST + c8], g_k + g);
            cpa16(&VS[r * FST + c8], g_v + g);
        }
        if (tid < 64) cpa4(&Ms0[bsel * 64 + tid], pmask + b * SS + kb * 64 + tid);
        cpa_commit();
    };

    // Prologue: Q (128x64 single fp16) + K0/V0/mask0 in ONE group
    #pragma unroll
    for (int i = 0; i < 4; i++) {
        int idx = i * 256 + tid;
        int r = idx >> 3, c8 = (idx & 7) * 8;
        size_t g = head_off + (size_t)(qb * 128 + r) * DD + c8;
        cpa16(&fsm[r * FST + c8], g_q + g);
    }
    {
        __half* KS_ = fsm + KOFF;
        __half* VS = fsm + VOFF;
        #pragma unroll
        for (int i = 0; i < 2; i++) {
            int idx = i * 256 + tid;
            int r = idx >> 3, c8 = (idx & 7) * 8;
            size_t g = head_off + (size_t)r * DD + c8;
            cpa16(&KS_[r * FST + c8], g_k + g);
            cpa16(&VS[r * FST + c8], g_v + g);
        }
        if (tid < 64) cpa4(&Ms0[tid], pmask + b * SS + tid);
        cpa_commit();
    }

    float o[8][4];
    #pragma unroll
    for (int nt = 0; nt < 8; nt++)
        #pragma unroll
        for (int j = 0; j < 4; j++) o[nt][j] = 0.f;
    float m0 = -1e30f, m1 = -1e30f, l0 = 0.f, l1 = 0.f;

    const uint32_t qbase = uQ + (uint32_t)(((warp * 16 + a_r) * FST + a_k) * 2);

    for (int kb = 0; kb < nkb; ++kb) {
        cpa_wait<0>();
        __syncthreads();
        if (kb + 1 < nkb) issueKV(kb + 1);

        // warp-uniform skip: entire kv-block above this warp's rows
        if (kb * 64 > qb * 128 + warp * 16 + 15) continue;

        const uint32_t uKH = smem_u32(fsm + KOFF + F64 * (kb & 1));
        const uint32_t uVS = smem_u32(fsm + VOFF + F64 * (kb & 1));
        const int* Ms = Ms0 + (kb & 1) * 64;

        // mask fast-path detection (warp-uniform)
        unsigned mw0 = __ballot_sync(0xffffffffu, Ms[lane] != 0);
        unsigned mw1 = __ballot_sync(0xffffffffu, Ms[32 + lane] != 0);
        const bool needmask = ((mw0 & mw1) != 0xffffffffu) ||
                              (kb * 64 + 63 > qb * 128 + warp * 16);

        // --- S = Q K^T (warp: 16 x 64), single-term fp16 ---
        float sc[8][4];
        #pragma unroll
        for (int nt = 0; nt < 8; nt++)
            #pragma unroll
            for (int j = 0; j < 4; j++) sc[nt][j] = 0.f;

        const uint32_t kbase = uKH + (uint32_t)((b_n * FST + b_k) * 2);
        #pragma unroll
        for (int ch = 0; ch < 4; ++ch) {
            const uint32_t kc2 = (uint32_t)(ch * 32);
            unsigned ah[4];
            ldm_x4(ah, qbase + kc2);
            #pragma unroll
            for (int ntp = 0; ntp < 4; ntp++) {
                unsigned kf[4];
                ldm_x4(kf, kbase + (uint32_t)(ntp * 16 * FST * 2) + kc2);
                unsigned bb0[2] = {kf[0], kf[2]}, bb1[2] = {kf[1], kf[3]};
                mma_f16(sc[2 * ntp],     ah, bb0);
                mma_f16(sc[2 * ntp + 1], ah, bb1);
            }
        }

        // --- mask (slow path only; Q pre-scaled; sentinel -1e30) ---
        if (needmask) {
            const int gm0 = qb * 128 + row0, gm1 = gm0 + 8;
            #pragma unroll
            for (int nt = 0; nt < 8; nt++) {
                int nloc = nt * 8 + cq * 2;
                int gn = kb * 64 + nloc;
                #pragma unroll
                for (int j = 0; j < 2; j++) {
                    bool pv = (Ms[nloc + j] != 0);
                    sc[nt][j]     = (pv && (gn + j) <= gm0) ? sc[nt][j]     : -1e30f;
                    sc[nt][2 + j] = (pv && (gn + j) <= gm1) ? sc[nt][2 + j] : -1e30f;
                }
            }
        }

        // --- online softmax ---
        float mx0 = -1e30f, mx1 = -1e30f;
        #pragma unroll
        for (int nt = 0; nt < 8; nt++) {
            mx0 = fmaxf(mx0, fmaxf(sc[nt][0], sc[nt][1]));
            mx1 = fmaxf(mx1, fmaxf(sc[nt][2], sc[nt][3]));
        }
        mx0 = fmaxf(mx0, __shfl_xor_sync(0xffffffffu, mx0, 1));
        mx0 = fmaxf(mx0, __shfl_xor_sync(0xffffffffu, mx0, 2));
        mx1 = fmaxf(mx1, __shfl_xor_sync(0xffffffffu, mx1, 1));
        mx1 = fmaxf(mx1, __shfl_xor_sync(0xffffffffu, mx1, 2));

        float mn0 = fmaxf(m0, mx0), mn1 = fmaxf(m1, mx1);
        float al0 = ex2f((m0 - mn0) * LOG2E);
        float al1 = ex2f((m1 - mn1) * LOG2E);
        const float c0 = mn0 * LOG2E, c1 = mn1 * LOG2E;

        float s0 = 0.f, s1 = 0.f;
        #pragma unroll
        for (int nt = 0; nt < 8; nt++) {
            sc[nt][0] = ex2f(fmaf(sc[nt][0], LOG2E, -c0));
            sc[nt][1] = ex2f(fmaf(sc[nt][1], LOG2E, -c0));
            sc[nt][2] = ex2f(fmaf(sc[nt][2], LOG2E, -c1));
            sc[nt][3] = ex2f(fmaf(sc[nt][3], LOG2E, -c1));
            s0 += sc[nt][0] + sc[nt][1];
            s1 += sc[nt][2] + sc[nt][3];
        }
        s0 += __shfl_xor_sync(0xffffffffu, s0, 1);
        s0 += __shfl_xor_sync(0xffffffffu, s0, 2);
        s1 += __shfl_xor_sync(0xffffffffu, s1, 1);
        s1 += __shfl_xor_sync(0xffffffffu, s1, 2);

        l0 = l0 * al0 + s0;
        l1 = l1 * al1 + s1;
        m0 = mn0; m1 = mn1;

        #pragma unroll
        for (int nt = 0; nt < 8; nt++) {
            o[nt][0] *= al0; o[nt][1] *= al0;
            o[nt][2] *= al1; o[nt][3] *= al1;
        }

        // --- P -> fp16x2 fragments (exact pack) ---
        unsigned pf[16];
        #pragma unroll
        for (int nt = 0; nt < 8; nt++) {
            pf[2 * nt]     = f16x2_of(sc[nt][1], sc[nt][0]);
            pf[2 * nt + 1] = f16x2_of(sc[nt][3], sc[nt][2]);
        }

        // --- O += P V (fp16, single V term) ---
        const uint32_t vbase = uVS + (uint32_t)((v_k * FST + v_n) * 2);
        #pragma unroll
        for (int ch = 0; ch < 4; ++ch) {
            unsigned* af = &pf[4 * ch];
            const uint32_t cOff = (uint32_t)(ch * 16 * FST * 2);
            #pragma unroll
            for (int ntp = 0; ntp < 4; ntp++) {
                unsigned vf[4];
                ldm_x4t(vf, vbase + cOff + (uint32_t)(ntp * 16 * 2));
                unsigned bb0[2] = {vf[0], vf[1]}, bb1[2] = {vf[2], vf[3]};
                mma_f16(o[2 * ntp],     af, bb0);
                mma_f16(o[2 * ntp + 1], af, bb1);
            }
        }
    }

    // --- epilogue: normalize, store single fp16 to g_a [b, s, h, dh] ---
    float i0 = (l0 > 0.f) ? 1.f / l0 : 0.f;
    float i1 = (l1 > 0.f) ? 1.f / l1 : 0.f;
    size_t ob = head_off + (size_t)(qb * 128) * DD;
    #pragma unroll
    for (int nt = 0; nt < 8; nt++) {
        int c = nt * 8 + cq * 2;
        *reinterpret_cast<unsigned*>(g_a + ob + (size_t)row0 * DD + c) =
            f16x2_of(o[nt][1] * i0, o[nt][0] * i0);
        *reinterpret_cast<unsigned*>(g_a + ob + (size_t)(row0 + 8) * DD + c) =
            f16x2_of(o[nt][3] * i1, o[nt][2] * i1);
    }
}

// ---------------------------------------------------------------------------
extern "C" void kernel_launch(void* const* d_in, const int* in_sizes, int n_in,
                              void* d_out, int out_size)
{
    (void)in_sizes; (void)n_in; (void)out_size;
    const float* x  = (const float*)d_in[0];
    const float* Wq = (const float*)d_in[1];
    const float* bq = (const float*)d_in[2];
    const float* Wk = (const float*)d_in[3];
    const float* bk = (const float*)d_in[4];
    const float* Wv = (const float*)d_in[5];
    const float* bv = (const float*)d_in[6];
    const float* Wo = (const float*)d_in[7];
    const float* bo = (const float*)d_in[8];
    const int*   pm = (const int*)d_in[9];
    float* out = (float*)d_out;

    cudaFuncSetAttribute(gemm_k, cudaFuncAttributeMaxDynamicSharedMemorySize, GEMM_SMEM);
    cudaFuncSetAttribute(flash_attn_kernel, cudaFuncAttributeMaxDynamicSharedMemorySize, FLASH_SMEM);

    split_src<<<(BSROWS * DD / 4) / 256, 256>>>(x);
    dim3 wgrid(32, 32, 4);
    wsplit_all<<<wgrid, 256>>>(Wq, Wk, Wv, Wo);

    dim3 qkvgrid(BSROWS / 128, DD / 128, 3);    // (64, 8, 3)
    gemm_k<<<qkvgrid, 256, GEMM_SMEM>>>(bq, bk, bv, nullptr, -1);

    dim3 fgrid(SS / 128, BB * HH);              // (16, 64)
    flash_attn_kernel<<<fgrid, 256, FLASH_SMEM>>>(pm);

    dim3 ogrid(BSROWS / 128, DD / 128, 1);      // (64, 8, 1)
    gemm_k<<<ogrid, 256, GEMM_SMEM>>>(bo, nullptr, nullptr, out, 3);
}